// round 2
// baseline (speedup 1.0000x reference)
#include <cuda_runtime.h>

// Problem constants
static constexpr int B_  = 2;
static constexpr int S_  = 2048;
static constexpr int D_  = 1024;
static constexpr int H_  = 16;
static constexpr int DH_ = 64;
static constexpr int BS_ = B_ * S_;          // 4096
static constexpr int HD_ = H_ * DH_;         // 1024

// Scratch: q,k,v in [B,H,S,DH]; concat attention output in [B,S,H*DH]
__device__ float g_q[B_ * H_ * S_ * DH_];
__device__ float g_k[B_ * H_ * S_ * DH_];
__device__ float g_v[B_ * H_ * S_ * DH_];
__device__ float g_oc[B_ * S_ * HD_];

// ---------------------------------------------------------------------------
// Kernel 1: QKV projection.  out[b,h,s,d] = sum_i x[b,s,i] * W[h,i,d] + bias[h,d]
// grid: (BS/64, H, 3)  block: 256   tile 64x64, K-tile 16, 4x4 microtile
// ---------------------------------------------------------------------------
__global__ __launch_bounds__(256) void qkv_kernel(
    const float* __restrict__ x,
    const float* __restrict__ Wq, const float* __restrict__ bq,
    const float* __restrict__ Wk, const float* __restrict__ bk,
    const float* __restrict__ Wv, const float* __restrict__ bv)
{
    const int h    = blockIdx.y;
    const int wsel = blockIdx.z;
    const float* W    = (wsel == 0) ? Wq : (wsel == 1) ? Wk : Wv;
    const float* bias = (wsel == 0) ? bq : (wsel == 1) ? bk : bv;
    float* out        = (wsel == 0) ? g_q : (wsel == 1) ? g_k : g_v;

    __shared__ float Xs[16][68];   // [k][m], padded for bank conflicts, 16B-aligned rows
    __shared__ float Ws[16][64];   // [k][n]

    const int tid = threadIdx.x;
    const int tx = tid & 15, ty = tid >> 4;
    const int m0 = blockIdx.x * 64;

    float acc[4][4] = {};

    for (int k0 = 0; k0 < D_; k0 += 16) {
        #pragma unroll
        for (int i = 0; i < 4; i++) {
            int idx = tid + i * 256;
            int r = idx >> 4, c = idx & 15;            // 64 rows x 16 k
            Xs[c][r] = x[(size_t)(m0 + r) * D_ + k0 + c];
        }
        #pragma unroll
        for (int i = 0; i < 4; i++) {
            int idx = tid + i * 256;
            int r = idx >> 6, c = idx & 63;            // 16 k x 64 n
            Ws[r][c] = W[(size_t)(h * D_ + k0 + r) * DH_ + c];
        }
        __syncthreads();

        #pragma unroll
        for (int kk = 0; kk < 16; kk++) {
            float4 a4 = *(const float4*)&Xs[kk][ty * 4];
            float4 b4 = *(const float4*)&Ws[kk][tx * 4];
            float av[4] = {a4.x, a4.y, a4.z, a4.w};
            float bv4[4] = {b4.x, b4.y, b4.z, b4.w};
            #pragma unroll
            for (int i2 = 0; i2 < 4; i2++)
                #pragma unroll
                for (int j2 = 0; j2 < 4; j2++)
                    acc[i2][j2] += av[i2] * bv4[j2];
        }
        __syncthreads();
    }

    #pragma unroll
    for (int i2 = 0; i2 < 4; i2++) {
        int m = m0 + ty * 4 + i2;
        int bb = m / S_, s = m - bb * S_;
        float* orow = out + ((size_t)(bb * H_ + h) * S_ + s) * DH_;
        #pragma unroll
        for (int j2 = 0; j2 < 4; j2++) {
            int n = tx * 4 + j2;
            orow[n] = acc[i2][j2] + bias[h * DH_ + n];
        }
    }
}

// ---------------------------------------------------------------------------
// Kernel 2: flash attention.  One CTA per (b,h) x 64-query tile.
// ---------------------------------------------------------------------------
struct AttnSmem {
    float Qs[64][68];   // [d][i]  (transposed for float4 reads)
    float Ks[64][68];   // [d][j]
    float Vs[64][64];   // [j][d]  natural layout
    float Ss[64][65];   // scores / P, row-major [i][j]
    float m_s[64];
    float l_s[64];
    float c_s[64];
};

extern __shared__ char attn_smem_raw[];

__global__ __launch_bounds__(256) void attn_kernel()
{
    AttnSmem& sm = *(AttnSmem*)attn_smem_raw;
    const int qt = blockIdx.x;              // query tile (0..31)
    const int bh = blockIdx.y;              // b*H + h  (0..31)
    const int bb = bh / H_, h = bh - bb * H_;
    const int tid = threadIdx.x;
    const int tx = tid & 15, ty = tid >> 4;
    const float scale = 0.125f;             // 1/sqrt(64)

    const float* qbase = g_q + (size_t)bh * S_ * DH_;
    const float* kbase = g_k + (size_t)bh * S_ * DH_;
    const float* vbase = g_v + (size_t)bh * S_ * DH_;

    const int q0 = qt * 64;
    #pragma unroll
    for (int i = 0; i < 16; i++) {
        int idx = tid + i * 256;
        int r = idx >> 6, c = idx & 63;     // 64 rows x 64 d
        sm.Qs[c][r] = qbase[(size_t)(q0 + r) * DH_ + c];
    }
    if (tid < 64) { sm.m_s[tid] = -1e30f; sm.l_s[tid] = 0.f; }

    float o_acc[4][4] = {};

    for (int j0 = 0; j0 < S_; j0 += 64) {
        __syncthreads();   // prior PV-gemm done reading Ks/Vs/Ss; also covers init/Q load
        #pragma unroll
        for (int i = 0; i < 16; i++) {
            int idx = tid + i * 256;
            int r = idx >> 6, c = idx & 63;
            float kval = kbase[(size_t)(j0 + r) * DH_ + c];
            float vval = vbase[(size_t)(j0 + r) * DH_ + c];
            sm.Ks[c][r] = kval;
            sm.Vs[r][c] = vval;
        }
        __syncthreads();

        // ---- scores: Sc[i][j] = scale * sum_d Q[i][d] K[j][d]
        float acc[4][4] = {};
        #pragma unroll
        for (int d = 0; d < 64; d++) {
            float4 a4 = *(const float4*)&sm.Qs[d][ty * 4];
            float4 b4 = *(const float4*)&sm.Ks[d][tx * 4];
            float av[4] = {a4.x, a4.y, a4.z, a4.w};
            float bv4[4] = {b4.x, b4.y, b4.z, b4.w};
            #pragma unroll
            for (int i2 = 0; i2 < 4; i2++)
                #pragma unroll
                for (int j2 = 0; j2 < 4; j2++)
                    acc[i2][j2] += av[i2] * bv4[j2];
        }
        #pragma unroll
        for (int i2 = 0; i2 < 4; i2++)
            #pragma unroll
            for (int j2 = 0; j2 < 4; j2++)
                sm.Ss[ty * 4 + i2][tx * 4 + j2] = acc[i2][j2] * scale;
        __syncthreads();

        // ---- online softmax: one row per 4-thread quad
        {
            const int r = tid >> 2, ql = tid & 3;
            float mloc = -1e30f;
            #pragma unroll
            for (int j2 = 0; j2 < 16; j2++)
                mloc = fmaxf(mloc, sm.Ss[r][ql * 16 + j2]);
            mloc = fmaxf(mloc, __shfl_xor_sync(0xffffffffu, mloc, 1));
            mloc = fmaxf(mloc, __shfl_xor_sync(0xffffffffu, mloc, 2));
            float mold = sm.m_s[r];
            float mnew = fmaxf(mold, mloc);
            float sum = 0.f;
            #pragma unroll
            for (int j2 = 0; j2 < 16; j2++) {
                float p = __expf(sm.Ss[r][ql * 16 + j2] - mnew);
                sm.Ss[r][ql * 16 + j2] = p;
                sum += p;
            }
            sum += __shfl_xor_sync(0xffffffffu, sum, 1);
            sum += __shfl_xor_sync(0xffffffffu, sum, 2);
            if (ql == 0) {
                float corr = __expf(mold - mnew);
                sm.c_s[r] = corr;
                sm.m_s[r] = mnew;
                sm.l_s[r] = sm.l_s[r] * corr + sum;
            }
        }
        __syncthreads();

        // ---- rescale accumulated O, then O += P @ V
        #pragma unroll
        for (int i2 = 0; i2 < 4; i2++) {
            float corr = sm.c_s[ty * 4 + i2];
            #pragma unroll
            for (int j2 = 0; j2 < 4; j2++) o_acc[i2][j2] *= corr;
        }
        #pragma unroll
        for (int jj = 0; jj < 64; jj++) {
            float4 b4 = *(const float4*)&sm.Vs[jj][tx * 4];
            float bv4[4] = {b4.x, b4.y, b4.z, b4.w};
            #pragma unroll
            for (int i2 = 0; i2 < 4; i2++) {
                float a = sm.Ss[ty * 4 + i2][jj];
                #pragma unroll
                for (int j2 = 0; j2 < 4; j2++)
                    o_acc[i2][j2] += a * bv4[j2];
            }
        }
    }

    // ---- epilogue: normalize and write concat layout [B,S,H*DH]
    #pragma unroll
    for (int i2 = 0; i2 < 4; i2++) {
        int i = ty * 4 + i2;
        float inv_l = 1.f / sm.l_s[i];
        float* orow = g_oc + ((size_t)(bb * S_) + q0 + i) * HD_ + h * DH_;
        #pragma unroll
        for (int j2 = 0; j2 < 4; j2++)
            orow[tx * 4 + j2] = o_acc[i2][j2] * inv_l;
    }
}

// ---------------------------------------------------------------------------
// Kernel 3: output projection.  out[m, n] = sum_k oc[m,k] * Wo[k,n] + bo[n]
// grid: (BS/64, D/64)  block 256
// ---------------------------------------------------------------------------
__global__ __launch_bounds__(256) void proj_kernel(
    const float* __restrict__ Wo, const float* __restrict__ bo,
    float* __restrict__ out)
{
    __shared__ float Xs[16][68];
    __shared__ float Ws[16][64];

    const int tid = threadIdx.x;
    const int tx = tid & 15, ty = tid >> 4;
    const int m0 = blockIdx.x * 64;
    const int n0 = blockIdx.y * 64;

    float acc[4][4] = {};

    for (int k0 = 0; k0 < HD_; k0 += 16) {
        #pragma unroll
        for (int i = 0; i < 4; i++) {
            int idx = tid + i * 256;
            int r = idx >> 4, c = idx & 15;
            Xs[c][r] = g_oc[(size_t)(m0 + r) * HD_ + k0 + c];
        }
        #pragma unroll
        for (int i = 0; i < 4; i++) {
            int idx = tid + i * 256;
            int r = idx >> 6, c = idx & 63;
            Ws[r][c] = Wo[(size_t)(k0 + r) * D_ + n0 + c];
        }
        __syncthreads();

        #pragma unroll
        for (int kk = 0; kk < 16; kk++) {
            float4 a4 = *(const float4*)&Xs[kk][ty * 4];
            float4 b4 = *(const float4*)&Ws[kk][tx * 4];
            float av[4] = {a4.x, a4.y, a4.z, a4.w};
            float bv4[4] = {b4.x, b4.y, b4.z, b4.w};
            #pragma unroll
            for (int i2 = 0; i2 < 4; i2++)
                #pragma unroll
                for (int j2 = 0; j2 < 4; j2++)
                    acc[i2][j2] += av[i2] * bv4[j2];
        }
        __syncthreads();
    }

    #pragma unroll
    for (int i2 = 0; i2 < 4; i2++) {
        int m = m0 + ty * 4 + i2;
        #pragma unroll
        for (int j2 = 0; j2 < 4; j2++) {
            int n = n0 + tx * 4 + j2;
            out[(size_t)m * D_ + n] = acc[i2][j2] + bo[n];
        }
    }
}

// ---------------------------------------------------------------------------
extern "C" void kernel_launch(void* const* d_in, const int* in_sizes, int n_in,
                              void* d_out, int out_size)
{
    const float* x  = (const float*)d_in[0];
    const float* Wq = (const float*)d_in[1];
    const float* bq = (const float*)d_in[2];
    const float* Wk = (const float*)d_in[3];
    const float* bk = (const float*)d_in[4];
    const float* Wv = (const float*)d_in[5];
    const float* bv = (const float*)d_in[6];
    const float* Wo = (const float*)d_in[7];
    const float* bo = (const float*)d_in[8];
    float* out = (float*)d_out;

    cudaFuncSetAttribute(attn_kernel, cudaFuncAttributeMaxDynamicSharedMemorySize,
                         (int)sizeof(AttnSmem));

    qkv_kernel<<<dim3(BS_ / 64, H_, 3), 256>>>(x, Wq, bq, Wk, bk, Wv, bv);
    attn_kernel<<<dim3(S_ / 64, B_ * H_), 256, sizeof(AttnSmem)>>>();
    proj_kernel<<<dim3(BS_ / 64, D_ / 64), 256>>>(Wo, bo, out);
}

// round 5
// speedup vs baseline: 1.1591x; 1.1591x over previous
#include <cuda_runtime.h>
#include <cstdint>

// Problem constants
static constexpr int B_  = 2;
static constexpr int S_  = 2048;
static constexpr int D_  = 1024;
static constexpr int H_  = 16;
static constexpr int DH_ = 64;
static constexpr int BS_ = B_ * S_;          // 4096
static constexpr int HD_ = H_ * DH_;         // 1024
static constexpr int N3_ = 3 * D_;           // 3072

// Scratch
__device__ float g_qkv[BS_ * N3_];           // [4096,3072]: q|k|v
__device__ float g_wt [N3_ * D_];            // qkv weights transposed [3072,1024] (K-major)
__device__ float g_wot[D_ * D_];             // Wo transposed [1024,1024]
__device__ float g_bias[N3_];
__device__ float g_oc [BS_ * HD_];           // attention output concat [4096,1024]

// ---------------------------------------------------------------------------
// Helpers
// ---------------------------------------------------------------------------
__device__ __forceinline__ void cp16(uint32_t dst, const void* src) {
    asm volatile("cp.async.cg.shared.global [%0], [%1], 16;" :: "r"(dst), "l"(src));
}
#define CP_COMMIT() asm volatile("cp.async.commit_group;")
#define CP_WAIT(n)  asm volatile("cp.async.wait_group %0;" :: "n"(n))

__device__ __forceinline__ uint32_t smem_u32(const void* p) {
    uint32_t a;
    asm("{ .reg .u64 t; cvta.to.shared.u64 t, %1; cvt.u32.u64 %0, t; }" : "=r"(a) : "l"(p));
    return a;
}

// m16n8k8 tf32 MMA (A row-major, B col-major), fp32 accumulate
__device__ __forceinline__ void mma_tf32(float* c, const uint32_t* a, const uint32_t* b) {
    asm volatile(
        "mma.sync.aligned.m16n8k8.row.col.f32.tf32.tf32.f32 "
        "{%0,%1,%2,%3}, {%4,%5,%6,%7}, {%8,%9}, {%0,%1,%2,%3};"
        : "+f"(c[0]), "+f"(c[1]), "+f"(c[2]), "+f"(c[3])
        : "r"(a[0]), "r"(a[1]), "r"(a[2]), "r"(a[3]), "r"(b[0]), "r"(b[1]));
}

// 3xTF32 split: x = hi + lo (both tf32-representable, round-to-nearest)
__device__ __forceinline__ void split2(float x, uint32_t& hi, uint32_t& lo) {
    uint32_t h;
    asm("cvt.rna.tf32.f32 %0, %1;" : "=r"(h) : "f"(x));
    float r = x - __uint_as_float(h);
    asm("cvt.rna.tf32.f32 %0, %1;" : "=r"(lo) : "f"(r));
    hi = h;
}

// ---------------------------------------------------------------------------
// Weight transposes + bias concat
// ---------------------------------------------------------------------------
__global__ void build_wt(const float* __restrict__ Wq, const float* __restrict__ Wk,
                         const float* __restrict__ Wv) {
    const int wsel = blockIdx.z >> 4, h = blockIdx.z & 15;
    const float* W = (wsel == 0) ? Wq : (wsel == 1) ? Wk : Wv;
    __shared__ float t[32][33];
    const int k0 = blockIdx.x * 32, d0 = blockIdx.y * 32;
    #pragma unroll
    for (int i = 0; i < 4; i++) {
        int k = k0 + threadIdx.y + i * 8;
        t[threadIdx.y + i * 8][threadIdx.x] = W[(size_t)h * D_ * DH_ + (size_t)k * DH_ + d0 + threadIdx.x];
    }
    __syncthreads();
    #pragma unroll
    for (int i = 0; i < 4; i++) {
        int d = d0 + threadIdx.y + i * 8;
        g_wt[(size_t)(wsel * D_ + h * DH_ + d) * D_ + k0 + threadIdx.x] = t[threadIdx.x][threadIdx.y + i * 8];
    }
}

__global__ void build_wot(const float* __restrict__ Wo) {
    __shared__ float t[32][33];
    const int k0 = blockIdx.x * 32, n0 = blockIdx.y * 32;
    #pragma unroll
    for (int i = 0; i < 4; i++)
        t[threadIdx.y + i * 8][threadIdx.x] = Wo[(size_t)(k0 + threadIdx.y + i * 8) * D_ + n0 + threadIdx.x];
    __syncthreads();
    #pragma unroll
    for (int i = 0; i < 4; i++)
        g_wot[(size_t)(n0 + threadIdx.y + i * 8) * D_ + k0 + threadIdx.x] = t[threadIdx.x][threadIdx.y + i * 8];
}

__global__ void build_bias(const float* __restrict__ bq, const float* __restrict__ bk,
                           const float* __restrict__ bv) {
    const float* b = (blockIdx.x == 0) ? bq : (blockIdx.x == 1) ? bk : bv;
    g_bias[blockIdx.x * D_ + threadIdx.x] = b[threadIdx.x];
}

// ---------------------------------------------------------------------------
// 3xTF32 mma GEMM: C[m,n] = sum_k A[m,k]*Bt[n,k] + bias[n]
// Tile 128x128, K-chunk 32, double-buffered cp.async. 8 warps (4x2).
// ---------------------------------------------------------------------------
static constexpr int GSTR   = 36;
static constexpr int GSTAGE = 128 * GSTR;
static constexpr int G_SMEM = 2 * 2 * GSTAGE * 4;      // 73728 B

extern __shared__ float g_dyn[];

__global__ __launch_bounds__(256) void gemm_mma(
    const float* __restrict__ A, const float* __restrict__ Bt,
    const float* __restrict__ bias, float* __restrict__ C, int Ntotal)
{
    float* As = g_dyn;                 // [2][128][36]
    float* Bs = g_dyn + 2 * GSTAGE;    // [2][128][36]
    const uint32_t a_u32 = smem_u32(As);
    const uint32_t b_u32 = smem_u32(Bs);

    const int tid = threadIdx.x, wid = tid >> 5, lane = tid & 31;
    const int g = lane >> 2, t = lane & 3;
    const int wm = wid >> 1, wn = wid & 1;
    const int m0 = blockIdx.x * 128, n0 = blockIdx.y * 128;

    float Cacc[2][8][4] = {};

    auto load_chunk = [&](int kc, int s) {
        #pragma unroll
        for (int p = 0; p < 4; p++) {
            int o = tid + p * 256;
            int r = o >> 3, sg = o & 7;
            uint32_t doff = (uint32_t)(s * GSTAGE + r * GSTR) * 4 + sg * 16;
            cp16(a_u32 + doff, A  + (size_t)(m0 + r) * D_ + kc + sg * 4);
            cp16(b_u32 + doff, Bt + (size_t)(n0 + r) * D_ + kc + sg * 4);
        }
        CP_COMMIT();
    };

    load_chunk(0, 0);

    for (int ch = 0; ch < 32; ch++) {
        const int s = ch & 1;
        if (ch < 31) { load_chunk((ch + 1) * 32, s ^ 1); CP_WAIT(1); }
        else         { CP_WAIT(0); }
        __syncthreads();

        const float* as = As + s * GSTAGE;
        const float* bs = Bs + s * GSTAGE;
        #pragma unroll
        for (int ks = 0; ks < 4; ks++) {
            const int k = ks * 8;
            uint32_t ah[2][4], al[2][4];
            #pragma unroll
            for (int i = 0; i < 2; i++) {
                int row = wm * 32 + i * 16 + g;
                split2(as[row       * GSTR + k + t],     ah[i][0], al[i][0]);
                split2(as[(row + 8) * GSTR + k + t],     ah[i][1], al[i][1]);
                split2(as[row       * GSTR + k + t + 4], ah[i][2], al[i][2]);
                split2(as[(row + 8) * GSTR + k + t + 4], ah[i][3], al[i][3]);
            }
            #pragma unroll
            for (int n = 0; n < 8; n++) {
                int rn = wn * 64 + n * 8 + g;
                uint32_t bh[2], bl[2];
                split2(bs[rn * GSTR + k + t],     bh[0], bl[0]);
                split2(bs[rn * GSTR + k + t + 4], bh[1], bl[1]);
                #pragma unroll
                for (int i = 0; i < 2; i++) {
                    mma_tf32(Cacc[i][n], ah[i], bh);
                    mma_tf32(Cacc[i][n], ah[i], bl);
                    mma_tf32(Cacc[i][n], al[i], bh);
                }
            }
        }
        __syncthreads();
    }

    #pragma unroll
    for (int i = 0; i < 2; i++) {
        const int r0 = m0 + wm * 32 + i * 16 + g;
        #pragma unroll
        for (int n = 0; n < 8; n++) {
            const int c = n0 + wn * 64 + n * 8 + 2 * t;
            float bx = __ldg(bias + c), by = __ldg(bias + c + 1);
            float2 v0 = make_float2(Cacc[i][n][0] + bx, Cacc[i][n][1] + by);
            float2 v1 = make_float2(Cacc[i][n][2] + bx, Cacc[i][n][3] + by);
            *(float2*)(C + (size_t)r0 * Ntotal + c)       = v0;
            *(float2*)(C + (size_t)(r0 + 8) * Ntotal + c) = v1;
        }
    }
}

// ---------------------------------------------------------------------------
// Flash attention, 3xTF32 mma. CTA: 128 queries, 8 warps; j-tiles of 64.
// Q fragments (hi+lo) register-resident; Ps overlays Qs in smem.
// ---------------------------------------------------------------------------
struct ASmem {
    float QP[128][68];   // Q tile during prologue, then P tile
    float Ks[64][68];
    float Vs[64][72];
};
static constexpr int A_SMEM = sizeof(ASmem);   // 70656 B

extern __shared__ char attn_dyn[];

__global__ __launch_bounds__(256) void attn_mma()
{
    ASmem& sm = *(ASmem*)attn_dyn;
    const int qt = blockIdx.x, bh = blockIdx.y;
    const int bb = bh >> 4, h = bh & 15;
    const int tid = threadIdx.x, wid = tid >> 5, lane = tid & 31;
    const int g = lane >> 2, t = lane & 3;

    const float* qbase = g_qkv + (size_t)bb * S_ * N3_ + h * DH_;
    const float* kbase = qbase + D_;
    const float* vbase = qbase + 2 * D_;
    const int q0 = qt * 128;
    const int mrow = wid * 16 + g;

    // ---- Q cooperative load (pre-scaled), then per-warp fragment extraction
    #pragma unroll
    for (int p = 0; p < 8; p++) {
        int o = tid + p * 256;
        int r = o >> 4, c = o & 15;
        float4 v = *(const float4*)(qbase + (size_t)(q0 + r) * N3_ + c * 4);
        v.x *= 0.125f; v.y *= 0.125f; v.z *= 0.125f; v.w *= 0.125f;
        *(float4*)&sm.QP[r][c * 4] = v;
    }
    __syncthreads();

    uint32_t qh[8][4], ql[8][4];
    #pragma unroll
    for (int ks = 0; ks < 8; ks++) {
        const int k = ks * 8;
        split2(sm.QP[mrow][k + t],         qh[ks][0], ql[ks][0]);
        split2(sm.QP[mrow + 8][k + t],     qh[ks][1], ql[ks][1]);
        split2(sm.QP[mrow][k + t + 4],     qh[ks][2], ql[ks][2]);
        split2(sm.QP[mrow + 8][k + t + 4], qh[ks][3], ql[ks][3]);
    }

    float Oacc[8][4] = {};
    float m0r = -1e30f, m1r = -1e30f, l0r = 0.f, l1r = 0.f;

    for (int j0 = 0; j0 < S_; j0 += 64) {
        __syncthreads();   // covers Q extraction (first iter) and prior-iter K/V/P reads
        #pragma unroll
        for (int p = 0; p < 4; p++) {
            int o = tid + p * 256;
            int r = o >> 4, c = o & 15;
            *(float4*)&sm.Ks[r][c * 4] = *(const float4*)(kbase + (size_t)(j0 + r) * N3_ + c * 4);
            *(float4*)&sm.Vs[r][c * 4] = *(const float4*)(vbase + (size_t)(j0 + r) * N3_ + c * 4);
        }
        __syncthreads();

        // ---- S = Q @ K^T (3xTF32)
        float Sacc[8][4] = {};
        #pragma unroll
        for (int ks = 0; ks < 8; ks++) {
            const int k = ks * 8;
            #pragma unroll
            for (int n = 0; n < 8; n++) {
                uint32_t kh[2], kl[2];
                split2(sm.Ks[n * 8 + g][k + t],     kh[0], kl[0]);
                split2(sm.Ks[n * 8 + g][k + t + 4], kh[1], kl[1]);
                mma_tf32(Sacc[n], qh[ks], kh);
                mma_tf32(Sacc[n], qh[ks], kl);
                mma_tf32(Sacc[n], ql[ks], kh);
            }
        }

        // ---- online softmax (rows mrow, mrow+8; quad shares a row)
        float mx0 = -1e30f, mx1 = -1e30f;
        #pragma unroll
        for (int n = 0; n < 8; n++) {
            mx0 = fmaxf(mx0, fmaxf(Sacc[n][0], Sacc[n][1]));
            mx1 = fmaxf(mx1, fmaxf(Sacc[n][2], Sacc[n][3]));
        }
        mx0 = fmaxf(mx0, __shfl_xor_sync(0xffffffffu, mx0, 1));
        mx0 = fmaxf(mx0, __shfl_xor_sync(0xffffffffu, mx0, 2));
        mx1 = fmaxf(mx1, __shfl_xor_sync(0xffffffffu, mx1, 1));
        mx1 = fmaxf(mx1, __shfl_xor_sync(0xffffffffu, mx1, 2));

        const float mn0 = fmaxf(m0r, mx0), mn1 = fmaxf(m1r, mx1);
        const float c0 = __expf(m0r - mn0), c1 = __expf(m1r - mn1);
        float s0 = 0.f, s1 = 0.f;
        #pragma unroll
        for (int n = 0; n < 8; n++) {
            float p00 = __expf(Sacc[n][0] - mn0);
            float p01 = __expf(Sacc[n][1] - mn0);
            float p10 = __expf(Sacc[n][2] - mn1);
            float p11 = __expf(Sacc[n][3] - mn1);
            s0 += p00 + p01; s1 += p10 + p11;
            *(float2*)&sm.QP[mrow][n * 8 + 2 * t]     = make_float2(p00, p01);
            *(float2*)&sm.QP[mrow + 8][n * 8 + 2 * t] = make_float2(p10, p11);
        }
        s0 += __shfl_xor_sync(0xffffffffu, s0, 1);
        s0 += __shfl_xor_sync(0xffffffffu, s0, 2);
        s1 += __shfl_xor_sync(0xffffffffu, s1, 1);
        s1 += __shfl_xor_sync(0xffffffffu, s1, 2);
        l0r = l0r * c0 + s0;  l1r = l1r * c1 + s1;
        m0r = mn0;            m1r = mn1;

        #pragma unroll
        for (int n = 0; n < 8; n++) {
            Oacc[n][0] *= c0; Oacc[n][1] *= c0;
            Oacc[n][2] *= c1; Oacc[n][3] *= c1;
        }
        __syncwarp();   // P rows are warp-private; warp-level sync suffices

        // ---- O += P @ V (3xTF32)
        #pragma unroll
        for (int ks = 0; ks < 8; ks++) {
            const int k = ks * 8;
            uint32_t ph[4], pl[4];
            split2(sm.QP[mrow][k + t],         ph[0], pl[0]);
            split2(sm.QP[mrow + 8][k + t],     ph[1], pl[1]);
            split2(sm.QP[mrow][k + t + 4],     ph[2], pl[2]);
            split2(sm.QP[mrow + 8][k + t + 4], ph[3], pl[3]);
            #pragma unroll
            for (int n = 0; n < 8; n++) {
                uint32_t vh[2], vl[2];
                split2(sm.Vs[k + t][n * 8 + g],     vh[0], vl[0]);
                split2(sm.Vs[k + t + 4][n * 8 + g], vh[1], vl[1]);
                mma_tf32(Oacc[n], ph, vh);
                mma_tf32(Oacc[n], ph, vl);
                mma_tf32(Oacc[n], pl, vh);
            }
        }
    }

    // ---- epilogue
    const float inv0 = 1.f / l0r, inv1 = 1.f / l1r;
    float* obase = g_oc + ((size_t)bb * S_ + q0) * HD_ + h * DH_;
    #pragma unroll
    for (int n = 0; n < 8; n++) {
        const int c = n * 8 + 2 * t;
        *(float2*)(obase + (size_t)mrow * HD_ + c) =
            make_float2(Oacc[n][0] * inv0, Oacc[n][1] * inv0);
        *(float2*)(obase + (size_t)(mrow + 8) * HD_ + c) =
            make_float2(Oacc[n][2] * inv1, Oacc[n][3] * inv1);
    }
}

// ---------------------------------------------------------------------------
extern "C" void kernel_launch(void* const* d_in, const int* in_sizes, int n_in,
                              void* d_out, int out_size)
{
    const float* x  = (const float*)d_in[0];
    const float* Wq = (const float*)d_in[1];
    const float* bq = (const float*)d_in[2];
    const float* Wk = (const float*)d_in[3];
    const float* bk = (const float*)d_in[4];
    const float* Wv = (const float*)d_in[5];
    const float* bv = (const float*)d_in[6];
    const float* Wo = (const float*)d_in[7];
    const float* bo = (const float*)d_in[8];
    float* out = (float*)d_out;

    void *p_wt_, *p_wot_, *p_bias_, *p_qkv_, *p_oc_;
    cudaGetSymbolAddress(&p_wt_,  g_wt);
    cudaGetSymbolAddress(&p_wot_, g_wot);
    cudaGetSymbolAddress(&p_bias_,g_bias);
    cudaGetSymbolAddress(&p_qkv_, g_qkv);
    cudaGetSymbolAddress(&p_oc_,  g_oc);

    cudaFuncSetAttribute(gemm_mma, cudaFuncAttributeMaxDynamicSharedMemorySize, G_SMEM);
    cudaFuncSetAttribute(attn_mma, cudaFuncAttributeMaxDynamicSharedMemorySize, A_SMEM);

    build_wt  <<<dim3(D_ / 32, DH_ / 32, 3 * H_), dim3(32, 8)>>>(Wq, Wk, Wv);
    build_wot <<<dim3(D_ / 32, D_ / 32), dim3(32, 8)>>>(Wo);
    build_bias<<<3, D_>>>(bq, bk, bv);

    gemm_mma<<<dim3(BS_ / 128, N3_ / 128), 256, G_SMEM>>>(
        x, (const float*)p_wt_, (const float*)p_bias_, (float*)p_qkv_, N3_);
    attn_mma<<<dim3(S_ / 128, B_ * H_), 256, A_SMEM>>>();
    gemm_mma<<<dim3(BS_ / 128, D_ / 128), 256, G_SMEM>>>(
        (const float*)p_oc_, (const float*)p_wot_, bo, out, D_);
}

// round 7
// speedup vs baseline: 2.0287x; 1.7503x over previous
#include <cuda_runtime.h>
#include <cuda_bf16.h>
#include <cstdint>

// Problem constants
static constexpr int B_  = 2;
static constexpr int S_  = 2048;
static constexpr int D_  = 1024;
static constexpr int H_  = 16;
static constexpr int DH_ = 64;
static constexpr int BS_ = B_ * S_;          // 4096
static constexpr int HD_ = H_ * DH_;         // 1024
static constexpr int N3_ = 3 * D_;           // 3072

// Pre-split operand storage (hi + lo bf16 pairs reconstruct fp32 to ~2^-18)
__device__ __nv_bfloat16 g_x_hi [BS_ * D_],  g_x_lo [BS_ * D_];
__device__ __nv_bfloat16 g_wt_hi[N3_ * D_],  g_wt_lo[N3_ * D_];   // qkv weights, [n][k]
__device__ __nv_bfloat16 g_wot_hi[D_ * D_],  g_wot_lo[D_ * D_];   // Wo transposed [n][k]
__device__ __nv_bfloat16 g_qkv_hi[BS_ * N3_], g_qkv_lo[BS_ * N3_]; // q|k|v, [4096][3072]
__device__ __nv_bfloat16 g_oc_hi[BS_ * HD_], g_oc_lo[BS_ * HD_];  // attn out concat
__device__ float g_bias[N3_];

// ---------------------------------------------------------------------------
// Helpers
// ---------------------------------------------------------------------------
__device__ __forceinline__ void cp16(uint32_t dst, const void* src) {
    asm volatile("cp.async.cg.shared.global [%0], [%1], 16;" :: "r"(dst), "l"(src));
}
#define CP_COMMIT() asm volatile("cp.async.commit_group;")
#define CP_WAIT(n)  asm volatile("cp.async.wait_group %0;" :: "n"(n))

__device__ __forceinline__ uint32_t smem_u32(const void* p) {
    uint32_t a;
    asm("{ .reg .u64 t; cvta.to.shared.u64 t, %1; cvt.u32.u64 %0, t; }" : "=r"(a) : "l"(p));
    return a;
}
__device__ __forceinline__ uint32_t lds32(const __nv_bfloat16* p) {
    return *(const uint32_t*)p;
}

// m16n8k16 bf16 MMA (A row-major, B col-major), fp32 accumulate
__device__ __forceinline__ void mma_bf16(float* c, const uint32_t* a, const uint32_t* b) {
    asm volatile(
        "mma.sync.aligned.m16n8k16.row.col.f32.bf16.bf16.f32 "
        "{%0,%1,%2,%3}, {%4,%5,%6,%7}, {%8,%9}, {%0,%1,%2,%3};"
        : "+f"(c[0]), "+f"(c[1]), "+f"(c[2]), "+f"(c[3])
        : "r"(a[0]), "r"(a[1]), "r"(a[2]), "r"(a[3]), "r"(b[0]), "r"(b[1]));
}

// Pack hi parts of (a,b) into bf16x2 word; return residuals
__device__ __forceinline__ uint32_t pack_hi(float a, float b, float& ra, float& rb) {
    __nv_bfloat16 ha = __float2bfloat16_rn(a), hb = __float2bfloat16_rn(b);
    ra = a - __bfloat162float(ha);
    rb = b - __bfloat162float(hb);
    return (uint32_t)__bfloat16_as_ushort(ha) | ((uint32_t)__bfloat16_as_ushort(hb) << 16);
}
__device__ __forceinline__ uint32_t pack_bf(float a, float b) {
    __nv_bfloat16 ha = __float2bfloat16_rn(a), hb = __float2bfloat16_rn(b);
    return (uint32_t)__bfloat16_as_ushort(ha) | ((uint32_t)__bfloat16_as_ushort(hb) << 16);
}

// ---------------------------------------------------------------------------
// Prep kernels
// ---------------------------------------------------------------------------
__global__ void prep_x(const float* __restrict__ x) {
    int i = (blockIdx.x * 256 + threadIdx.x) * 4;
    float4 v = *(const float4*)(x + i);
    float r0, r1, r2, r3;
    uint32_t h01 = pack_hi(v.x, v.y, r0, r1);
    uint32_t h23 = pack_hi(v.z, v.w, r2, r3);
    *(uint2*)(g_x_hi + i) = make_uint2(h01, h23);
    *(uint2*)(g_x_lo + i) = make_uint2(pack_bf(r0, r1), pack_bf(r2, r3));
}

__global__ void build_wt(const float* __restrict__ Wq, const float* __restrict__ Wk,
                         const float* __restrict__ Wv) {
    const int wsel = blockIdx.z >> 4, h = blockIdx.z & 15;
    const float* W = (wsel == 0) ? Wq : (wsel == 1) ? Wk : Wv;
    __shared__ float t[32][33];
    const int k0 = blockIdx.x * 32, d0 = blockIdx.y * 32;
    #pragma unroll
    for (int i = 0; i < 4; i++) {
        int k = k0 + threadIdx.y + i * 8;
        t[threadIdx.y + i * 8][threadIdx.x] = W[(size_t)h * D_ * DH_ + (size_t)k * DH_ + d0 + threadIdx.x];
    }
    __syncthreads();
    #pragma unroll
    for (int i = 0; i < 4; i++) {
        int d = d0 + threadIdx.y + i * 8;
        float v = t[threadIdx.x][threadIdx.y + i * 8];
        size_t idx = (size_t)(wsel * D_ + h * DH_ + d) * D_ + k0 + threadIdx.x;
        __nv_bfloat16 hv = __float2bfloat16_rn(v);
        g_wt_hi[idx] = hv;
        g_wt_lo[idx] = __float2bfloat16_rn(v - __bfloat162float(hv));
    }
}

__global__ void build_wot(const float* __restrict__ Wo) {
    __shared__ float t[32][33];
    const int k0 = blockIdx.x * 32, n0 = blockIdx.y * 32;
    #pragma unroll
    for (int i = 0; i < 4; i++)
        t[threadIdx.y + i * 8][threadIdx.x] = Wo[(size_t)(k0 + threadIdx.y + i * 8) * D_ + n0 + threadIdx.x];
    __syncthreads();
    #pragma unroll
    for (int i = 0; i < 4; i++) {
        int n = n0 + threadIdx.y + i * 8;
        float v = t[threadIdx.x][threadIdx.y + i * 8];
        size_t idx = (size_t)n * D_ + k0 + threadIdx.x;
        __nv_bfloat16 hv = __float2bfloat16_rn(v);
        g_wot_hi[idx] = hv;
        g_wot_lo[idx] = __float2bfloat16_rn(v - __bfloat162float(hv));
    }
}

__global__ void build_bias(const float* __restrict__ bq, const float* __restrict__ bk,
                           const float* __restrict__ bv) {
    const float* b = (blockIdx.x == 0) ? bq : (blockIdx.x == 1) ? bk : bv;
    g_bias[blockIdx.x * D_ + threadIdx.x] = b[threadIdx.x];
}

// ---------------------------------------------------------------------------
// Split-bf16 GEMM (4-product): C[m,n] = sum_k A[m,k]*Bt[n,k] + bias[n]
// A,Bt pre-split hi/lo bf16, K=1024. Tile 128x128, K-chunk 32, double buffered.
// Output: fp32 (Cf) or pre-split bf16 (Ch/Cl).
// ---------------------------------------------------------------------------
static constexpr int TSTR   = 40;             // bf16 per smem row (32 data + 8 pad)
static constexpr int TTILE  = 128 * TSTR;     // 5120 bf16
static constexpr int TSTAGE = 4 * TTILE;      // Ah|Al|Bh|Bl
static constexpr int G_SMEM = 2 * TSTAGE * 2; // 81920 bytes

extern __shared__ __nv_bfloat16 g_sm[];

__global__ __launch_bounds__(256) void gemm_bf16(
    const __nv_bfloat16* __restrict__ Ah, const __nv_bfloat16* __restrict__ Al,
    const __nv_bfloat16* __restrict__ Bh, const __nv_bfloat16* __restrict__ Bl,
    const float* __restrict__ bias,
    float* __restrict__ Cf, __nv_bfloat16* __restrict__ Ch, __nv_bfloat16* __restrict__ Cl,
    int Ntotal)
{
    const uint32_t sb = smem_u32(g_sm);
    const int tid = threadIdx.x, wid = tid >> 5, lane = tid & 31;
    const int g = lane >> 2, t = lane & 3;
    const int wm = wid >> 1, wn = wid & 1;
    const int m0 = blockIdx.x * 128, n0 = blockIdx.y * 128;

    float Cacc[2][8][4] = {};

    auto load_chunk = [&](int kc, int s) {
        #pragma unroll
        for (int p = 0; p < 8; p++) {
            int o = tid + p * 256;
            int arr = o >> 9, r = (o >> 2) & 127, sg = o & 3;
            const __nv_bfloat16* src =
                (arr == 0) ? Ah + (size_t)(m0 + r) * D_ + kc + sg * 8 :
                (arr == 1) ? Al + (size_t)(m0 + r) * D_ + kc + sg * 8 :
                (arr == 2) ? Bh + (size_t)(n0 + r) * D_ + kc + sg * 8 :
                             Bl + (size_t)(n0 + r) * D_ + kc + sg * 8;
            cp16(sb + (uint32_t)(s * TSTAGE + arr * TTILE + r * TSTR + sg * 8) * 2, src);
        }
        CP_COMMIT();
    };

    load_chunk(0, 0);

    for (int ch = 0; ch < 32; ch++) {
        const int s = ch & 1;
        if (ch < 31) { load_chunk((ch + 1) * 32, s ^ 1); CP_WAIT(1); }
        else         { CP_WAIT(0); }
        __syncthreads();

        const __nv_bfloat16* ah_t = g_sm + s * TSTAGE;
        const __nv_bfloat16* al_t = ah_t + TTILE;
        const __nv_bfloat16* bh_t = ah_t + 2 * TTILE;
        const __nv_bfloat16* bl_t = ah_t + 3 * TTILE;

        #pragma unroll
        for (int ks = 0; ks < 2; ks++) {
            const int kb = 2 * t + 16 * ks;
            uint32_t af[2][4], alr[2][4];
            #pragma unroll
            for (int i = 0; i < 2; i++) {
                const int row = wm * 32 + i * 16 + g;
                af[i][0]  = lds32(ah_t + row * TSTR + kb);
                af[i][1]  = lds32(ah_t + (row + 8) * TSTR + kb);
                af[i][2]  = lds32(ah_t + row * TSTR + kb + 8);
                af[i][3]  = lds32(ah_t + (row + 8) * TSTR + kb + 8);
                alr[i][0] = lds32(al_t + row * TSTR + kb);
                alr[i][1] = lds32(al_t + (row + 8) * TSTR + kb);
                alr[i][2] = lds32(al_t + row * TSTR + kb + 8);
                alr[i][3] = lds32(al_t + (row + 8) * TSTR + kb + 8);
            }
            #pragma unroll
            for (int n = 0; n < 8; n++) {
                const int rn = wn * 64 + n * 8 + g;
                uint32_t bhf[2] = { lds32(bh_t + rn * TSTR + kb), lds32(bh_t + rn * TSTR + kb + 8) };
                uint32_t blf[2] = { lds32(bl_t + rn * TSTR + kb), lds32(bl_t + rn * TSTR + kb + 8) };
                #pragma unroll
                for (int i = 0; i < 2; i++) {
                    mma_bf16(Cacc[i][n], af[i], bhf);
                    mma_bf16(Cacc[i][n], af[i], blf);
                    mma_bf16(Cacc[i][n], alr[i], bhf);
                    mma_bf16(Cacc[i][n], alr[i], blf);
                }
            }
        }
        __syncthreads();
    }

    #pragma unroll
    for (int i = 0; i < 2; i++) {
        const int r0 = m0 + wm * 32 + i * 16 + g;
        #pragma unroll
        for (int n = 0; n < 8; n++) {
            const int c = n0 + wn * 64 + n * 8 + 2 * t;
            float bx = __ldg(bias + c), by = __ldg(bias + c + 1);
            float v00 = Cacc[i][n][0] + bx, v01 = Cacc[i][n][1] + by;
            float v10 = Cacc[i][n][2] + bx, v11 = Cacc[i][n][3] + by;
            if (Cf) {
                *(float2*)(Cf + (size_t)r0 * Ntotal + c)       = make_float2(v00, v01);
                *(float2*)(Cf + (size_t)(r0 + 8) * Ntotal + c) = make_float2(v10, v11);
            } else {
                float ra, rb;
                *(uint32_t*)(Ch + (size_t)r0 * Ntotal + c) = pack_hi(v00, v01, ra, rb);
                *(uint32_t*)(Cl + (size_t)r0 * Ntotal + c) = pack_bf(ra, rb);
                *(uint32_t*)(Ch + (size_t)(r0 + 8) * Ntotal + c) = pack_hi(v10, v11, ra, rb);
                *(uint32_t*)(Cl + (size_t)(r0 + 8) * Ntotal + c) = pack_bf(ra, rb);
            }
        }
    }
}

// ---------------------------------------------------------------------------
// Flash attention, split-bf16 (3-product). CTA: 128 queries, 8 warps, j-tiles 64.
// ---------------------------------------------------------------------------
static constexpr int ASTR   = 72;                 // bf16 row stride
static constexpr int OFF_QH = 0;
static constexpr int OFF_QL = 128 * ASTR;         // 9216
static constexpr int OFF_KH = OFF_QL + 128 * ASTR;
static constexpr int OFF_KL = OFF_KH + 64 * ASTR;
static constexpr int OFF_VH = OFF_KL + 64 * ASTR;
static constexpr int OFF_VL = OFF_VH + 64 * ASTR;
static constexpr int A_SMEM = (OFF_VL + 64 * ASTR) * 2;   // 73728 bytes

__global__ __launch_bounds__(256) void attn_bf16()
{
    __nv_bfloat16* smb = g_sm;
    const uint32_t sb = smem_u32(smb);
    const int qt = blockIdx.x, bh = blockIdx.y;
    const int bb = bh >> 4, h = bh & 15;
    const int tid = threadIdx.x, wid = tid >> 5, lane = tid & 31;
    const int g = lane >> 2, t = lane & 3;
    const int q0 = qt * 128;
    const int mrow = wid * 16 + g;

    // ---- Q tile load (hi/lo) via cp.async
    #pragma unroll
    for (int p = 0; p < 8; p++) {
        int o = tid + p * 256;
        int arr = o >> 10, r = (o >> 3) & 127, sg = o & 7;
        const __nv_bfloat16* src = ((arr == 0) ? g_qkv_hi : g_qkv_lo)
            + (size_t)(bb * S_ + q0 + r) * N3_ + h * DH_ + sg * 8;
        cp16(sb + (uint32_t)((arr == 0 ? OFF_QH : OFF_QL) + r * ASTR + sg * 8) * 2, src);
    }
    CP_COMMIT(); CP_WAIT(0);
    __syncthreads();

    // ---- Q fragments -> registers
    uint32_t qh[4][4], ql[4][4];
    #pragma unroll
    for (int ks = 0; ks < 4; ks++) {
        const int kb = 2 * t + 16 * ks;
        qh[ks][0] = lds32(smb + OFF_QH + mrow * ASTR + kb);
        qh[ks][1] = lds32(smb + OFF_QH + (mrow + 8) * ASTR + kb);
        qh[ks][2] = lds32(smb + OFF_QH + mrow * ASTR + kb + 8);
        qh[ks][3] = lds32(smb + OFF_QH + (mrow + 8) * ASTR + kb + 8);
        ql[ks][0] = lds32(smb + OFF_QL + mrow * ASTR + kb);
        ql[ks][1] = lds32(smb + OFF_QL + (mrow + 8) * ASTR + kb);
        ql[ks][2] = lds32(smb + OFF_QL + mrow * ASTR + kb + 8);
        ql[ks][3] = lds32(smb + OFF_QL + (mrow + 8) * ASTR + kb + 8);
    }

    float Oacc[8][4] = {};
    float m0r = -1e30f, m1r = -1e30f, l0r = 0.f, l1r = 0.f;

    for (int j0 = 0; j0 < S_; j0 += 64) {
        __syncthreads();   // prior tile fully consumed

        // K tiles via cp.async
        #pragma unroll
        for (int p = 0; p < 4; p++) {
            int o = tid + p * 256;
            int arr = o >> 9, r = (o >> 3) & 63, sg = o & 7;
            const __nv_bfloat16* src = ((arr == 0) ? g_qkv_hi : g_qkv_lo)
                + (size_t)(bb * S_ + j0 + r) * N3_ + D_ + h * DH_ + sg * 8;
            cp16(sb + (uint32_t)((arr == 0 ? OFF_KH : OFF_KL) + r * ASTR + sg * 8) * 2, src);
        }
        CP_COMMIT();

        // V tiles: load + transpose to [d][j]
        {
            int jp = tid >> 3, ds = tid & 7;
            const size_t rbase = (size_t)(bb * S_ + j0 + 2 * jp) * N3_ + 2 * D_ + h * DH_ + ds * 8;
            uint4 h0 = *(const uint4*)(g_qkv_hi + rbase);
            uint4 h1 = *(const uint4*)(g_qkv_hi + rbase + N3_);
            uint4 l0 = *(const uint4*)(g_qkv_lo + rbase);
            uint4 l1 = *(const uint4*)(g_qkv_lo + rbase + N3_);
            const ushort* e0 = (const ushort*)&h0; const ushort* e1 = (const ushort*)&h1;
            const ushort* f0 = (const ushort*)&l0; const ushort* f1 = (const ushort*)&l1;
            #pragma unroll
            for (int q = 0; q < 8; q++) {
                *(uint32_t*)(smb + OFF_VH + (ds * 8 + q) * ASTR + 2 * jp) =
                    (uint32_t)e0[q] | ((uint32_t)e1[q] << 16);
                *(uint32_t*)(smb + OFF_VL + (ds * 8 + q) * ASTR + 2 * jp) =
                    (uint32_t)f0[q] | ((uint32_t)f1[q] << 16);
            }
        }
        CP_WAIT(0);
        __syncthreads();

        // ---- S = Q @ K^T (3-product)
        float Sacc[8][4] = {};
        #pragma unroll
        for (int ks = 0; ks < 4; ks++) {
            const int kb = 2 * t + 16 * ks;
            #pragma unroll
            for (int n = 0; n < 8; n++) {
                const int rn = n * 8 + g;
                uint32_t kh2[2] = { lds32(smb + OFF_KH + rn * ASTR + kb),
                                    lds32(smb + OFF_KH + rn * ASTR + kb + 8) };
                uint32_t kl2[2] = { lds32(smb + OFF_KL + rn * ASTR + kb),
                                    lds32(smb + OFF_KL + rn * ASTR + kb + 8) };
                mma_bf16(Sacc[n], qh[ks], kh2);
                mma_bf16(Sacc[n], qh[ks], kl2);
                mma_bf16(Sacc[n], ql[ks], kh2);
            }
        }
        #pragma unroll
        for (int n = 0; n < 8; n++) {
            Sacc[n][0] *= 0.125f; Sacc[n][1] *= 0.125f;
            Sacc[n][2] *= 0.125f; Sacc[n][3] *= 0.125f;
        }

        // ---- online softmax
        float mx0 = -1e30f, mx1 = -1e30f;
        #pragma unroll
        for (int n = 0; n < 8; n++) {
            mx0 = fmaxf(mx0, fmaxf(Sacc[n][0], Sacc[n][1]));
            mx1 = fmaxf(mx1, fmaxf(Sacc[n][2], Sacc[n][3]));
        }
        mx0 = fmaxf(mx0, __shfl_xor_sync(0xffffffffu, mx0, 1));
        mx0 = fmaxf(mx0, __shfl_xor_sync(0xffffffffu, mx0, 2));
        mx1 = fmaxf(mx1, __shfl_xor_sync(0xffffffffu, mx1, 1));
        mx1 = fmaxf(mx1, __shfl_xor_sync(0xffffffffu, mx1, 2));

        const float mn0 = fmaxf(m0r, mx0), mn1 = fmaxf(m1r, mx1);
        const float c0 = __expf(m0r - mn0), c1 = __expf(m1r - mn1);
        float s0 = 0.f, s1 = 0.f;
        #pragma unroll
        for (int n = 0; n < 8; n++) {
            float p00 = __expf(Sacc[n][0] - mn0);
            float p01 = __expf(Sacc[n][1] - mn0);
            float p10 = __expf(Sacc[n][2] - mn1);
            float p11 = __expf(Sacc[n][3] - mn1);
            s0 += p00 + p01; s1 += p10 + p11;
            float ra, rb;
            const int col = n * 8 + 2 * t;
            *(uint32_t*)(smb + OFF_QH + mrow * ASTR + col) = pack_hi(p00, p01, ra, rb);
            *(uint32_t*)(smb + OFF_QL + mrow * ASTR + col) = pack_bf(ra, rb);
            *(uint32_t*)(smb + OFF_QH + (mrow + 8) * ASTR + col) = pack_hi(p10, p11, ra, rb);
            *(uint32_t*)(smb + OFF_QL + (mrow + 8) * ASTR + col) = pack_bf(ra, rb);
        }
        s0 += __shfl_xor_sync(0xffffffffu, s0, 1);
        s0 += __shfl_xor_sync(0xffffffffu, s0, 2);
        s1 += __shfl_xor_sync(0xffffffffu, s1, 1);
        s1 += __shfl_xor_sync(0xffffffffu, s1, 2);
        l0r = l0r * c0 + s0;  l1r = l1r * c1 + s1;
        m0r = mn0;            m1r = mn1;

        #pragma unroll
        for (int n = 0; n < 8; n++) {
            Oacc[n][0] *= c0; Oacc[n][1] *= c0;
            Oacc[n][2] *= c1; Oacc[n][3] *= c1;
        }
        __syncwarp();   // P rows are warp-private

        // ---- O += P @ V (3-product)
        #pragma unroll
        for (int ks = 0; ks < 4; ks++) {
            const int kb = 2 * t + 16 * ks;
            uint32_t ph[4] = { lds32(smb + OFF_QH + mrow * ASTR + kb),
                               lds32(smb + OFF_QH + (mrow + 8) * ASTR + kb),
                               lds32(smb + OFF_QH + mrow * ASTR + kb + 8),
                               lds32(smb + OFF_QH + (mrow + 8) * ASTR + kb + 8) };
            uint32_t pl[4] = { lds32(smb + OFF_QL + mrow * ASTR + kb),
                               lds32(smb + OFF_QL + (mrow + 8) * ASTR + kb),
                               lds32(smb + OFF_QL + mrow * ASTR + kb + 8),
                               lds32(smb + OFF_QL + (mrow + 8) * ASTR + kb + 8) };
            #pragma unroll
            for (int n = 0; n < 8; n++) {
                const int rn = n * 8 + g;
                uint32_t vh2[2] = { lds32(smb + OFF_VH + rn * ASTR + kb),
                                    lds32(smb + OFF_VH + rn * ASTR + kb + 8) };
                uint32_t vl2[2] = { lds32(smb + OFF_VL + rn * ASTR + kb),
                                    lds32(smb + OFF_VL + rn * ASTR + kb + 8) };
                mma_bf16(Oacc[n], ph, vh2);
                mma_bf16(Oacc[n], ph, vl2);
                mma_bf16(Oacc[n], pl, vh2);
            }
        }
    }

    // ---- epilogue: normalize + pre-split write for proj GEMM
    const float inv0 = 1.f / l0r, inv1 = 1.f / l1r;
    __nv_bfloat16* oh = g_oc_hi + (size_t)(bb * S_ + q0) * HD_ + h * DH_;
    __nv_bfloat16* ol = g_oc_lo + (size_t)(bb * S_ + q0) * HD_ + h * DH_;
    #pragma unroll
    for (int n = 0; n < 8; n++) {
        const int c = n * 8 + 2 * t;
        float ra, rb;
        *(uint32_t*)(oh + (size_t)mrow * HD_ + c) =
            pack_hi(Oacc[n][0] * inv0, Oacc[n][1] * inv0, ra, rb);
        *(uint32_t*)(ol + (size_t)mrow * HD_ + c) = pack_bf(ra, rb);
        *(uint32_t*)(oh + (size_t)(mrow + 8) * HD_ + c) =
            pack_hi(Oacc[n][2] * inv1, Oacc[n][3] * inv1, ra, rb);
        *(uint32_t*)(ol + (size_t)(mrow + 8) * HD_ + c) = pack_bf(ra, rb);
    }
}

// ---------------------------------------------------------------------------
extern "C" void kernel_launch(void* const* d_in, const int* in_sizes, int n_in,
                              void* d_out, int out_size)
{
    const float* x  = (const float*)d_in[0];
    const float* Wq = (const float*)d_in[1];
    const float* bq = (const float*)d_in[2];
    const float* Wk = (const float*)d_in[3];
    const float* bk = (const float*)d_in[4];
    const float* Wv = (const float*)d_in[5];
    const float* bv = (const float*)d_in[6];
    const float* Wo = (const float*)d_in[7];
    const float* bo = (const float*)d_in[8];
    float* out = (float*)d_out;

    void *xh, *xl, *wth, *wtl, *woh, *wol, *qh, *qlp, *och, *ocl, *bs;
    cudaGetSymbolAddress(&xh,  g_x_hi);   cudaGetSymbolAddress(&xl,  g_x_lo);
    cudaGetSymbolAddress(&wth, g_wt_hi);  cudaGetSymbolAddress(&wtl, g_wt_lo);
    cudaGetSymbolAddress(&woh, g_wot_hi); cudaGetSymbolAddress(&wol, g_wot_lo);
    cudaGetSymbolAddress(&qh,  g_qkv_hi); cudaGetSymbolAddress(&qlp, g_qkv_lo);
    cudaGetSymbolAddress(&och, g_oc_hi);  cudaGetSymbolAddress(&ocl, g_oc_lo);
    cudaGetSymbolAddress(&bs,  g_bias);

    cudaFuncSetAttribute(gemm_bf16, cudaFuncAttributeMaxDynamicSharedMemorySize, G_SMEM);
    cudaFuncSetAttribute(attn_bf16, cudaFuncAttributeMaxDynamicSharedMemorySize, A_SMEM);

    prep_x   <<<BS_ * D_ / 1024, 256>>>(x);
    build_wt <<<dim3(D_ / 32, DH_ / 32, 3 * H_), dim3(32, 8)>>>(Wq, Wk, Wv);
    build_wot<<<dim3(D_ / 32, D_ / 32), dim3(32, 8)>>>(Wo);
    build_bias<<<3, D_>>>(bq, bk, bv);

    gemm_bf16<<<dim3(BS_ / 128, N3_ / 128), 256, G_SMEM>>>(
        (const __nv_bfloat16*)xh, (const __nv_bfloat16*)xl,
        (const __nv_bfloat16*)wth, (const __nv_bfloat16*)wtl,
        (const float*)bs, nullptr,
        (__nv_bfloat16*)qh, (__nv_bfloat16*)qlp, N3_);

    attn_bf16<<<dim3(S_ / 128, B_ * H_), 256, A_SMEM>>>();

    gemm_bf16<<<dim3(BS_ / 128, D_ / 128), 256, G_SMEM>>>(
        (const __nv_bfloat16*)och, (const __nv_bfloat16*)ocl,
        (const __nv_bfloat16*)woh, (const __nv_bfloat16*)wol,
        bo, out, nullptr, nullptr, D_);
}

// round 8
// speedup vs baseline: 2.2914x; 1.1295x over previous
#include <cuda_runtime.h>
#include <cuda_fp16.h>
#include <cstdint>

// Problem constants
static constexpr int B_  = 2;
static constexpr int S_  = 2048;
static constexpr int D_  = 1024;
static constexpr int H_  = 16;
static constexpr int DH_ = 64;
static constexpr int BS_ = B_ * S_;          // 4096
static constexpr int HD_ = H_ * DH_;         // 1024
static constexpr int N3_ = 3 * D_;           // 3072

// Pre-split operand storage (hi + lo fp16 pairs reconstruct fp32 to ~2^-22)
__device__ __half g_x_hi [BS_ * D_],  g_x_lo [BS_ * D_];
__device__ __half g_wt_hi[N3_ * D_],  g_wt_lo[N3_ * D_];   // qkv weights, [n][k]
__device__ __half g_wot_hi[D_ * D_],  g_wot_lo[D_ * D_];   // Wo transposed [n][k]
__device__ __half g_qkv_hi[BS_ * N3_], g_qkv_lo[BS_ * N3_]; // q|k|v, [4096][3072]
__device__ __half g_oc_hi[BS_ * HD_], g_oc_lo[BS_ * HD_];  // attn out concat
__device__ float g_bias[N3_];

// ---------------------------------------------------------------------------
// Helpers
// ---------------------------------------------------------------------------
__device__ __forceinline__ void cp16(uint32_t dst, const void* src) {
    asm volatile("cp.async.cg.shared.global [%0], [%1], 16;" :: "r"(dst), "l"(src));
}
#define CP_COMMIT() asm volatile("cp.async.commit_group;")
#define CP_WAIT(n)  asm volatile("cp.async.wait_group %0;" :: "n"(n))

__device__ __forceinline__ uint32_t smem_u32(const void* p) {
    uint32_t a;
    asm("{ .reg .u64 t; cvta.to.shared.u64 t, %1; cvt.u32.u64 %0, t; }" : "=r"(a) : "l"(p));
    return a;
}
__device__ __forceinline__ uint32_t lds32(const __half* p) {
    return *(const uint32_t*)p;
}

// m16n8k16 fp16 MMA (A row-major, B col-major), fp32 accumulate
__device__ __forceinline__ void mma_f16(float* c, const uint32_t* a, const uint32_t* b) {
    asm volatile(
        "mma.sync.aligned.m16n8k16.row.col.f32.f16.f16.f32 "
        "{%0,%1,%2,%3}, {%4,%5,%6,%7}, {%8,%9}, {%0,%1,%2,%3};"
        : "+f"(c[0]), "+f"(c[1]), "+f"(c[2]), "+f"(c[3])
        : "r"(a[0]), "r"(a[1]), "r"(a[2]), "r"(a[3]), "r"(b[0]), "r"(b[1]));
}

// Pack hi parts of (a,b) into fp16x2 word; return residuals
__device__ __forceinline__ uint32_t packh_hi(float a, float b, float& ra, float& rb) {
    __half ha = __float2half_rn(a), hb = __float2half_rn(b);
    ra = a - __half2float(ha);
    rb = b - __half2float(hb);
    return (uint32_t)__half_as_ushort(ha) | ((uint32_t)__half_as_ushort(hb) << 16);
}
__device__ __forceinline__ uint32_t packh(float a, float b) {
    return (uint32_t)__half_as_ushort(__float2half_rn(a)) |
           ((uint32_t)__half_as_ushort(__float2half_rn(b)) << 16);
}

// ---------------------------------------------------------------------------
// Prep kernels
// ---------------------------------------------------------------------------
__global__ void prep_x(const float* __restrict__ x) {
    int i = (blockIdx.x * 256 + threadIdx.x) * 4;
    float4 v = *(const float4*)(x + i);
    float r0, r1, r2, r3;
    uint32_t h01 = packh_hi(v.x, v.y, r0, r1);
    uint32_t h23 = packh_hi(v.z, v.w, r2, r3);
    *(uint2*)(g_x_hi + i) = make_uint2(h01, h23);
    *(uint2*)(g_x_lo + i) = make_uint2(packh(r0, r1), packh(r2, r3));
}

__global__ void build_wt(const float* __restrict__ Wq, const float* __restrict__ Wk,
                         const float* __restrict__ Wv) {
    const int wsel = blockIdx.z >> 4, h = blockIdx.z & 15;
    const float* W = (wsel == 0) ? Wq : (wsel == 1) ? Wk : Wv;
    __shared__ float t[32][33];
    const int k0 = blockIdx.x * 32, d0 = blockIdx.y * 32;
    #pragma unroll
    for (int i = 0; i < 4; i++) {
        int k = k0 + threadIdx.y + i * 8;
        t[threadIdx.y + i * 8][threadIdx.x] = W[(size_t)h * D_ * DH_ + (size_t)k * DH_ + d0 + threadIdx.x];
    }
    __syncthreads();
    #pragma unroll
    for (int i = 0; i < 4; i++) {
        int d = d0 + threadIdx.y + i * 8;
        float v = t[threadIdx.x][threadIdx.y + i * 8];
        size_t idx = (size_t)(wsel * D_ + h * DH_ + d) * D_ + k0 + threadIdx.x;
        __half hv = __float2half_rn(v);
        g_wt_hi[idx] = hv;
        g_wt_lo[idx] = __float2half_rn(v - __half2float(hv));
    }
}

__global__ void build_wot(const float* __restrict__ Wo) {
    __shared__ float t[32][33];
    const int k0 = blockIdx.x * 32, n0 = blockIdx.y * 32;
    #pragma unroll
    for (int i = 0; i < 4; i++)
        t[threadIdx.y + i * 8][threadIdx.x] = Wo[(size_t)(k0 + threadIdx.y + i * 8) * D_ + n0 + threadIdx.x];
    __syncthreads();
    #pragma unroll
    for (int i = 0; i < 4; i++) {
        int n = n0 + threadIdx.y + i * 8;
        float v = t[threadIdx.x][threadIdx.y + i * 8];
        size_t idx = (size_t)n * D_ + k0 + threadIdx.x;
        __half hv = __float2half_rn(v);
        g_wot_hi[idx] = hv;
        g_wot_lo[idx] = __float2half_rn(v - __half2float(hv));
    }
}

__global__ void build_bias(const float* __restrict__ bq, const float* __restrict__ bk,
                           const float* __restrict__ bv) {
    const float* b = (blockIdx.x == 0) ? bq : (blockIdx.x == 1) ? bk : bv;
    g_bias[blockIdx.x * D_ + threadIdx.x] = b[threadIdx.x];
}

// ---------------------------------------------------------------------------
// Split-fp16 GEMM (3-product): C[m,n] = sum_k A[m,k]*Bt[n,k] + bias[n]
// A,Bt pre-split hi/lo fp16, K=1024. Tile 128x128, K-chunk 32, double buffered.
// ---------------------------------------------------------------------------
static constexpr int TSTR   = 40;             // fp16 per smem row (32 data + 8 pad)
static constexpr int TTILE  = 128 * TSTR;     // 5120
static constexpr int TSTAGE = 4 * TTILE;      // Ah|Al|Bh|Bl
static constexpr int G_SMEM = 2 * TSTAGE * 2; // 81920 bytes

extern __shared__ __half g_sm[];

__global__ __launch_bounds__(256) void gemm_f16(
    const __half* __restrict__ Ah, const __half* __restrict__ Al,
    const __half* __restrict__ Bh, const __half* __restrict__ Bl,
    const float* __restrict__ bias,
    float* __restrict__ Cf, __half* __restrict__ Ch, __half* __restrict__ Cl,
    int Ntotal)
{
    const uint32_t sb = smem_u32(g_sm);
    const int tid = threadIdx.x, wid = tid >> 5, lane = tid & 31;
    const int g = lane >> 2, t = lane & 3;
    const int wm = wid >> 1, wn = wid & 1;
    const int m0 = blockIdx.x * 128, n0 = blockIdx.y * 128;

    float Cacc[2][8][4] = {};

    auto load_chunk = [&](int kc, int s) {
        #pragma unroll
        for (int p = 0; p < 8; p++) {
            int o = tid + p * 256;
            int arr = o >> 9, r = (o >> 2) & 127, sg = o & 3;
            const __half* src =
                (arr == 0) ? Ah + (size_t)(m0 + r) * D_ + kc + sg * 8 :
                (arr == 1) ? Al + (size_t)(m0 + r) * D_ + kc + sg * 8 :
                (arr == 2) ? Bh + (size_t)(n0 + r) * D_ + kc + sg * 8 :
                             Bl + (size_t)(n0 + r) * D_ + kc + sg * 8;
            cp16(sb + (uint32_t)(s * TSTAGE + arr * TTILE + r * TSTR + sg * 8) * 2, src);
        }
        CP_COMMIT();
    };

    load_chunk(0, 0);

    for (int ch = 0; ch < 32; ch++) {
        const int s = ch & 1;
        if (ch < 31) { load_chunk((ch + 1) * 32, s ^ 1); CP_WAIT(1); }
        else         { CP_WAIT(0); }
        __syncthreads();

        const __half* ah_t = g_sm + s * TSTAGE;
        const __half* al_t = ah_t + TTILE;
        const __half* bh_t = ah_t + 2 * TTILE;
        const __half* bl_t = ah_t + 3 * TTILE;

        #pragma unroll
        for (int ks = 0; ks < 2; ks++) {
            const int kb = 2 * t + 16 * ks;
            uint32_t af[2][4], alr[2][4];
            #pragma unroll
            for (int i = 0; i < 2; i++) {
                const int row = wm * 32 + i * 16 + g;
                af[i][0]  = lds32(ah_t + row * TSTR + kb);
                af[i][1]  = lds32(ah_t + (row + 8) * TSTR + kb);
                af[i][2]  = lds32(ah_t + row * TSTR + kb + 8);
                af[i][3]  = lds32(ah_t + (row + 8) * TSTR + kb + 8);
                alr[i][0] = lds32(al_t + row * TSTR + kb);
                alr[i][1] = lds32(al_t + (row + 8) * TSTR + kb);
                alr[i][2] = lds32(al_t + row * TSTR + kb + 8);
                alr[i][3] = lds32(al_t + (row + 8) * TSTR + kb + 8);
            }
            #pragma unroll
            for (int n = 0; n < 8; n++) {
                const int rn = wn * 64 + n * 8 + g;
                uint32_t bhf[2] = { lds32(bh_t + rn * TSTR + kb), lds32(bh_t + rn * TSTR + kb + 8) };
                uint32_t blf[2] = { lds32(bl_t + rn * TSTR + kb), lds32(bl_t + rn * TSTR + kb + 8) };
                #pragma unroll
                for (int i = 0; i < 2; i++) {
                    mma_f16(Cacc[i][n], af[i], bhf);
                    mma_f16(Cacc[i][n], af[i], blf);
                    mma_f16(Cacc[i][n], alr[i], bhf);
                }
            }
        }
        __syncthreads();
    }

    #pragma unroll
    for (int i = 0; i < 2; i++) {
        const int r0 = m0 + wm * 32 + i * 16 + g;
        #pragma unroll
        for (int n = 0; n < 8; n++) {
            const int c = n0 + wn * 64 + n * 8 + 2 * t;
            float bx = __ldg(bias + c), by = __ldg(bias + c + 1);
            float v00 = Cacc[i][n][0] + bx, v01 = Cacc[i][n][1] + by;
            float v10 = Cacc[i][n][2] + bx, v11 = Cacc[i][n][3] + by;
            if (Cf) {
                *(float2*)(Cf + (size_t)r0 * Ntotal + c)       = make_float2(v00, v01);
                *(float2*)(Cf + (size_t)(r0 + 8) * Ntotal + c) = make_float2(v10, v11);
            } else {
                float ra, rb;
                *(uint32_t*)(Ch + (size_t)r0 * Ntotal + c) = packh_hi(v00, v01, ra, rb);
                *(uint32_t*)(Cl + (size_t)r0 * Ntotal + c) = packh(ra, rb);
                *(uint32_t*)(Ch + (size_t)(r0 + 8) * Ntotal + c) = packh_hi(v10, v11, ra, rb);
                *(uint32_t*)(Cl + (size_t)(r0 + 8) * Ntotal + c) = packh(ra, rb);
            }
        }
    }
}

// ---------------------------------------------------------------------------
// Flash attention, split-fp16 (3-product), register-resident P.
// CTA: 128 queries, 8 warps; j-tiles of 64.
// ---------------------------------------------------------------------------
static constexpr int ASTR   = 72;                 // fp16 row stride
static constexpr int OFF_QH = 0;
static constexpr int OFF_QL = 128 * ASTR;
static constexpr int OFF_KH = OFF_QL + 128 * ASTR;
static constexpr int OFF_KL = OFF_KH + 64 * ASTR;
static constexpr int OFF_VH = OFF_KL + 64 * ASTR;
static constexpr int OFF_VL = OFF_VH + 64 * ASTR;
static constexpr int A_SMEM = (OFF_VL + 64 * ASTR) * 2;   // 73728 bytes

__global__ __launch_bounds__(256) void attn_f16()
{
    __half* smb = g_sm;
    const uint32_t sb = smem_u32(smb);
    const int qt = blockIdx.x, bh = blockIdx.y;
    const int bb = bh >> 4, h = bh & 15;
    const int tid = threadIdx.x, wid = tid >> 5, lane = tid & 31;
    const int g = lane >> 2, t = lane & 3;
    const int q0 = qt * 128;
    const int mrow = wid * 16 + g;

    // ---- Q tile load (hi/lo) via cp.async
    #pragma unroll
    for (int p = 0; p < 8; p++) {
        int o = tid + p * 256;
        int arr = o >> 10, r = (o >> 3) & 127, sg = o & 7;
        const __half* src = ((arr == 0) ? g_qkv_hi : g_qkv_lo)
            + (size_t)(bb * S_ + q0 + r) * N3_ + h * DH_ + sg * 8;
        cp16(sb + (uint32_t)((arr == 0 ? OFF_QH : OFF_QL) + r * ASTR + sg * 8) * 2, src);
    }
    CP_COMMIT(); CP_WAIT(0);
    __syncthreads();

    // ---- Q fragments -> registers
    uint32_t qh[4][4], ql[4][4];
    #pragma unroll
    for (int ks = 0; ks < 4; ks++) {
        const int kb = 2 * t + 16 * ks;
        qh[ks][0] = lds32(smb + OFF_QH + mrow * ASTR + kb);
        qh[ks][1] = lds32(smb + OFF_QH + (mrow + 8) * ASTR + kb);
        qh[ks][2] = lds32(smb + OFF_QH + mrow * ASTR + kb + 8);
        qh[ks][3] = lds32(smb + OFF_QH + (mrow + 8) * ASTR + kb + 8);
        ql[ks][0] = lds32(smb + OFF_QL + mrow * ASTR + kb);
        ql[ks][1] = lds32(smb + OFF_QL + (mrow + 8) * ASTR + kb);
        ql[ks][2] = lds32(smb + OFF_QL + mrow * ASTR + kb + 8);
        ql[ks][3] = lds32(smb + OFF_QL + (mrow + 8) * ASTR + kb + 8);
    }

    float Oacc[8][4] = {};
    float m0r = -1e30f, m1r = -1e30f, l0r = 0.f, l1r = 0.f;

    for (int j0 = 0; j0 < S_; j0 += 64) {
        __syncthreads();   // prior K/V tile fully consumed

        // K tiles via cp.async
        #pragma unroll
        for (int p = 0; p < 4; p++) {
            int o = tid + p * 256;
            int arr = o >> 9, r = (o >> 3) & 63, sg = o & 7;
            const __half* src = ((arr == 0) ? g_qkv_hi : g_qkv_lo)
                + (size_t)(bb * S_ + j0 + r) * N3_ + D_ + h * DH_ + sg * 8;
            cp16(sb + (uint32_t)((arr == 0 ? OFF_KH : OFF_KL) + r * ASTR + sg * 8) * 2, src);
        }
        CP_COMMIT();

        // V tiles: load + transpose to [d][j]
        {
            int jp = tid >> 3, ds = tid & 7;
            const size_t rbase = (size_t)(bb * S_ + j0 + 2 * jp) * N3_ + 2 * D_ + h * DH_ + ds * 8;
            uint4 h0 = *(const uint4*)(g_qkv_hi + rbase);
            uint4 h1 = *(const uint4*)(g_qkv_hi + rbase + N3_);
            uint4 l0 = *(const uint4*)(g_qkv_lo + rbase);
            uint4 l1 = *(const uint4*)(g_qkv_lo + rbase + N3_);
            const ushort* e0 = (const ushort*)&h0; const ushort* e1 = (const ushort*)&h1;
            const ushort* f0 = (const ushort*)&l0; const ushort* f1 = (const ushort*)&l1;
            #pragma unroll
            for (int q = 0; q < 8; q++) {
                *(uint32_t*)(smb + OFF_VH + (ds * 8 + q) * ASTR + 2 * jp) =
                    (uint32_t)e0[q] | ((uint32_t)e1[q] << 16);
                *(uint32_t*)(smb + OFF_VL + (ds * 8 + q) * ASTR + 2 * jp) =
                    (uint32_t)f0[q] | ((uint32_t)f1[q] << 16);
            }
        }
        CP_WAIT(0);
        __syncthreads();

        // ---- S = Q @ K^T (3-product)
        float Sacc[8][4] = {};
        #pragma unroll
        for (int ks = 0; ks < 4; ks++) {
            const int kb = 2 * t + 16 * ks;
            #pragma unroll
            for (int n = 0; n < 8; n++) {
                const int rn = n * 8 + g;
                uint32_t kh2[2] = { lds32(smb + OFF_KH + rn * ASTR + kb),
                                    lds32(smb + OFF_KH + rn * ASTR + kb + 8) };
                uint32_t kl2[2] = { lds32(smb + OFF_KL + rn * ASTR + kb),
                                    lds32(smb + OFF_KL + rn * ASTR + kb + 8) };
                mma_f16(Sacc[n], qh[ks], kh2);
                mma_f16(Sacc[n], qh[ks], kl2);
                mma_f16(Sacc[n], ql[ks], kh2);
            }
        }
        #pragma unroll
        for (int n = 0; n < 8; n++) {
            Sacc[n][0] *= 0.125f; Sacc[n][1] *= 0.125f;
            Sacc[n][2] *= 0.125f; Sacc[n][3] *= 0.125f;
        }

        // ---- online softmax (rows mrow, mrow+8; quad shares a row)
        float mx0 = -1e30f, mx1 = -1e30f;
        #pragma unroll
        for (int n = 0; n < 8; n++) {
            mx0 = fmaxf(mx0, fmaxf(Sacc[n][0], Sacc[n][1]));
            mx1 = fmaxf(mx1, fmaxf(Sacc[n][2], Sacc[n][3]));
        }
        mx0 = fmaxf(mx0, __shfl_xor_sync(0xffffffffu, mx0, 1));
        mx0 = fmaxf(mx0, __shfl_xor_sync(0xffffffffu, mx0, 2));
        mx1 = fmaxf(mx1, __shfl_xor_sync(0xffffffffu, mx1, 1));
        mx1 = fmaxf(mx1, __shfl_xor_sync(0xffffffffu, mx1, 2));

        const float mn0 = fmaxf(m0r, mx0), mn1 = fmaxf(m1r, mx1);
        const float c0 = __expf(m0r - mn0), c1 = __expf(m1r - mn1);
        float s0 = 0.f, s1 = 0.f;
        #pragma unroll
        for (int n = 0; n < 8; n++) {
            Sacc[n][0] = __expf(Sacc[n][0] - mn0);
            Sacc[n][1] = __expf(Sacc[n][1] - mn0);
            Sacc[n][2] = __expf(Sacc[n][2] - mn1);
            Sacc[n][3] = __expf(Sacc[n][3] - mn1);
            s0 += Sacc[n][0] + Sacc[n][1];
            s1 += Sacc[n][2] + Sacc[n][3];
        }
        s0 += __shfl_xor_sync(0xffffffffu, s0, 1);
        s0 += __shfl_xor_sync(0xffffffffu, s0, 2);
        s1 += __shfl_xor_sync(0xffffffffu, s1, 1);
        s1 += __shfl_xor_sync(0xffffffffu, s1, 2);
        l0r = l0r * c0 + s0;  l1r = l1r * c1 + s1;
        m0r = mn0;            m1r = mn1;

        #pragma unroll
        for (int n = 0; n < 8; n++) {
            Oacc[n][0] *= c0; Oacc[n][1] *= c0;
            Oacc[n][2] *= c1; Oacc[n][3] *= c1;
        }

        // ---- O += P @ V (3-product), P fragments built directly from Sacc.
        // A-frag for k-block ks:  a0 = P[g][16ks+2t,+1]      = Sacc[2ks][0,1]
        //                         a1 = P[g+8][16ks+2t,+1]    = Sacc[2ks][2,3]
        //                         a2 = P[g][16ks+8+2t,+1]    = Sacc[2ks+1][0,1]
        //                         a3 = P[g+8][16ks+8+2t,+1]  = Sacc[2ks+1][2,3]
        #pragma unroll
        for (int ks = 0; ks < 4; ks++) {
            const int kb = 2 * t + 16 * ks;
            uint32_t ph[4], pl[4];
            float r0a, r0b, r1a, r1b;
            ph[0] = packh_hi(Sacc[2*ks][0],   Sacc[2*ks][1],   r0a, r0b);
            pl[0] = packh(r0a, r0b);
            ph[1] = packh_hi(Sacc[2*ks][2],   Sacc[2*ks][3],   r1a, r1b);
            pl[1] = packh(r1a, r1b);
            ph[2] = packh_hi(Sacc[2*ks+1][0], Sacc[2*ks+1][1], r0a, r0b);
            pl[2] = packh(r0a, r0b);
            ph[3] = packh_hi(Sacc[2*ks+1][2], Sacc[2*ks+1][3], r1a, r1b);
            pl[3] = packh(r1a, r1b);
            #pragma unroll
            for (int n = 0; n < 8; n++) {
                const int rn = n * 8 + g;
                uint32_t vh2[2] = { lds32(smb + OFF_VH + rn * ASTR + kb),
                                    lds32(smb + OFF_VH + rn * ASTR + kb + 8) };
                uint32_t vl2[2] = { lds32(smb + OFF_VL + rn * ASTR + kb),
                                    lds32(smb + OFF_VL + rn * ASTR + kb + 8) };
                mma_f16(Oacc[n], ph, vh2);
                mma_f16(Oacc[n], ph, vl2);
                mma_f16(Oacc[n], pl, vh2);
            }
        }
    }

    // ---- epilogue: normalize + pre-split write for proj GEMM
    const float inv0 = 1.f / l0r, inv1 = 1.f / l1r;
    __half* oh = g_oc_hi + (size_t)(bb * S_ + q0) * HD_ + h * DH_;
    __half* ol = g_oc_lo + (size_t)(bb * S_ + q0) * HD_ + h * DH_;
    #pragma unroll
    for (int n = 0; n < 8; n++) {
        const int c = n * 8 + 2 * t;
        float ra, rb;
        *(uint32_t*)(oh + (size_t)mrow * HD_ + c) =
            packh_hi(Oacc[n][0] * inv0, Oacc[n][1] * inv0, ra, rb);
        *(uint32_t*)(ol + (size_t)mrow * HD_ + c) = packh(ra, rb);
        *(uint32_t*)(oh + (size_t)(mrow + 8) * HD_ + c) =
            packh_hi(Oacc[n][2] * inv1, Oacc[n][3] * inv1, ra, rb);
        *(uint32_t*)(ol + (size_t)(mrow + 8) * HD_ + c) = packh(ra, rb);
    }
}

// ---------------------------------------------------------------------------
extern "C" void kernel_launch(void* const* d_in, const int* in_sizes, int n_in,
                              void* d_out, int out_size)
{
    const float* x  = (const float*)d_in[0];
    const float* Wq = (const float*)d_in[1];
    const float* bq = (const float*)d_in[2];
    const float* Wk = (const float*)d_in[3];
    const float* bk = (const float*)d_in[4];
    const float* Wv = (const float*)d_in[5];
    const float* bv = (const float*)d_in[6];
    const float* Wo = (const float*)d_in[7];
    const float* bo = (const float*)d_in[8];
    float* out = (float*)d_out;

    void *xh, *xl, *wth, *wtl, *woh, *wol, *qh, *qlp, *och, *ocl, *bs;
    cudaGetSymbolAddress(&xh,  g_x_hi);   cudaGetSymbolAddress(&xl,  g_x_lo);
    cudaGetSymbolAddress(&wth, g_wt_hi);  cudaGetSymbolAddress(&wtl, g_wt_lo);
    cudaGetSymbolAddress(&woh, g_wot_hi); cudaGetSymbolAddress(&wol, g_wot_lo);
    cudaGetSymbolAddress(&qh,  g_qkv_hi); cudaGetSymbolAddress(&qlp, g_qkv_lo);
    cudaGetSymbolAddress(&och, g_oc_hi);  cudaGetSymbolAddress(&ocl, g_oc_lo);
    cudaGetSymbolAddress(&bs,  g_bias);

    cudaFuncSetAttribute(gemm_f16, cudaFuncAttributeMaxDynamicSharedMemorySize, G_SMEM);
    cudaFuncSetAttribute(attn_f16, cudaFuncAttributeMaxDynamicSharedMemorySize, A_SMEM);

    prep_x   <<<BS_ * D_ / 1024, 256>>>(x);
    build_wt <<<dim3(D_ / 32, DH_ / 32, 3 * H_), dim3(32, 8)>>>(Wq, Wk, Wv);
    build_wot<<<dim3(D_ / 32, D_ / 32), dim3(32, 8)>>>(Wo);
    build_bias<<<3, D_>>>(bq, bk, bv);

    gemm_f16<<<dim3(BS_ / 128, N3_ / 128), 256, G_SMEM>>>(
        (const __half*)xh, (const __half*)xl,
        (const __half*)wth, (const __half*)wtl,
        (const float*)bs, nullptr,
        (__half*)qh, (__half*)qlp, N3_);

    attn_f16<<<dim3(S_ / 128, B_ * H_), 256, A_SMEM>>>();

    gemm_f16<<<dim3(BS_ / 128, D_ / 128), 256, G_SMEM>>>(
        (const __half*)och, (const __half*)ocl,
        (const __half*)woh, (const __half*)wol,
        bo, out, nullptr, nullptr, D_);
}

// round 9
// speedup vs baseline: 2.6733x; 1.1667x over previous
#include <cuda_runtime.h>
#include <cuda_fp16.h>
#include <cstdint>

// Problem constants
static constexpr int B_  = 2;
static constexpr int S_  = 2048;
static constexpr int D_  = 1024;
static constexpr int H_  = 16;
static constexpr int DH_ = 64;
static constexpr int BS_ = B_ * S_;          // 4096
static constexpr int HD_ = H_ * DH_;         // 1024
static constexpr int N3_ = 3 * D_;           // 3072

// Pre-split operand storage (hi + lo fp16 pairs reconstruct fp32 to ~2^-22)
__device__ __half g_x_hi [BS_ * D_],  g_x_lo [BS_ * D_];
__device__ __half g_wt_hi[N3_ * D_],  g_wt_lo[N3_ * D_];
__device__ __half g_wot_hi[D_ * D_],  g_wot_lo[D_ * D_];
__device__ __half g_qkv_hi[BS_ * N3_], g_qkv_lo[BS_ * N3_];
__device__ __half g_oc_hi[BS_ * HD_], g_oc_lo[BS_ * HD_];
__device__ float g_bias[N3_];

// ---------------------------------------------------------------------------
// Helpers
// ---------------------------------------------------------------------------
__device__ __forceinline__ void cp16(uint32_t dst, const void* src) {
    asm volatile("cp.async.cg.shared.global [%0], [%1], 16;" :: "r"(dst), "l"(src));
}
#define CP_COMMIT() asm volatile("cp.async.commit_group;")
#define CP_WAIT(n)  asm volatile("cp.async.wait_group %0;" :: "n"(n))

__device__ __forceinline__ uint32_t smem_u32(const void* p) {
    uint32_t a;
    asm("{ .reg .u64 t; cvta.to.shared.u64 t, %1; cvt.u32.u64 %0, t; }" : "=r"(a) : "l"(p));
    return a;
}
__device__ __forceinline__ uint32_t lds32(const __half* p) {
    return *(const uint32_t*)p;
}
__device__ __forceinline__ void ldsm_x4(uint32_t& r0, uint32_t& r1, uint32_t& r2, uint32_t& r3,
                                        uint32_t addr) {
    asm volatile("ldmatrix.sync.aligned.m8n8.x4.shared.b16 {%0,%1,%2,%3}, [%4];"
                 : "=r"(r0), "=r"(r1), "=r"(r2), "=r"(r3) : "r"(addr));
}
__device__ __forceinline__ void ldsm_x4t(uint32_t& r0, uint32_t& r1, uint32_t& r2, uint32_t& r3,
                                         uint32_t addr) {
    asm volatile("ldmatrix.sync.aligned.m8n8.x4.trans.shared.b16 {%0,%1,%2,%3}, [%4];"
                 : "=r"(r0), "=r"(r1), "=r"(r2), "=r"(r3) : "r"(addr));
}

// m16n8k16 fp16 MMA (A row-major, B col-major), fp32 accumulate
__device__ __forceinline__ void mma_f16(float* c, const uint32_t* a, const uint32_t* b) {
    asm volatile(
        "mma.sync.aligned.m16n8k16.row.col.f32.f16.f16.f32 "
        "{%0,%1,%2,%3}, {%4,%5,%6,%7}, {%8,%9}, {%0,%1,%2,%3};"
        : "+f"(c[0]), "+f"(c[1]), "+f"(c[2]), "+f"(c[3])
        : "r"(a[0]), "r"(a[1]), "r"(a[2]), "r"(a[3]), "r"(b[0]), "r"(b[1]));
}
__device__ __forceinline__ void mma_f16_2(float* c, const uint32_t* a, uint32_t b0, uint32_t b1) {
    asm volatile(
        "mma.sync.aligned.m16n8k16.row.col.f32.f16.f16.f32 "
        "{%0,%1,%2,%3}, {%4,%5,%6,%7}, {%8,%9}, {%0,%1,%2,%3};"
        : "+f"(c[0]), "+f"(c[1]), "+f"(c[2]), "+f"(c[3])
        : "r"(a[0]), "r"(a[1]), "r"(a[2]), "r"(a[3]), "r"(b0), "r"(b1));
}

__device__ __forceinline__ uint32_t packh_hi(float a, float b, float& ra, float& rb) {
    __half ha = __float2half_rn(a), hb = __float2half_rn(b);
    ra = a - __half2float(ha);
    rb = b - __half2float(hb);
    return (uint32_t)__half_as_ushort(ha) | ((uint32_t)__half_as_ushort(hb) << 16);
}
__device__ __forceinline__ uint32_t packh(float a, float b) {
    return (uint32_t)__half_as_ushort(__float2half_rn(a)) |
           ((uint32_t)__half_as_ushort(__float2half_rn(b)) << 16);
}

// ---------------------------------------------------------------------------
// Prep kernels
// ---------------------------------------------------------------------------
__global__ void prep_x(const float* __restrict__ x) {
    int i = (blockIdx.x * 256 + threadIdx.x) * 4;
    float4 v = *(const float4*)(x + i);
    float r0, r1, r2, r3;
    uint32_t h01 = packh_hi(v.x, v.y, r0, r1);
    uint32_t h23 = packh_hi(v.z, v.w, r2, r3);
    *(uint2*)(g_x_hi + i) = make_uint2(h01, h23);
    *(uint2*)(g_x_lo + i) = make_uint2(packh(r0, r1), packh(r2, r3));
}

__global__ void build_wt(const float* __restrict__ Wq, const float* __restrict__ Wk,
                         const float* __restrict__ Wv) {
    const int wsel = blockIdx.z >> 4, h = blockIdx.z & 15;
    const float* W = (wsel == 0) ? Wq : (wsel == 1) ? Wk : Wv;
    __shared__ float t[32][33];
    const int k0 = blockIdx.x * 32, d0 = blockIdx.y * 32;
    #pragma unroll
    for (int i = 0; i < 4; i++) {
        int k = k0 + threadIdx.y + i * 8;
        t[threadIdx.y + i * 8][threadIdx.x] = W[(size_t)h * D_ * DH_ + (size_t)k * DH_ + d0 + threadIdx.x];
    }
    __syncthreads();
    #pragma unroll
    for (int i = 0; i < 4; i++) {
        int d = d0 + threadIdx.y + i * 8;
        float v = t[threadIdx.x][threadIdx.y + i * 8];
        size_t idx = (size_t)(wsel * D_ + h * DH_ + d) * D_ + k0 + threadIdx.x;
        __half hv = __float2half_rn(v);
        g_wt_hi[idx] = hv;
        g_wt_lo[idx] = __float2half_rn(v - __half2float(hv));
    }
}

__global__ void build_wot(const float* __restrict__ Wo) {
    __shared__ float t[32][33];
    const int k0 = blockIdx.x * 32, n0 = blockIdx.y * 32;
    #pragma unroll
    for (int i = 0; i < 4; i++)
        t[threadIdx.y + i * 8][threadIdx.x] = Wo[(size_t)(k0 + threadIdx.y + i * 8) * D_ + n0 + threadIdx.x];
    __syncthreads();
    #pragma unroll
    for (int i = 0; i < 4; i++) {
        int n = n0 + threadIdx.y + i * 8;
        float v = t[threadIdx.x][threadIdx.y + i * 8];
        size_t idx = (size_t)n * D_ + k0 + threadIdx.x;
        __half hv = __float2half_rn(v);
        g_wot_hi[idx] = hv;
        g_wot_lo[idx] = __float2half_rn(v - __half2float(hv));
    }
}

__global__ void build_bias(const float* __restrict__ bq, const float* __restrict__ bk,
                           const float* __restrict__ bv) {
    const float* b = (blockIdx.x == 0) ? bq : (blockIdx.x == 1) ? bk : bv;
    g_bias[blockIdx.x * D_ + threadIdx.x] = b[threadIdx.x];
}

// ---------------------------------------------------------------------------
// Split-fp16 GEMM (3-product), ldmatrix fragment loads.
// ---------------------------------------------------------------------------
static constexpr int TSTR   = 40;             // fp16 per smem row
static constexpr int TTILE  = 128 * TSTR;
static constexpr int TSTAGE = 4 * TTILE;
static constexpr int G_SMEM = 2 * TSTAGE * 2; // 81920 bytes

extern __shared__ __half g_sm[];

__global__ __launch_bounds__(256) void gemm_f16(
    const __half* __restrict__ Ah, const __half* __restrict__ Al,
    const __half* __restrict__ Bh, const __half* __restrict__ Bl,
    const float* __restrict__ bias,
    float* __restrict__ Cf, __half* __restrict__ Ch, __half* __restrict__ Cl,
    int Ntotal)
{
    const uint32_t sb = smem_u32(g_sm);
    const int tid = threadIdx.x, wid = tid >> 5, lane = tid & 31;
    const int g = lane >> 2, t = lane & 3;
    const int grp = lane >> 3, l7 = lane & 7;
    const int wm = wid >> 1, wn = wid & 1;
    const int m0 = blockIdx.x * 128, n0blk = blockIdx.y * 128;

    // ldmatrix lane offsets (halves)
    const int a_off = ((grp & 1) * 8 + l7) * TSTR + (grp >> 1) * 8;
    const int b_off = ((grp >> 1) * 8 + l7) * TSTR + (grp & 1) * 8;

    float Cacc[2][8][4] = {};

    auto load_chunk = [&](int kc, int s) {
        #pragma unroll
        for (int p = 0; p < 8; p++) {
            int o = tid + p * 256;
            int arr = o >> 9, r = (o >> 2) & 127, sg = o & 3;
            const __half* src =
                (arr == 0) ? Ah + (size_t)(m0 + r) * D_ + kc + sg * 8 :
                (arr == 1) ? Al + (size_t)(m0 + r) * D_ + kc + sg * 8 :
                (arr == 2) ? Bh + (size_t)(n0blk + r) * D_ + kc + sg * 8 :
                             Bl + (size_t)(n0blk + r) * D_ + kc + sg * 8;
            cp16(sb + (uint32_t)(s * TSTAGE + arr * TTILE + r * TSTR + sg * 8) * 2, src);
        }
        CP_COMMIT();
    };

    load_chunk(0, 0);

    for (int ch = 0; ch < 32; ch++) {
        const int s = ch & 1;
        if (ch < 31) { load_chunk((ch + 1) * 32, s ^ 1); CP_WAIT(1); }
        else         { CP_WAIT(0); }
        __syncthreads();

        const uint32_t ah_b = sb + (uint32_t)(s * TSTAGE) * 2;
        const uint32_t al_b = ah_b + TTILE * 2;
        const uint32_t bh_b = ah_b + 2 * TTILE * 2;
        const uint32_t bl_b = ah_b + 3 * TTILE * 2;

        #pragma unroll
        for (int ks = 0; ks < 2; ks++) {
            const int kb0 = 16 * ks;
            uint32_t af[2][4], alr[2][4];
            #pragma unroll
            for (int i = 0; i < 2; i++) {
                const int rb = (wm * 32 + i * 16) * TSTR + kb0;
                ldsm_x4(af[i][0], af[i][1], af[i][2], af[i][3],
                        ah_b + (uint32_t)(rb + a_off) * 2);
                ldsm_x4(alr[i][0], alr[i][1], alr[i][2], alr[i][3],
                        al_b + (uint32_t)(rb + a_off) * 2);
            }
            #pragma unroll
            for (int np = 0; np < 4; np++) {
                const int n = np * 2;
                const int rb = (wn * 64 + n * 8) * TSTR + kb0;
                uint32_t bh0, bh1, bh2, bh3, bl0, bl1, bl2, bl3;
                ldsm_x4(bh0, bh1, bh2, bh3, bh_b + (uint32_t)(rb + b_off) * 2);
                ldsm_x4(bl0, bl1, bl2, bl3, bl_b + (uint32_t)(rb + b_off) * 2);
                #pragma unroll
                for (int i = 0; i < 2; i++) {
                    mma_f16_2(Cacc[i][n],     af[i],  bh0, bh1);
                    mma_f16_2(Cacc[i][n],     af[i],  bl0, bl1);
                    mma_f16_2(Cacc[i][n],     alr[i], bh0, bh1);
                    mma_f16_2(Cacc[i][n + 1], af[i],  bh2, bh3);
                    mma_f16_2(Cacc[i][n + 1], af[i],  bl2, bl3);
                    mma_f16_2(Cacc[i][n + 1], alr[i], bh2, bh3);
                }
            }
        }
        __syncthreads();
    }

    #pragma unroll
    for (int i = 0; i < 2; i++) {
        const int r0 = m0 + wm * 32 + i * 16 + g;
        #pragma unroll
        for (int n = 0; n < 8; n++) {
            const int c = n0blk + wn * 64 + n * 8 + 2 * t;
            float bx = __ldg(bias + c), by = __ldg(bias + c + 1);
            float v00 = Cacc[i][n][0] + bx, v01 = Cacc[i][n][1] + by;
            float v10 = Cacc[i][n][2] + bx, v11 = Cacc[i][n][3] + by;
            if (Cf) {
                *(float2*)(Cf + (size_t)r0 * Ntotal + c)       = make_float2(v00, v01);
                *(float2*)(Cf + (size_t)(r0 + 8) * Ntotal + c) = make_float2(v10, v11);
            } else {
                float ra, rb;
                *(uint32_t*)(Ch + (size_t)r0 * Ntotal + c) = packh_hi(v00, v01, ra, rb);
                *(uint32_t*)(Cl + (size_t)r0 * Ntotal + c) = packh(ra, rb);
                *(uint32_t*)(Ch + (size_t)(r0 + 8) * Ntotal + c) = packh_hi(v10, v11, ra, rb);
                *(uint32_t*)(Cl + (size_t)(r0 + 8) * Ntotal + c) = packh(ra, rb);
            }
        }
    }
}

// ---------------------------------------------------------------------------
// Flash attention: double-buffered cp.async KV, ldmatrix K + V(trans),
// register P. CTA: 128 queries, 8 warps; j-tiles of 64.
// ---------------------------------------------------------------------------
static constexpr int ASTR  = 72;                  // halves per row
static constexpr int KVROW = 64 * ASTR;           // one 64-row array
static constexpr int STG   = 4 * KVROW;           // KH|KL|VH|VL per stage (halves)
static constexpr int A_SMEM = 2 * STG * 2;        // 73728 bytes

__global__ __launch_bounds__(256) void attn_f16()
{
    const uint32_t sb = smem_u32(g_sm);
    const int qt = blockIdx.x, bh = blockIdx.y;
    const int bb = bh >> 4, h = bh & 15;
    const int tid = threadIdx.x, wid = tid >> 5, lane = tid & 31;
    const int g = lane >> 2, t = lane & 3;
    const int grp = lane >> 3, l7 = lane & 7;
    const int q0 = qt * 128;
    const int mrow = wid * 16 + g;

    // ldmatrix lane offsets (halves)
    const int kb_off = ((grp >> 1) * 8 + l7) * ASTR + (grp & 1) * 8;   // K (non-trans B)
    const int v_off  = ((grp & 1) * 8 + l7) * ASTR + (grp >> 1) * 8;   // V (trans B)

    const size_t rowbase = (size_t)(bb * S_);

    // ---- issue Q loads (into stage 1 region) + KV tile 0 (stage 0)
    {
        #pragma unroll
        for (int p = 0; p < 8; p++) {
            int o = tid + p * 256;
            int arr = o >> 10, r = (o >> 3) & 127, sg = o & 7;
            const __half* src = ((arr == 0) ? g_qkv_hi : g_qkv_lo)
                + (rowbase + q0 + r) * N3_ + h * DH_ + sg * 8;
            cp16(sb + (uint32_t)(STG + arr * 2 * KVROW + r * ASTR + sg * 8) * 2, src);
        }
        CP_COMMIT();
    }
    auto load_kv = [&](int j0, int s) {
        #pragma unroll
        for (int p = 0; p < 8; p++) {
            int o = tid + p * 256;
            int arr = o >> 9, r = (o >> 3) & 63, sg = o & 7;
            // arr: 0=KH 1=KL 2=VH 3=VL
            const __half* src = ((arr & 1) == 0 ? g_qkv_hi : g_qkv_lo)
                + (rowbase + j0 + r) * N3_ + ((arr >> 1) + 1) * D_ + h * DH_ + sg * 8;
            cp16(sb + (uint32_t)(s * STG + arr * KVROW + r * ASTR + sg * 8) * 2, src);
        }
        CP_COMMIT();
    };
    load_kv(0, 0);

    // ---- wait for Q (KV0 may still be in flight), extract Q fragments
    CP_WAIT(1);
    __syncthreads();
    const __half* smh = g_sm;
    uint32_t qh[4][4], ql[4][4];
    #pragma unroll
    for (int ks = 0; ks < 4; ks++) {
        const int kb = 2 * t + 16 * ks;
        const __half* QH = smh + STG;
        const __half* QL = smh + STG + 2 * KVROW;
        qh[ks][0] = lds32(QH + mrow * ASTR + kb);
        qh[ks][1] = lds32(QH + (mrow + 8) * ASTR + kb);
        qh[ks][2] = lds32(QH + mrow * ASTR + kb + 8);
        qh[ks][3] = lds32(QH + (mrow + 8) * ASTR + kb + 8);
        ql[ks][0] = lds32(QL + mrow * ASTR + kb);
        ql[ks][1] = lds32(QL + (mrow + 8) * ASTR + kb);
        ql[ks][2] = lds32(QL + mrow * ASTR + kb + 8);
        ql[ks][3] = lds32(QL + (mrow + 8) * ASTR + kb + 8);
    }
    __syncthreads();   // Q reads done before stage-1 gets overwritten by tile 1

    float Oacc[8][4] = {};
    float m0r = -1e30f, m1r = -1e30f, l0r = 0.f, l1r = 0.f;

    for (int it = 0; it < 32; it++) {
        if (it + 1 < 32) { load_kv((it + 1) * 64, (it + 1) & 1); CP_WAIT(1); }
        else             { CP_WAIT(0); }
        __syncthreads();

        const uint32_t stg = sb + (uint32_t)((it & 1) * STG) * 2;
        const uint32_t KHb = stg;
        const uint32_t KLb = stg + (uint32_t)KVROW * 2;
        const uint32_t VHb = stg + (uint32_t)(2 * KVROW) * 2;
        const uint32_t VLb = stg + (uint32_t)(3 * KVROW) * 2;

        // ---- S = Q @ K^T (3-product)
        float Sacc[8][4] = {};
        #pragma unroll
        for (int ks = 0; ks < 4; ks++) {
            const int kb0 = 16 * ks;
            #pragma unroll
            for (int np = 0; np < 4; np++) {
                const int n = np * 2;
                const uint32_t off = (uint32_t)(n * 8 * ASTR + kb0 + kb_off) * 2;
                uint32_t kh0, kh1, kh2, kh3, kl0, kl1, kl2, kl3;
                ldsm_x4(kh0, kh1, kh2, kh3, KHb + off);
                ldsm_x4(kl0, kl1, kl2, kl3, KLb + off);
                mma_f16_2(Sacc[n],     qh[ks], kh0, kh1);
                mma_f16_2(Sacc[n],     qh[ks], kl0, kl1);
                mma_f16_2(Sacc[n],     ql[ks], kh0, kh1);
                mma_f16_2(Sacc[n + 1], qh[ks], kh2, kh3);
                mma_f16_2(Sacc[n + 1], qh[ks], kl2, kl3);
                mma_f16_2(Sacc[n + 1], ql[ks], kh2, kh3);
            }
        }
        #pragma unroll
        for (int n = 0; n < 8; n++) {
            Sacc[n][0] *= 0.125f; Sacc[n][1] *= 0.125f;
            Sacc[n][2] *= 0.125f; Sacc[n][3] *= 0.125f;
        }

        // ---- online softmax
        float mx0 = -1e30f, mx1 = -1e30f;
        #pragma unroll
        for (int n = 0; n < 8; n++) {
            mx0 = fmaxf(mx0, fmaxf(Sacc[n][0], Sacc[n][1]));
            mx1 = fmaxf(mx1, fmaxf(Sacc[n][2], Sacc[n][3]));
        }
        mx0 = fmaxf(mx0, __shfl_xor_sync(0xffffffffu, mx0, 1));
        mx0 = fmaxf(mx0, __shfl_xor_sync(0xffffffffu, mx0, 2));
        mx1 = fmaxf(mx1, __shfl_xor_sync(0xffffffffu, mx1, 1));
        mx1 = fmaxf(mx1, __shfl_xor_sync(0xffffffffu, mx1, 2));

        const float mn0 = fmaxf(m0r, mx0), mn1 = fmaxf(m1r, mx1);
        const float c0 = __expf(m0r - mn0), c1 = __expf(m1r - mn1);
        float s0 = 0.f, s1 = 0.f;
        #pragma unroll
        for (int n = 0; n < 8; n++) {
            Sacc[n][0] = __expf(Sacc[n][0] - mn0);
            Sacc[n][1] = __expf(Sacc[n][1] - mn0);
            Sacc[n][2] = __expf(Sacc[n][2] - mn1);
            Sacc[n][3] = __expf(Sacc[n][3] - mn1);
            s0 += Sacc[n][0] + Sacc[n][1];
            s1 += Sacc[n][2] + Sacc[n][3];
        }
        s0 += __shfl_xor_sync(0xffffffffu, s0, 1);
        s0 += __shfl_xor_sync(0xffffffffu, s0, 2);
        s1 += __shfl_xor_sync(0xffffffffu, s1, 1);
        s1 += __shfl_xor_sync(0xffffffffu, s1, 2);
        l0r = l0r * c0 + s0;  l1r = l1r * c1 + s1;
        m0r = mn0;            m1r = mn1;

        #pragma unroll
        for (int n = 0; n < 8; n++) {
            Oacc[n][0] *= c0; Oacc[n][1] *= c0;
            Oacc[n][2] *= c1; Oacc[n][3] *= c1;
        }

        // ---- O += P @ V (3-product); P fragments from Sacc, V via ldsm.trans
        #pragma unroll
        for (int ks = 0; ks < 4; ks++) {
            uint32_t ph[4], pl[4];
            float r0a, r0b, r1a, r1b;
            ph[0] = packh_hi(Sacc[2*ks][0],   Sacc[2*ks][1],   r0a, r0b);
            pl[0] = packh(r0a, r0b);
            ph[1] = packh_hi(Sacc[2*ks][2],   Sacc[2*ks][3],   r1a, r1b);
            pl[1] = packh(r1a, r1b);
            ph[2] = packh_hi(Sacc[2*ks+1][0], Sacc[2*ks+1][1], r0a, r0b);
            pl[2] = packh(r0a, r0b);
            ph[3] = packh_hi(Sacc[2*ks+1][2], Sacc[2*ks+1][3], r1a, r1b);
            pl[3] = packh(r1a, r1b);
            #pragma unroll
            for (int np = 0; np < 4; np++) {
                const int n = np * 2;
                const uint32_t off = (uint32_t)(16 * ks * ASTR + n * 8 + v_off) * 2;
                uint32_t vh0, vh1, vh2, vh3, vl0, vl1, vl2, vl3;
                ldsm_x4t(vh0, vh1, vh2, vh3, VHb + off);
                ldsm_x4t(vl0, vl1, vl2, vl3, VLb + off);
                mma_f16_2(Oacc[n],     ph, vh0, vh1);
                mma_f16_2(Oacc[n],     ph, vl0, vl1);
                mma_f16_2(Oacc[n],     pl, vh0, vh1);
                mma_f16_2(Oacc[n + 1], ph, vh2, vh3);
                mma_f16_2(Oacc[n + 1], ph, vl2, vl3);
                mma_f16_2(Oacc[n + 1], pl, vh2, vh3);
            }
        }
        __syncthreads();   // stage fully consumed before next iteration's load overwrites
    }

    // ---- epilogue: normalize + pre-split write for proj GEMM
    const float inv0 = 1.f / l0r, inv1 = 1.f / l1r;
    __half* oh = g_oc_hi + (rowbase + q0) * HD_ + h * DH_;
    __half* ol = g_oc_lo + (rowbase + q0) * HD_ + h * DH_;
    #pragma unroll
    for (int n = 0; n < 8; n++) {
        const int c = n * 8 + 2 * t;
        float ra, rb;
        *(uint32_t*)(oh + (size_t)mrow * HD_ + c) =
            packh_hi(Oacc[n][0] * inv0, Oacc[n][1] * inv0, ra, rb);
        *(uint32_t*)(ol + (size_t)mrow * HD_ + c) = packh(ra, rb);
        *(uint32_t*)(oh + (size_t)(mrow + 8) * HD_ + c) =
            packh_hi(Oacc[n][2] * inv1, Oacc[n][3] * inv1, ra, rb);
        *(uint32_t*)(ol + (size_t)(mrow + 8) * HD_ + c) = packh(ra, rb);
    }
}

// ---------------------------------------------------------------------------
extern "C" void kernel_launch(void* const* d_in, const int* in_sizes, int n_in,
                              void* d_out, int out_size)
{
    const float* x  = (const float*)d_in[0];
    const float* Wq = (const float*)d_in[1];
    const float* bq = (const float*)d_in[2];
    const float* Wk = (const float*)d_in[3];
    const float* bk = (const float*)d_in[4];
    const float* Wv = (const float*)d_in[5];
    const float* bv = (const float*)d_in[6];
    const float* Wo = (const float*)d_in[7];
    const float* bo = (const float*)d_in[8];
    float* out = (float*)d_out;

    void *xh, *xl, *wth, *wtl, *woh, *wol, *qh, *qlp, *och, *ocl, *bs;
    cudaGetSymbolAddress(&xh,  g_x_hi);   cudaGetSymbolAddress(&xl,  g_x_lo);
    cudaGetSymbolAddress(&wth, g_wt_hi);  cudaGetSymbolAddress(&wtl, g_wt_lo);
    cudaGetSymbolAddress(&woh, g_wot_hi); cudaGetSymbolAddress(&wol, g_wot_lo);
    cudaGetSymbolAddress(&qh,  g_qkv_hi); cudaGetSymbolAddress(&qlp, g_qkv_lo);
    cudaGetSymbolAddress(&och, g_oc_hi);  cudaGetSymbolAddress(&ocl, g_oc_lo);
    cudaGetSymbolAddress(&bs,  g_bias);

    cudaFuncSetAttribute(gemm_f16, cudaFuncAttributeMaxDynamicSharedMemorySize, G_SMEM);
    cudaFuncSetAttribute(attn_f16, cudaFuncAttributeMaxDynamicSharedMemorySize, A_SMEM);

    prep_x   <<<BS_ * D_ / 1024, 256>>>(x);
    build_wt <<<dim3(D_ / 32, DH_ / 32, 3 * H_), dim3(32, 8)>>>(Wq, Wk, Wv);
    build_wot<<<dim3(D_ / 32, D_ / 32), dim3(32, 8)>>>(Wo);
    build_bias<<<3, D_>>>(bq, bk, bv);

    gemm_f16<<<dim3(BS_ / 128, N3_ / 128), 256, G_SMEM>>>(
        (const __half*)xh, (const __half*)xl,
        (const __half*)wth, (const __half*)wtl,
        (const float*)bs, nullptr,
        (__half*)qh, (__half*)qlp, N3_);

    attn_f16<<<dim3(S_ / 128, B_ * H_), 256, A_SMEM>>>();

    gemm_f16<<<dim3(BS_ / 128, D_ / 128), 256, G_SMEM>>>(
        (const __half*)och, (const __half*)ocl,
        (const __half*)woh, (const __half*)wol,
        bo, out, nullptr, nullptr, D_);
}

// round 10
// speedup vs baseline: 3.2239x; 1.2060x over previous
#include <cuda_runtime.h>
#include <cuda_fp16.h>
#include <cstdint>

// Problem constants
static constexpr int B_  = 2;
static constexpr int S_  = 2048;
static constexpr int D_  = 1024;
static constexpr int H_  = 16;
static constexpr int DH_ = 64;
static constexpr int BS_ = B_ * S_;          // 4096
static constexpr int HD_ = H_ * DH_;         // 1024
static constexpr int N3_ = 3 * D_;           // 3072

// Pre-split operand storage (hi + lo fp16 pairs reconstruct fp32 to ~2^-22)
__device__ __half g_x_hi [BS_ * D_],  g_x_lo [BS_ * D_];
__device__ __half g_wt_hi[N3_ * D_],  g_wt_lo[N3_ * D_];
__device__ __half g_wot_hi[D_ * D_],  g_wot_lo[D_ * D_];
__device__ __half g_qkv_hi[BS_ * N3_], g_qkv_lo[BS_ * N3_];
__device__ __half g_oc_hi[BS_ * HD_], g_oc_lo[BS_ * HD_];
__device__ float g_bias[N3_];

// ---------------------------------------------------------------------------
// Helpers
// ---------------------------------------------------------------------------
__device__ __forceinline__ void cp16(uint32_t dst, const void* src) {
    asm volatile("cp.async.cg.shared.global [%0], [%1], 16;" :: "r"(dst), "l"(src));
}
#define CP_COMMIT() asm volatile("cp.async.commit_group;")
#define CP_WAIT(n)  asm volatile("cp.async.wait_group %0;" :: "n"(n))

__device__ __forceinline__ uint32_t smem_u32(const void* p) {
    uint32_t a;
    asm("{ .reg .u64 t; cvta.to.shared.u64 t, %1; cvt.u32.u64 %0, t; }" : "=r"(a) : "l"(p));
    return a;
}
__device__ __forceinline__ uint32_t lds32(const __half* p) {
    return *(const uint32_t*)p;
}
__device__ __forceinline__ void ldsm_x4(uint32_t& r0, uint32_t& r1, uint32_t& r2, uint32_t& r3,
                                        uint32_t addr) {
    asm volatile("ldmatrix.sync.aligned.m8n8.x4.shared.b16 {%0,%1,%2,%3}, [%4];"
                 : "=r"(r0), "=r"(r1), "=r"(r2), "=r"(r3) : "r"(addr));
}
__device__ __forceinline__ void ldsm_x4t(uint32_t& r0, uint32_t& r1, uint32_t& r2, uint32_t& r3,
                                         uint32_t addr) {
    asm volatile("ldmatrix.sync.aligned.m8n8.x4.trans.shared.b16 {%0,%1,%2,%3}, [%4];"
                 : "=r"(r0), "=r"(r1), "=r"(r2), "=r"(r3) : "r"(addr));
}

// m16n8k16 fp16 MMA (A row-major, B col-major), fp32 accumulate
__device__ __forceinline__ void mma_f16_2(float* c, const uint32_t* a, uint32_t b0, uint32_t b1) {
    asm volatile(
        "mma.sync.aligned.m16n8k16.row.col.f32.f16.f16.f32 "
        "{%0,%1,%2,%3}, {%4,%5,%6,%7}, {%8,%9}, {%0,%1,%2,%3};"
        : "+f"(c[0]), "+f"(c[1]), "+f"(c[2]), "+f"(c[3])
        : "r"(a[0]), "r"(a[1]), "r"(a[2]), "r"(a[3]), "r"(b0), "r"(b1));
}

__device__ __forceinline__ uint32_t packh_hi(float a, float b, float& ra, float& rb) {
    __half ha = __float2half_rn(a), hb = __float2half_rn(b);
    ra = a - __half2float(ha);
    rb = b - __half2float(hb);
    return (uint32_t)__half_as_ushort(ha) | ((uint32_t)__half_as_ushort(hb) << 16);
}
__device__ __forceinline__ uint32_t packh(float a, float b) {
    return (uint32_t)__half_as_ushort(__float2half_rn(a)) |
           ((uint32_t)__half_as_ushort(__float2half_rn(b)) << 16);
}

// ---------------------------------------------------------------------------
// Prep kernels
// ---------------------------------------------------------------------------
__global__ void prep_x(const float* __restrict__ x) {
    int i = (blockIdx.x * 256 + threadIdx.x) * 4;
    float4 v = *(const float4*)(x + i);
    float r0, r1, r2, r3;
    uint32_t h01 = packh_hi(v.x, v.y, r0, r1);
    uint32_t h23 = packh_hi(v.z, v.w, r2, r3);
    *(uint2*)(g_x_hi + i) = make_uint2(h01, h23);
    *(uint2*)(g_x_lo + i) = make_uint2(packh(r0, r1), packh(r2, r3));
}

__global__ void build_wt(const float* __restrict__ Wq, const float* __restrict__ Wk,
                         const float* __restrict__ Wv) {
    const int wsel = blockIdx.z >> 4, h = blockIdx.z & 15;
    const float* W = (wsel == 0) ? Wq : (wsel == 1) ? Wk : Wv;
    __shared__ float t[32][33];
    const int k0 = blockIdx.x * 32, d0 = blockIdx.y * 32;
    #pragma unroll
    for (int i = 0; i < 4; i++) {
        int k = k0 + threadIdx.y + i * 8;
        t[threadIdx.y + i * 8][threadIdx.x] = W[(size_t)h * D_ * DH_ + (size_t)k * DH_ + d0 + threadIdx.x];
    }
    __syncthreads();
    #pragma unroll
    for (int i = 0; i < 4; i++) {
        int d = d0 + threadIdx.y + i * 8;
        float v = t[threadIdx.x][threadIdx.y + i * 8];
        size_t idx = (size_t)(wsel * D_ + h * DH_ + d) * D_ + k0 + threadIdx.x;
        __half hv = __float2half_rn(v);
        g_wt_hi[idx] = hv;
        g_wt_lo[idx] = __float2half_rn(v - __half2float(hv));
    }
}

__global__ void build_wot(const float* __restrict__ Wo) {
    __shared__ float t[32][33];
    const int k0 = blockIdx.x * 32, n0 = blockIdx.y * 32;
    #pragma unroll
    for (int i = 0; i < 4; i++)
        t[threadIdx.y + i * 8][threadIdx.x] = Wo[(size_t)(k0 + threadIdx.y + i * 8) * D_ + n0 + threadIdx.x];
    __syncthreads();
    #pragma unroll
    for (int i = 0; i < 4; i++) {
        int n = n0 + threadIdx.y + i * 8;
        float v = t[threadIdx.x][threadIdx.y + i * 8];
        size_t idx = (size_t)n * D_ + k0 + threadIdx.x;
        __half hv = __float2half_rn(v);
        g_wot_hi[idx] = hv;
        g_wot_lo[idx] = __float2half_rn(v - __half2float(hv));
    }
}

__global__ void build_bias(const float* __restrict__ bq, const float* __restrict__ bk,
                           const float* __restrict__ bv) {
    const float* b = (blockIdx.x == 0) ? bq : (blockIdx.x == 1) ? bk : bv;
    g_bias[blockIdx.x * D_ + threadIdx.x] = b[threadIdx.x];
}

// ---------------------------------------------------------------------------
// Split-fp16 GEMM (3-product), ldmatrix fragment loads.
// ---------------------------------------------------------------------------
static constexpr int TSTR   = 40;             // fp16 per smem row
static constexpr int TTILE  = 128 * TSTR;
static constexpr int TSTAGE = 4 * TTILE;
static constexpr int G_SMEM = 2 * TSTAGE * 2; // 81920 bytes

extern __shared__ __half g_sm[];

__global__ __launch_bounds__(256) void gemm_f16(
    const __half* __restrict__ Ah, const __half* __restrict__ Al,
    const __half* __restrict__ Bh, const __half* __restrict__ Bl,
    const float* __restrict__ bias,
    float* __restrict__ Cf, __half* __restrict__ Ch, __half* __restrict__ Cl,
    int Ntotal)
{
    const uint32_t sb = smem_u32(g_sm);
    const int tid = threadIdx.x, wid = tid >> 5, lane = tid & 31;
    const int g = lane >> 2, t = lane & 3;
    const int grp = lane >> 3, l7 = lane & 7;
    const int wm = wid >> 1, wn = wid & 1;
    const int m0 = blockIdx.x * 128, n0blk = blockIdx.y * 128;

    const int a_off = ((grp & 1) * 8 + l7) * TSTR + (grp >> 1) * 8;
    const int b_off = ((grp >> 1) * 8 + l7) * TSTR + (grp & 1) * 8;

    float Cacc[2][8][4] = {};

    auto load_chunk = [&](int kc, int s) {
        #pragma unroll
        for (int p = 0; p < 8; p++) {
            int o = tid + p * 256;
            int arr = o >> 9, r = (o >> 2) & 127, sg = o & 3;
            const __half* src =
                (arr == 0) ? Ah + (size_t)(m0 + r) * D_ + kc + sg * 8 :
                (arr == 1) ? Al + (size_t)(m0 + r) * D_ + kc + sg * 8 :
                (arr == 2) ? Bh + (size_t)(n0blk + r) * D_ + kc + sg * 8 :
                             Bl + (size_t)(n0blk + r) * D_ + kc + sg * 8;
            cp16(sb + (uint32_t)(s * TSTAGE + arr * TTILE + r * TSTR + sg * 8) * 2, src);
        }
        CP_COMMIT();
    };

    load_chunk(0, 0);

    for (int ch = 0; ch < 32; ch++) {
        const int s = ch & 1;
        if (ch < 31) { load_chunk((ch + 1) * 32, s ^ 1); CP_WAIT(1); }
        else         { CP_WAIT(0); }
        __syncthreads();

        const uint32_t ah_b = sb + (uint32_t)(s * TSTAGE) * 2;
        const uint32_t al_b = ah_b + TTILE * 2;
        const uint32_t bh_b = ah_b + 2 * TTILE * 2;
        const uint32_t bl_b = ah_b + 3 * TTILE * 2;

        #pragma unroll
        for (int ks = 0; ks < 2; ks++) {
            const int kb0 = 16 * ks;
            uint32_t af[2][4], alr[2][4];
            #pragma unroll
            for (int i = 0; i < 2; i++) {
                const int rb = (wm * 32 + i * 16) * TSTR + kb0;
                ldsm_x4(af[i][0], af[i][1], af[i][2], af[i][3],
                        ah_b + (uint32_t)(rb + a_off) * 2);
                ldsm_x4(alr[i][0], alr[i][1], alr[i][2], alr[i][3],
                        al_b + (uint32_t)(rb + a_off) * 2);
            }
            #pragma unroll
            for (int np = 0; np < 4; np++) {
                const int n = np * 2;
                const int rb = (wn * 64 + n * 8) * TSTR + kb0;
                uint32_t bh0, bh1, bh2, bh3, bl0, bl1, bl2, bl3;
                ldsm_x4(bh0, bh1, bh2, bh3, bh_b + (uint32_t)(rb + b_off) * 2);
                ldsm_x4(bl0, bl1, bl2, bl3, bl_b + (uint32_t)(rb + b_off) * 2);
                #pragma unroll
                for (int i = 0; i < 2; i++) {
                    mma_f16_2(Cacc[i][n],     af[i],  bh0, bh1);
                    mma_f16_2(Cacc[i][n],     af[i],  bl0, bl1);
                    mma_f16_2(Cacc[i][n],     alr[i], bh0, bh1);
                    mma_f16_2(Cacc[i][n + 1], af[i],  bh2, bh3);
                    mma_f16_2(Cacc[i][n + 1], af[i],  bl2, bl3);
                    mma_f16_2(Cacc[i][n + 1], alr[i], bh2, bh3);
                }
            }
        }
        __syncthreads();
    }

    #pragma unroll
    for (int i = 0; i < 2; i++) {
        const int r0 = m0 + wm * 32 + i * 16 + g;
        #pragma unroll
        for (int n = 0; n < 8; n++) {
            const int c = n0blk + wn * 64 + n * 8 + 2 * t;
            float bx = __ldg(bias + c), by = __ldg(bias + c + 1);
            float v00 = Cacc[i][n][0] + bx, v01 = Cacc[i][n][1] + by;
            float v10 = Cacc[i][n][2] + bx, v11 = Cacc[i][n][3] + by;
            if (Cf) {
                *(float2*)(Cf + (size_t)r0 * Ntotal + c)       = make_float2(v00, v01);
                *(float2*)(Cf + (size_t)(r0 + 8) * Ntotal + c) = make_float2(v10, v11);
            } else {
                float ra, rb;
                *(uint32_t*)(Ch + (size_t)r0 * Ntotal + c) = packh_hi(v00, v01, ra, rb);
                *(uint32_t*)(Cl + (size_t)r0 * Ntotal + c) = packh(ra, rb);
                *(uint32_t*)(Ch + (size_t)(r0 + 8) * Ntotal + c) = packh_hi(v10, v11, ra, rb);
                *(uint32_t*)(Cl + (size_t)(r0 + 8) * Ntotal + c) = packh(ra, rb);
            }
        }
    }
}

// ---------------------------------------------------------------------------
// Flash attention: 2-product S and PV (q_hi / p_hi only on A side).
// Double-buffered cp.async KV, ldmatrix K + V(trans). 128 queries, 8 warps.
// ---------------------------------------------------------------------------
static constexpr int ASTR  = 72;                  // halves per row
static constexpr int KVROW = 64 * ASTR;
static constexpr int STG   = 4 * KVROW;           // KH|KL|VH|VL per stage
static constexpr int A_SMEM = 2 * STG * 2;        // 73728 bytes

// softmax in exp2 domain: logits scaled by 0.125 * log2(e)
static constexpr float SCL2 = 0.125f * 1.4426950408889634f;

__global__ __launch_bounds__(256) void attn_f16()
{
    const uint32_t sb = smem_u32(g_sm);
    const int qt = blockIdx.x, bh = blockIdx.y;
    const int bb = bh >> 4, h = bh & 15;
    const int tid = threadIdx.x, wid = tid >> 5, lane = tid & 31;
    const int g = lane >> 2, t = lane & 3;
    const int grp = lane >> 3, l7 = lane & 7;
    const int q0 = qt * 128;
    const int mrow = wid * 16 + g;

    const int kb_off = ((grp >> 1) * 8 + l7) * ASTR + (grp & 1) * 8;   // K (non-trans B)
    const int v_off  = ((grp & 1) * 8 + l7) * ASTR + (grp >> 1) * 8;   // V (trans B)

    const size_t rowbase = (size_t)(bb * S_);

    // ---- issue Q-hi load (into stage 1 region) + KV tile 0 (stage 0)
    {
        #pragma unroll
        for (int p = 0; p < 4; p++) {
            int o = tid + p * 256;
            int r = o >> 3, sg = o & 7;
            const __half* src = g_qkv_hi + (rowbase + q0 + r) * N3_ + h * DH_ + sg * 8;
            cp16(sb + (uint32_t)(STG + r * ASTR + sg * 8) * 2, src);
        }
        CP_COMMIT();
    }
    auto load_kv = [&](int j0, int s) {
        #pragma unroll
        for (int p = 0; p < 8; p++) {
            int o = tid + p * 256;
            int arr = o >> 9, r = (o >> 3) & 63, sg = o & 7;
            // arr: 0=KH 1=KL 2=VH 3=VL
            const __half* src = ((arr & 1) == 0 ? g_qkv_hi : g_qkv_lo)
                + (rowbase + j0 + r) * N3_ + ((arr >> 1) + 1) * D_ + h * DH_ + sg * 8;
            cp16(sb + (uint32_t)(s * STG + arr * KVROW + r * ASTR + sg * 8) * 2, src);
        }
        CP_COMMIT();
    };
    load_kv(0, 0);

    // ---- wait for Q (KV0 may still be in flight), extract Q-hi fragments
    CP_WAIT(1);
    __syncthreads();
    const __half* smh = g_sm;
    uint32_t qh[4][4];
    #pragma unroll
    for (int ks = 0; ks < 4; ks++) {
        const int kb = 2 * t + 16 * ks;
        const __half* QH = smh + STG;
        qh[ks][0] = lds32(QH + mrow * ASTR + kb);
        qh[ks][1] = lds32(QH + (mrow + 8) * ASTR + kb);
        qh[ks][2] = lds32(QH + mrow * ASTR + kb + 8);
        qh[ks][3] = lds32(QH + (mrow + 8) * ASTR + kb + 8);
    }
    __syncthreads();   // Q reads done before stage-1 is overwritten by tile 1

    float Oacc[8][4] = {};
    float m0r = -1e30f, m1r = -1e30f, l0r = 0.f, l1r = 0.f;

    for (int it = 0; it < 32; it++) {
        if (it + 1 < 32) { load_kv((it + 1) * 64, (it + 1) & 1); CP_WAIT(1); }
        else             { CP_WAIT(0); }
        __syncthreads();

        const uint32_t stg = sb + (uint32_t)((it & 1) * STG) * 2;
        const uint32_t KHb = stg;
        const uint32_t KLb = stg + (uint32_t)KVROW * 2;
        const uint32_t VHb = stg + (uint32_t)(2 * KVROW) * 2;
        const uint32_t VLb = stg + (uint32_t)(3 * KVROW) * 2;

        // ---- S = Q_hi @ (K_hi + K_lo)^T  (2-product)
        float Sacc[8][4] = {};
        #pragma unroll
        for (int ks = 0; ks < 4; ks++) {
            const int kb0 = 16 * ks;
            #pragma unroll
            for (int np = 0; np < 4; np++) {
                const int n = np * 2;
                const uint32_t off = (uint32_t)(n * 8 * ASTR + kb0 + kb_off) * 2;
                uint32_t kh0, kh1, kh2, kh3, kl0, kl1, kl2, kl3;
                ldsm_x4(kh0, kh1, kh2, kh3, KHb + off);
                ldsm_x4(kl0, kl1, kl2, kl3, KLb + off);
                mma_f16_2(Sacc[n],     qh[ks], kh0, kh1);
                mma_f16_2(Sacc[n],     qh[ks], kl0, kl1);
                mma_f16_2(Sacc[n + 1], qh[ks], kh2, kh3);
                mma_f16_2(Sacc[n + 1], qh[ks], kl2, kl3);
            }
        }
        #pragma unroll
        for (int n = 0; n < 8; n++) {
            Sacc[n][0] *= SCL2; Sacc[n][1] *= SCL2;
            Sacc[n][2] *= SCL2; Sacc[n][3] *= SCL2;
        }

        // ---- online softmax (base-2 domain)
        float mx0 = -1e30f, mx1 = -1e30f;
        #pragma unroll
        for (int n = 0; n < 8; n++) {
            mx0 = fmaxf(mx0, fmaxf(Sacc[n][0], Sacc[n][1]));
            mx1 = fmaxf(mx1, fmaxf(Sacc[n][2], Sacc[n][3]));
        }
        mx0 = fmaxf(mx0, __shfl_xor_sync(0xffffffffu, mx0, 1));
        mx0 = fmaxf(mx0, __shfl_xor_sync(0xffffffffu, mx0, 2));
        mx1 = fmaxf(mx1, __shfl_xor_sync(0xffffffffu, mx1, 1));
        mx1 = fmaxf(mx1, __shfl_xor_sync(0xffffffffu, mx1, 2));

        const float mn0 = fmaxf(m0r, mx0), mn1 = fmaxf(m1r, mx1);
        const float c0 = exp2f(m0r - mn0), c1 = exp2f(m1r - mn1);
        float s0 = 0.f, s1 = 0.f;
        #pragma unroll
        for (int n = 0; n < 8; n++) {
            Sacc[n][0] = exp2f(Sacc[n][0] - mn0);
            Sacc[n][1] = exp2f(Sacc[n][1] - mn0);
            Sacc[n][2] = exp2f(Sacc[n][2] - mn1);
            Sacc[n][3] = exp2f(Sacc[n][3] - mn1);
            s0 += Sacc[n][0] + Sacc[n][1];
            s1 += Sacc[n][2] + Sacc[n][3];
        }
        s0 += __shfl_xor_sync(0xffffffffu, s0, 1);
        s0 += __shfl_xor_sync(0xffffffffu, s0, 2);
        s1 += __shfl_xor_sync(0xffffffffu, s1, 1);
        s1 += __shfl_xor_sync(0xffffffffu, s1, 2);
        l0r = l0r * c0 + s0;  l1r = l1r * c1 + s1;
        m0r = mn0;            m1r = mn1;

        #pragma unroll
        for (int n = 0; n < 8; n++) {
            Oacc[n][0] *= c0; Oacc[n][1] *= c0;
            Oacc[n][2] *= c1; Oacc[n][3] *= c1;
        }

        // ---- O += P_hi @ (V_hi + V_lo)  (2-product); P fragments from Sacc
        #pragma unroll
        for (int ks = 0; ks < 4; ks++) {
            uint32_t ph[4];
            ph[0] = packh(Sacc[2*ks][0],   Sacc[2*ks][1]);
            ph[1] = packh(Sacc[2*ks][2],   Sacc[2*ks][3]);
            ph[2] = packh(Sacc[2*ks+1][0], Sacc[2*ks+1][1]);
            ph[3] = packh(Sacc[2*ks+1][2], Sacc[2*ks+1][3]);
            #pragma unroll
            for (int np = 0; np < 4; np++) {
                const int n = np * 2;
                const uint32_t off = (uint32_t)(16 * ks * ASTR + n * 8 + v_off) * 2;
                uint32_t vh0, vh1, vh2, vh3, vl0, vl1, vl2, vl3;
                ldsm_x4t(vh0, vh1, vh2, vh3, VHb + off);
                ldsm_x4t(vl0, vl1, vl2, vl3, VLb + off);
                mma_f16_2(Oacc[n],     ph, vh0, vh1);
                mma_f16_2(Oacc[n],     ph, vl0, vl1);
                mma_f16_2(Oacc[n + 1], ph, vh2, vh3);
                mma_f16_2(Oacc[n + 1], ph, vl2, vl3);
            }
        }
        __syncthreads();   // stage fully consumed before next load overwrites
    }

    // ---- epilogue: normalize + pre-split write for proj GEMM
    const float inv0 = 1.f / l0r, inv1 = 1.f / l1r;
    __half* oh = g_oc_hi + (rowbase + q0) * HD_ + h * DH_;
    __half* ol = g_oc_lo + (rowbase + q0) * HD_ + h * DH_;
    #pragma unroll
    for (int n = 0; n < 8; n++) {
        const int c = n * 8 + 2 * t;
        float ra, rb;
        *(uint32_t*)(oh + (size_t)mrow * HD_ + c) =
            packh_hi(Oacc[n][0] * inv0, Oacc[n][1] * inv0, ra, rb);
        *(uint32_t*)(ol + (size_t)mrow * HD_ + c) = packh(ra, rb);
        *(uint32_t*)(oh + (size_t)(mrow + 8) * HD_ + c) =
            packh_hi(Oacc[n][2] * inv1, Oacc[n][3] * inv1, ra, rb);
        *(uint32_t*)(ol + (size_t)(mrow + 8) * HD_ + c) = packh(ra, rb);
    }
}

// ---------------------------------------------------------------------------
extern "C" void kernel_launch(void* const* d_in, const int* in_sizes, int n_in,
                              void* d_out, int out_size)
{
    const float* x  = (const float*)d_in[0];
    const float* Wq = (const float*)d_in[1];
    const float* bq = (const float*)d_in[2];
    const float* Wk = (const float*)d_in[3];
    const float* bk = (const float*)d_in[4];
    const float* Wv = (const float*)d_in[5];
    const float* bv = (const float*)d_in[6];
    const float* Wo = (const float*)d_in[7];
    const float* bo = (const float*)d_in[8];
    float* out = (float*)d_out;

    void *xh, *xl, *wth, *wtl, *woh, *wol, *qh, *qlp, *och, *ocl, *bs;
    cudaGetSymbolAddress(&xh,  g_x_hi);   cudaGetSymbolAddress(&xl,  g_x_lo);
    cudaGetSymbolAddress(&wth, g_wt_hi);  cudaGetSymbolAddress(&wtl, g_wt_lo);
    cudaGetSymbolAddress(&woh, g_wot_hi); cudaGetSymbolAddress(&wol, g_wot_lo);
    cudaGetSymbolAddress(&qh,  g_qkv_hi); cudaGetSymbolAddress(&qlp, g_qkv_lo);
    cudaGetSymbolAddress(&och, g_oc_hi);  cudaGetSymbolAddress(&ocl, g_oc_lo);
    cudaGetSymbolAddress(&bs,  g_bias);

    cudaFuncSetAttribute(gemm_f16, cudaFuncAttributeMaxDynamicSharedMemorySize, G_SMEM);
    cudaFuncSetAttribute(attn_f16, cudaFuncAttributeMaxDynamicSharedMemorySize, A_SMEM);

    prep_x   <<<BS_ * D_ / 1024, 256>>>(x);
    build_wt <<<dim3(D_ / 32, DH_ / 32, 3 * H_), dim3(32, 8)>>>(Wq, Wk, Wv);
    build_wot<<<dim3(D_ / 32, D_ / 32), dim3(32, 8)>>>(Wo);
    build_bias<<<3, D_>>>(bq, bk, bv);

    gemm_f16<<<dim3(BS_ / 128, N3_ / 128), 256, G_SMEM>>>(
        (const __half*)xh, (const __half*)xl,
        (const __half*)wth, (const __half*)wtl,
        (const float*)bs, nullptr,
        (__half*)qh, (__half*)qlp, N3_);

    attn_f16<<<dim3(S_ / 128, B_ * H_), 256, A_SMEM>>>();

    gemm_f16<<<dim3(BS_ / 128, D_ / 128), 256, G_SMEM>>>(
        (const __half*)och, (const __half*)ocl,
        (const __half*)woh, (const __half*)wol,
        bo, out, nullptr, nullptr, D_);
}

// round 11
// speedup vs baseline: 3.8013x; 1.1791x over previous
#include <cuda_runtime.h>
#include <cuda_fp16.h>
#include <cstdint>

// Problem constants
static constexpr int B_  = 2;
static constexpr int S_  = 2048;
static constexpr int D_  = 1024;
static constexpr int H_  = 16;
static constexpr int DH_ = 64;
static constexpr int BS_ = B_ * S_;          // 4096
static constexpr int HD_ = H_ * DH_;         // 1024
static constexpr int N3_ = 3 * D_;           // 3072

// Operand storage. Scheme: every matmul computes A_hi @ (B_hi + B_lo).
__device__ __half g_x_hi [BS_ * D_];                         // A of qkv GEMM (hi only)
__device__ __half g_wt_hi[N3_ * D_],  g_wt_lo[N3_ * D_];     // B of qkv GEMM
__device__ __half g_wot_hi[D_ * D_],  g_wot_lo[D_ * D_];     // B of proj GEMM
__device__ __half g_qkv_hi[BS_ * N3_], g_qkv_lo[BS_ * N3_];  // q(A,hi used)|k,v(B, hi+lo)
__device__ __half g_oc_hi[BS_ * HD_];                        // A of proj GEMM (hi only)
__device__ float g_bias[N3_];

// ---------------------------------------------------------------------------
// Helpers
// ---------------------------------------------------------------------------
__device__ __forceinline__ void cp16(uint32_t dst, const void* src) {
    asm volatile("cp.async.cg.shared.global [%0], [%1], 16;" :: "r"(dst), "l"(src));
}
#define CP_COMMIT() asm volatile("cp.async.commit_group;")
#define CP_WAIT(n)  asm volatile("cp.async.wait_group %0;" :: "n"(n))

__device__ __forceinline__ uint32_t smem_u32(const void* p) {
    uint32_t a;
    asm("{ .reg .u64 t; cvta.to.shared.u64 t, %1; cvt.u32.u64 %0, t; }" : "=r"(a) : "l"(p));
    return a;
}
__device__ __forceinline__ uint32_t lds32(const __half* p) {
    return *(const uint32_t*)p;
}
__device__ __forceinline__ void ldsm_x4(uint32_t& r0, uint32_t& r1, uint32_t& r2, uint32_t& r3,
                                        uint32_t addr) {
    asm volatile("ldmatrix.sync.aligned.m8n8.x4.shared.b16 {%0,%1,%2,%3}, [%4];"
                 : "=r"(r0), "=r"(r1), "=r"(r2), "=r"(r3) : "r"(addr));
}
__device__ __forceinline__ void ldsm_x4t(uint32_t& r0, uint32_t& r1, uint32_t& r2, uint32_t& r3,
                                         uint32_t addr) {
    asm volatile("ldmatrix.sync.aligned.m8n8.x4.trans.shared.b16 {%0,%1,%2,%3}, [%4];"
                 : "=r"(r0), "=r"(r1), "=r"(r2), "=r"(r3) : "r"(addr));
}

// m16n8k16 fp16 MMA (A row-major, B col-major), fp32 accumulate
__device__ __forceinline__ void mma_f16_2(float* c, const uint32_t* a, uint32_t b0, uint32_t b1) {
    asm volatile(
        "mma.sync.aligned.m16n8k16.row.col.f32.f16.f16.f32 "
        "{%0,%1,%2,%3}, {%4,%5,%6,%7}, {%8,%9}, {%0,%1,%2,%3};"
        : "+f"(c[0]), "+f"(c[1]), "+f"(c[2]), "+f"(c[3])
        : "r"(a[0]), "r"(a[1]), "r"(a[2]), "r"(a[3]), "r"(b0), "r"(b1));
}

__device__ __forceinline__ uint32_t packh_hi(float a, float b, float& ra, float& rb) {
    __half ha = __float2half_rn(a), hb = __float2half_rn(b);
    ra = a - __half2float(ha);
    rb = b - __half2float(hb);
    return (uint32_t)__half_as_ushort(ha) | ((uint32_t)__half_as_ushort(hb) << 16);
}
__device__ __forceinline__ uint32_t packh(float a, float b) {
    return (uint32_t)__half_as_ushort(__float2half_rn(a)) |
           ((uint32_t)__half_as_ushort(__float2half_rn(b)) << 16);
}

// ---------------------------------------------------------------------------
// Prep kernels
// ---------------------------------------------------------------------------
__global__ void prep_x(const float* __restrict__ x) {
    int i = (blockIdx.x * 256 + threadIdx.x) * 4;
    float4 v = *(const float4*)(x + i);
    *(uint2*)(g_x_hi + i) = make_uint2(packh(v.x, v.y), packh(v.z, v.w));
}

__global__ void build_wt(const float* __restrict__ Wq, const float* __restrict__ Wk,
                         const float* __restrict__ Wv) {
    const int wsel = blockIdx.z >> 4, h = blockIdx.z & 15;
    const float* W = (wsel == 0) ? Wq : (wsel == 1) ? Wk : Wv;
    __shared__ float t[32][33];
    const int k0 = blockIdx.x * 32, d0 = blockIdx.y * 32;
    #pragma unroll
    for (int i = 0; i < 4; i++) {
        int k = k0 + threadIdx.y + i * 8;
        t[threadIdx.y + i * 8][threadIdx.x] = W[(size_t)h * D_ * DH_ + (size_t)k * DH_ + d0 + threadIdx.x];
    }
    __syncthreads();
    #pragma unroll
    for (int i = 0; i < 4; i++) {
        int d = d0 + threadIdx.y + i * 8;
        float v = t[threadIdx.x][threadIdx.y + i * 8];
        size_t idx = (size_t)(wsel * D_ + h * DH_ + d) * D_ + k0 + threadIdx.x;
        __half hv = __float2half_rn(v);
        g_wt_hi[idx] = hv;
        g_wt_lo[idx] = __float2half_rn(v - __half2float(hv));
    }
}

__global__ void build_wot(const float* __restrict__ Wo) {
    __shared__ float t[32][33];
    const int k0 = blockIdx.x * 32, n0 = blockIdx.y * 32;
    #pragma unroll
    for (int i = 0; i < 4; i++)
        t[threadIdx.y + i * 8][threadIdx.x] = Wo[(size_t)(k0 + threadIdx.y + i * 8) * D_ + n0 + threadIdx.x];
    __syncthreads();
    #pragma unroll
    for (int i = 0; i < 4; i++) {
        int n = n0 + threadIdx.y + i * 8;
        float v = t[threadIdx.x][threadIdx.y + i * 8];
        size_t idx = (size_t)n * D_ + k0 + threadIdx.x;
        __half hv = __float2half_rn(v);
        g_wot_hi[idx] = hv;
        g_wot_lo[idx] = __float2half_rn(v - __half2float(hv));
    }
}

__global__ void build_bias(const float* __restrict__ bq, const float* __restrict__ bk,
                           const float* __restrict__ bv) {
    const float* b = (blockIdx.x == 0) ? bq : (blockIdx.x == 1) ? bk : bv;
    g_bias[blockIdx.x * D_ + threadIdx.x] = b[threadIdx.x];
}

// ---------------------------------------------------------------------------
// 2-product GEMM: C = A_hi @ (B_hi + B_lo)^T + bias.
// Tile 128x128, K-chunk 32, double-buffered. Smem tiles: Ah|Bh|Bl.
// ---------------------------------------------------------------------------
static constexpr int TSTR   = 40;             // fp16 per smem row
static constexpr int TTILE  = 128 * TSTR;
static constexpr int TSTAGE = 3 * TTILE;      // Ah|Bh|Bl
static constexpr int G_SMEM = 2 * TSTAGE * 2; // 61440 bytes

extern __shared__ __half g_sm[];

__global__ __launch_bounds__(256) void gemm_f16(
    const __half* __restrict__ Ah,
    const __half* __restrict__ Bh, const __half* __restrict__ Bl,
    const float* __restrict__ bias,
    float* __restrict__ Cf, __half* __restrict__ Ch, __half* __restrict__ Cl,
    int Ntotal)
{
    const uint32_t sb = smem_u32(g_sm);
    const int tid = threadIdx.x, wid = tid >> 5, lane = tid & 31;
    const int g = lane >> 2, t = lane & 3;
    const int grp = lane >> 3, l7 = lane & 7;
    const int wm = wid >> 1, wn = wid & 1;
    const int m0 = blockIdx.x * 128, n0blk = blockIdx.y * 128;

    const int a_off = ((grp & 1) * 8 + l7) * TSTR + (grp >> 1) * 8;
    const int b_off = ((grp >> 1) * 8 + l7) * TSTR + (grp & 1) * 8;

    float Cacc[2][8][4] = {};

    auto load_chunk = [&](int kc, int s) {
        #pragma unroll
        for (int p = 0; p < 6; p++) {
            int o = tid + p * 256;
            int arr = o >> 9, r = (o >> 2) & 127, sg = o & 3;
            const __half* src =
                (arr == 0) ? Ah + (size_t)(m0 + r) * D_ + kc + sg * 8 :
                (arr == 1) ? Bh + (size_t)(n0blk + r) * D_ + kc + sg * 8 :
                             Bl + (size_t)(n0blk + r) * D_ + kc + sg * 8;
            cp16(sb + (uint32_t)(s * TSTAGE + arr * TTILE + r * TSTR + sg * 8) * 2, src);
        }
        CP_COMMIT();
    };

    load_chunk(0, 0);

    for (int ch = 0; ch < 32; ch++) {
        const int s = ch & 1;
        if (ch < 31) { load_chunk((ch + 1) * 32, s ^ 1); CP_WAIT(1); }
        else         { CP_WAIT(0); }
        __syncthreads();

        const uint32_t ah_b = sb + (uint32_t)(s * TSTAGE) * 2;
        const uint32_t bh_b = ah_b + TTILE * 2;
        const uint32_t bl_b = ah_b + 2 * TTILE * 2;

        #pragma unroll
        for (int ks = 0; ks < 2; ks++) {
            const int kb0 = 16 * ks;
            uint32_t af[2][4];
            #pragma unroll
            for (int i = 0; i < 2; i++) {
                const int rb = (wm * 32 + i * 16) * TSTR + kb0;
                ldsm_x4(af[i][0], af[i][1], af[i][2], af[i][3],
                        ah_b + (uint32_t)(rb + a_off) * 2);
            }
            #pragma unroll
            for (int np = 0; np < 4; np++) {
                const int n = np * 2;
                const int rb = (wn * 64 + n * 8) * TSTR + kb0;
                uint32_t bh0, bh1, bh2, bh3, bl0, bl1, bl2, bl3;
                ldsm_x4(bh0, bh1, bh2, bh3, bh_b + (uint32_t)(rb + b_off) * 2);
                ldsm_x4(bl0, bl1, bl2, bl3, bl_b + (uint32_t)(rb + b_off) * 2);
                #pragma unroll
                for (int i = 0; i < 2; i++) {
                    mma_f16_2(Cacc[i][n],     af[i], bh0, bh1);
                    mma_f16_2(Cacc[i][n],     af[i], bl0, bl1);
                    mma_f16_2(Cacc[i][n + 1], af[i], bh2, bh3);
                    mma_f16_2(Cacc[i][n + 1], af[i], bl2, bl3);
                }
            }
        }
        __syncthreads();
    }

    #pragma unroll
    for (int i = 0; i < 2; i++) {
        const int r0 = m0 + wm * 32 + i * 16 + g;
        #pragma unroll
        for (int n = 0; n < 8; n++) {
            const int c = n0blk + wn * 64 + n * 8 + 2 * t;
            float bx = __ldg(bias + c), by = __ldg(bias + c + 1);
            float v00 = Cacc[i][n][0] + bx, v01 = Cacc[i][n][1] + by;
            float v10 = Cacc[i][n][2] + bx, v11 = Cacc[i][n][3] + by;
            if (Cf) {
                *(float2*)(Cf + (size_t)r0 * Ntotal + c)       = make_float2(v00, v01);
                *(float2*)(Cf + (size_t)(r0 + 8) * Ntotal + c) = make_float2(v10, v11);
            } else {
                float ra, rb;
                *(uint32_t*)(Ch + (size_t)r0 * Ntotal + c) = packh_hi(v00, v01, ra, rb);
                *(uint32_t*)(Cl + (size_t)r0 * Ntotal + c) = packh(ra, rb);
                *(uint32_t*)(Ch + (size_t)(r0 + 8) * Ntotal + c) = packh_hi(v10, v11, ra, rb);
                *(uint32_t*)(Cl + (size_t)(r0 + 8) * Ntotal + c) = packh(ra, rb);
            }
        }
    }
}

// ---------------------------------------------------------------------------
// Flash attention: 2-product S and PV (q_hi / p_hi on A side).
// Double-buffered cp.async KV, ldmatrix K + V(trans). 128 queries, 8 warps.
// ---------------------------------------------------------------------------
static constexpr int ASTR  = 72;                  // halves per row
static constexpr int KVROW = 64 * ASTR;
static constexpr int STG   = 4 * KVROW;           // KH|KL|VH|VL per stage
static constexpr int A_SMEM = 2 * STG * 2;        // 73728 bytes

// softmax in exp2 domain: logits scaled by 0.125 * log2(e)
static constexpr float SCL2 = 0.125f * 1.4426950408889634f;

__global__ __launch_bounds__(256) void attn_f16()
{
    const uint32_t sb = smem_u32(g_sm);
    const int qt = blockIdx.x, bh = blockIdx.y;
    const int bb = bh >> 4, h = bh & 15;
    const int tid = threadIdx.x, wid = tid >> 5, lane = tid & 31;
    const int g = lane >> 2, t = lane & 3;
    const int grp = lane >> 3, l7 = lane & 7;
    const int q0 = qt * 128;
    const int mrow = wid * 16 + g;

    const int kb_off = ((grp >> 1) * 8 + l7) * ASTR + (grp & 1) * 8;   // K (non-trans B)
    const int v_off  = ((grp & 1) * 8 + l7) * ASTR + (grp >> 1) * 8;   // V (trans B)

    const size_t rowbase = (size_t)(bb * S_);

    // ---- issue Q-hi load (into stage 1 region) + KV tile 0 (stage 0)
    {
        #pragma unroll
        for (int p = 0; p < 4; p++) {
            int o = tid + p * 256;
            int r = o >> 3, sg = o & 7;
            const __half* src = g_qkv_hi + (rowbase + q0 + r) * N3_ + h * DH_ + sg * 8;
            cp16(sb + (uint32_t)(STG + r * ASTR + sg * 8) * 2, src);
        }
        CP_COMMIT();
    }
    auto load_kv = [&](int j0, int s) {
        #pragma unroll
        for (int p = 0; p < 8; p++) {
            int o = tid + p * 256;
            int arr = o >> 9, r = (o >> 3) & 63, sg = o & 7;
            // arr: 0=KH 1=KL 2=VH 3=VL
            const __half* src = ((arr & 1) == 0 ? g_qkv_hi : g_qkv_lo)
                + (rowbase + j0 + r) * N3_ + ((arr >> 1) + 1) * D_ + h * DH_ + sg * 8;
            cp16(sb + (uint32_t)(s * STG + arr * KVROW + r * ASTR + sg * 8) * 2, src);
        }
        CP_COMMIT();
    };
    load_kv(0, 0);

    // ---- wait for Q (KV0 may still be in flight), extract Q-hi fragments
    CP_WAIT(1);
    __syncthreads();
    const __half* smh = g_sm;
    uint32_t qh[4][4];
    #pragma unroll
    for (int ks = 0; ks < 4; ks++) {
        const int kb = 2 * t + 16 * ks;
        const __half* QH = smh + STG;
        qh[ks][0] = lds32(QH + mrow * ASTR + kb);
        qh[ks][1] = lds32(QH + (mrow + 8) * ASTR + kb);
        qh[ks][2] = lds32(QH + mrow * ASTR + kb + 8);
        qh[ks][3] = lds32(QH + (mrow + 8) * ASTR + kb + 8);
    }
    __syncthreads();   // Q reads done before stage-1 is overwritten by tile 1

    float Oacc[8][4] = {};
    float m0r = -1e30f, m1r = -1e30f, l0r = 0.f, l1r = 0.f;

    for (int it = 0; it < 32; it++) {
        if (it + 1 < 32) { load_kv((it + 1) * 64, (it + 1) & 1); CP_WAIT(1); }
        else             { CP_WAIT(0); }
        __syncthreads();

        const uint32_t stg = sb + (uint32_t)((it & 1) * STG) * 2;
        const uint32_t KHb = stg;
        const uint32_t KLb = stg + (uint32_t)KVROW * 2;
        const uint32_t VHb = stg + (uint32_t)(2 * KVROW) * 2;
        const uint32_t VLb = stg + (uint32_t)(3 * KVROW) * 2;

        // ---- S = Q_hi @ (K_hi + K_lo)^T
        float Sacc[8][4] = {};
        #pragma unroll
        for (int ks = 0; ks < 4; ks++) {
            const int kb0 = 16 * ks;
            #pragma unroll
            for (int np = 0; np < 4; np++) {
                const int n = np * 2;
                const uint32_t off = (uint32_t)(n * 8 * ASTR + kb0 + kb_off) * 2;
                uint32_t kh0, kh1, kh2, kh3, kl0, kl1, kl2, kl3;
                ldsm_x4(kh0, kh1, kh2, kh3, KHb + off);
                ldsm_x4(kl0, kl1, kl2, kl3, KLb + off);
                mma_f16_2(Sacc[n],     qh[ks], kh0, kh1);
                mma_f16_2(Sacc[n],     qh[ks], kl0, kl1);
                mma_f16_2(Sacc[n + 1], qh[ks], kh2, kh3);
                mma_f16_2(Sacc[n + 1], qh[ks], kl2, kl3);
            }
        }
        #pragma unroll
        for (int n = 0; n < 8; n++) {
            Sacc[n][0] *= SCL2; Sacc[n][1] *= SCL2;
            Sacc[n][2] *= SCL2; Sacc[n][3] *= SCL2;
        }

        // ---- online softmax (base-2 domain)
        float mx0 = -1e30f, mx1 = -1e30f;
        #pragma unroll
        for (int n = 0; n < 8; n++) {
            mx0 = fmaxf(mx0, fmaxf(Sacc[n][0], Sacc[n][1]));
            mx1 = fmaxf(mx1, fmaxf(Sacc[n][2], Sacc[n][3]));
        }
        mx0 = fmaxf(mx0, __shfl_xor_sync(0xffffffffu, mx0, 1));
        mx0 = fmaxf(mx0, __shfl_xor_sync(0xffffffffu, mx0, 2));
        mx1 = fmaxf(mx1, __shfl_xor_sync(0xffffffffu, mx1, 1));
        mx1 = fmaxf(mx1, __shfl_xor_sync(0xffffffffu, mx1, 2));

        const float mn0 = fmaxf(m0r, mx0), mn1 = fmaxf(m1r, mx1);
        const float c0 = exp2f(m0r - mn0), c1 = exp2f(m1r - mn1);
        float s0 = 0.f, s1 = 0.f;
        #pragma unroll
        for (int n = 0; n < 8; n++) {
            Sacc[n][0] = exp2f(Sacc[n][0] - mn0);
            Sacc[n][1] = exp2f(Sacc[n][1] - mn0);
            Sacc[n][2] = exp2f(Sacc[n][2] - mn1);
            Sacc[n][3] = exp2f(Sacc[n][3] - mn1);
            s0 += Sacc[n][0] + Sacc[n][1];
            s1 += Sacc[n][2] + Sacc[n][3];
        }
        s0 += __shfl_xor_sync(0xffffffffu, s0, 1);
        s0 += __shfl_xor_sync(0xffffffffu, s0, 2);
        s1 += __shfl_xor_sync(0xffffffffu, s1, 1);
        s1 += __shfl_xor_sync(0xffffffffu, s1, 2);
        l0r = l0r * c0 + s0;  l1r = l1r * c1 + s1;
        m0r = mn0;            m1r = mn1;

        #pragma unroll
        for (int n = 0; n < 8; n++) {
            Oacc[n][0] *= c0; Oacc[n][1] *= c0;
            Oacc[n][2] *= c1; Oacc[n][3] *= c1;
        }

        // ---- O += P_hi @ (V_hi + V_lo); P fragments from Sacc
        #pragma unroll
        for (int ks = 0; ks < 4; ks++) {
            uint32_t ph[4];
            ph[0] = packh(Sacc[2*ks][0],   Sacc[2*ks][1]);
            ph[1] = packh(Sacc[2*ks][2],   Sacc[2*ks][3]);
            ph[2] = packh(Sacc[2*ks+1][0], Sacc[2*ks+1][1]);
            ph[3] = packh(Sacc[2*ks+1][2], Sacc[2*ks+1][3]);
            #pragma unroll
            for (int np = 0; np < 4; np++) {
                const int n = np * 2;
                const uint32_t off = (uint32_t)(16 * ks * ASTR + n * 8 + v_off) * 2;
                uint32_t vh0, vh1, vh2, vh3, vl0, vl1, vl2, vl3;
                ldsm_x4t(vh0, vh1, vh2, vh3, VHb + off);
                ldsm_x4t(vl0, vl1, vl2, vl3, VLb + off);
                mma_f16_2(Oacc[n],     ph, vh0, vh1);
                mma_f16_2(Oacc[n],     ph, vl0, vl1);
                mma_f16_2(Oacc[n + 1], ph, vh2, vh3);
                mma_f16_2(Oacc[n + 1], ph, vl2, vl3);
            }
        }
        __syncthreads();   // stage fully consumed before next load overwrites
    }

    // ---- epilogue: normalize, write hi-only concat for proj GEMM
    const float inv0 = 1.f / l0r, inv1 = 1.f / l1r;
    __half* oh = g_oc_hi + (rowbase + q0) * HD_ + h * DH_;
    #pragma unroll
    for (int n = 0; n < 8; n++) {
        const int c = n * 8 + 2 * t;
        *(uint32_t*)(oh + (size_t)mrow * HD_ + c) =
            packh(Oacc[n][0] * inv0, Oacc[n][1] * inv0);
        *(uint32_t*)(oh + (size_t)(mrow + 8) * HD_ + c) =
            packh(Oacc[n][2] * inv1, Oacc[n][3] * inv1);
    }
}

// ---------------------------------------------------------------------------
extern "C" void kernel_launch(void* const* d_in, const int* in_sizes, int n_in,
                              void* d_out, int out_size)
{
    const float* x  = (const float*)d_in[0];
    const float* Wq = (const float*)d_in[1];
    const float* bq = (const float*)d_in[2];
    const float* Wk = (const float*)d_in[3];
    const float* bk = (const float*)d_in[4];
    const float* Wv = (const float*)d_in[5];
    const float* bv = (const float*)d_in[6];
    const float* Wo = (const float*)d_in[7];
    const float* bo = (const float*)d_in[8];
    float* out = (float*)d_out;

    void *xh, *wth, *wtl, *woh, *wol, *qh, *qlp, *och, *bs;
    cudaGetSymbolAddress(&xh,  g_x_hi);
    cudaGetSymbolAddress(&wth, g_wt_hi);  cudaGetSymbolAddress(&wtl, g_wt_lo);
    cudaGetSymbolAddress(&woh, g_wot_hi); cudaGetSymbolAddress(&wol, g_wot_lo);
    cudaGetSymbolAddress(&qh,  g_qkv_hi); cudaGetSymbolAddress(&qlp, g_qkv_lo);
    cudaGetSymbolAddress(&och, g_oc_hi);
    cudaGetSymbolAddress(&bs,  g_bias);

    cudaFuncSetAttribute(gemm_f16, cudaFuncAttributeMaxDynamicSharedMemorySize, G_SMEM);
    cudaFuncSetAttribute(attn_f16, cudaFuncAttributeMaxDynamicSharedMemorySize, A_SMEM);

    prep_x   <<<BS_ * D_ / 1024, 256>>>(x);
    build_wt <<<dim3(D_ / 32, DH_ / 32, 3 * H_), dim3(32, 8)>>>(Wq, Wk, Wv);
    build_wot<<<dim3(D_ / 32, D_ / 32), dim3(32, 8)>>>(Wo);
    build_bias<<<3, D_>>>(bq, bk, bv);

    gemm_f16<<<dim3(BS_ / 128, N3_ / 128), 256, G_SMEM>>>(
        (const __half*)xh,
        (const __half*)wth, (const __half*)wtl,
        (const float*)bs, nullptr,
        (__half*)qh, (__half*)qlp, N3_);

    attn_f16<<<dim3(S_ / 128, B_ * H_), 256, A_SMEM>>>();

    gemm_f16<<<dim3(BS_ / 128, D_ / 128), 256, G_SMEM>>>(
        (const __half*)och,
        (const __half*)woh, (const __half*)wol,
        bo, out, nullptr, nullptr, D_);
}

// round 12
// speedup vs baseline: 4.1110x; 1.0815x over previous
#include <cuda_runtime.h>
#include <cuda_fp16.h>
#include <cstdint>

// Problem constants
static constexpr int B_  = 2;
static constexpr int S_  = 2048;
static constexpr int D_  = 1024;
static constexpr int H_  = 16;
static constexpr int DH_ = 64;
static constexpr int BS_ = B_ * S_;          // 4096
static constexpr int HD_ = H_ * DH_;         // 1024
static constexpr int N3_ = 3 * D_;           // 3072

// Operand storage. GEMMs: A_hi @ (B_hi + B_lo). Attn: S = Q_hi(K_hi+K_lo)^T, O = P_hi V_hi.
__device__ __half g_x_hi [BS_ * D_];                         // A of qkv GEMM (hi only)
__device__ __half g_wt_hi[N3_ * D_],  g_wt_lo[N3_ * D_];     // B of qkv GEMM
__device__ __half g_wot_hi[D_ * D_],  g_wot_lo[D_ * D_];     // B of proj GEMM
__device__ __half g_qkv_hi[BS_ * N3_], g_qkv_lo[BS_ * N3_];  // q|k|v (lo used for k only)
__device__ __half g_oc_hi[BS_ * HD_];                        // A of proj GEMM (hi only)
__device__ float g_bias[N3_];

// ---------------------------------------------------------------------------
// Helpers
// ---------------------------------------------------------------------------
__device__ __forceinline__ void cp16(uint32_t dst, const void* src) {
    asm volatile("cp.async.cg.shared.global [%0], [%1], 16;" :: "r"(dst), "l"(src));
}
#define CP_COMMIT() asm volatile("cp.async.commit_group;")
#define CP_WAIT(n)  asm volatile("cp.async.wait_group %0;" :: "n"(n))

__device__ __forceinline__ uint32_t smem_u32(const void* p) {
    uint32_t a;
    asm("{ .reg .u64 t; cvta.to.shared.u64 t, %1; cvt.u32.u64 %0, t; }" : "=r"(a) : "l"(p));
    return a;
}
__device__ __forceinline__ uint32_t lds32(const __half* p) {
    return *(const uint32_t*)p;
}
__device__ __forceinline__ void ldsm_x4(uint32_t& r0, uint32_t& r1, uint32_t& r2, uint32_t& r3,
                                        uint32_t addr) {
    asm volatile("ldmatrix.sync.aligned.m8n8.x4.shared.b16 {%0,%1,%2,%3}, [%4];"
                 : "=r"(r0), "=r"(r1), "=r"(r2), "=r"(r3) : "r"(addr));
}
__device__ __forceinline__ void ldsm_x4t(uint32_t& r0, uint32_t& r1, uint32_t& r2, uint32_t& r3,
                                         uint32_t addr) {
    asm volatile("ldmatrix.sync.aligned.m8n8.x4.trans.shared.b16 {%0,%1,%2,%3}, [%4];"
                 : "=r"(r0), "=r"(r1), "=r"(r2), "=r"(r3) : "r"(addr));
}

// m16n8k16 fp16 MMA (A row-major, B col-major), fp32 accumulate
__device__ __forceinline__ void mma_f16_2(float* c, const uint32_t* a, uint32_t b0, uint32_t b1) {
    asm volatile(
        "mma.sync.aligned.m16n8k16.row.col.f32.f16.f16.f32 "
        "{%0,%1,%2,%3}, {%4,%5,%6,%7}, {%8,%9}, {%0,%1,%2,%3};"
        : "+f"(c[0]), "+f"(c[1]), "+f"(c[2]), "+f"(c[3])
        : "r"(a[0]), "r"(a[1]), "r"(a[2]), "r"(a[3]), "r"(b0), "r"(b1));
}

__device__ __forceinline__ uint32_t packh_hi(float a, float b, float& ra, float& rb) {
    __half ha = __float2half_rn(a), hb = __float2half_rn(b);
    ra = a - __half2float(ha);
    rb = b - __half2float(hb);
    return (uint32_t)__half_as_ushort(ha) | ((uint32_t)__half_as_ushort(hb) << 16);
}
__device__ __forceinline__ uint32_t packh(float a, float b) {
    return (uint32_t)__half_as_ushort(__float2half_rn(a)) |
           ((uint32_t)__half_as_ushort(__float2half_rn(b)) << 16);
}

// ---------------------------------------------------------------------------
// Prep kernels
// ---------------------------------------------------------------------------
__global__ void prep_x(const float* __restrict__ x) {
    int i = (blockIdx.x * 256 + threadIdx.x) * 4;
    float4 v = *(const float4*)(x + i);
    *(uint2*)(g_x_hi + i) = make_uint2(packh(v.x, v.y), packh(v.z, v.w));
}

__global__ void build_wt(const float* __restrict__ Wq, const float* __restrict__ Wk,
                         const float* __restrict__ Wv) {
    const int wsel = blockIdx.z >> 4, h = blockIdx.z & 15;
    const float* W = (wsel == 0) ? Wq : (wsel == 1) ? Wk : Wv;
    __shared__ float t[32][33];
    const int k0 = blockIdx.x * 32, d0 = blockIdx.y * 32;
    #pragma unroll
    for (int i = 0; i < 4; i++) {
        int k = k0 + threadIdx.y + i * 8;
        t[threadIdx.y + i * 8][threadIdx.x] = W[(size_t)h * D_ * DH_ + (size_t)k * DH_ + d0 + threadIdx.x];
    }
    __syncthreads();
    #pragma unroll
    for (int i = 0; i < 4; i++) {
        int d = d0 + threadIdx.y + i * 8;
        float v = t[threadIdx.x][threadIdx.y + i * 8];
        size_t idx = (size_t)(wsel * D_ + h * DH_ + d) * D_ + k0 + threadIdx.x;
        __half hv = __float2half_rn(v);
        g_wt_hi[idx] = hv;
        g_wt_lo[idx] = __float2half_rn(v - __half2float(hv));
    }
}

__global__ void build_wot(const float* __restrict__ Wo) {
    __shared__ float t[32][33];
    const int k0 = blockIdx.x * 32, n0 = blockIdx.y * 32;
    #pragma unroll
    for (int i = 0; i < 4; i++)
        t[threadIdx.y + i * 8][threadIdx.x] = Wo[(size_t)(k0 + threadIdx.y + i * 8) * D_ + n0 + threadIdx.x];
    __syncthreads();
    #pragma unroll
    for (int i = 0; i < 4; i++) {
        int n = n0 + threadIdx.y + i * 8;
        float v = t[threadIdx.x][threadIdx.y + i * 8];
        size_t idx = (size_t)n * D_ + k0 + threadIdx.x;
        __half hv = __float2half_rn(v);
        g_wot_hi[idx] = hv;
        g_wot_lo[idx] = __float2half_rn(v - __half2float(hv));
    }
}

__global__ void build_bias(const float* __restrict__ bq, const float* __restrict__ bk,
                           const float* __restrict__ bv) {
    const float* b = (blockIdx.x == 0) ? bq : (blockIdx.x == 1) ? bk : bv;
    g_bias[blockIdx.x * D_ + threadIdx.x] = b[threadIdx.x];
}

// ---------------------------------------------------------------------------
// 2-product GEMM: C = A_hi @ (B_hi + B_lo)^T + bias.
// Tile 128x128, K-chunk 32, double-buffered. Smem tiles: Ah|Bh|Bl.
// ---------------------------------------------------------------------------
static constexpr int TSTR   = 40;             // fp16 per smem row
static constexpr int TTILE  = 128 * TSTR;
static constexpr int TSTAGE = 3 * TTILE;      // Ah|Bh|Bl
static constexpr int G_SMEM = 2 * TSTAGE * 2; // 61440 bytes

extern __shared__ __half g_sm[];

__global__ __launch_bounds__(256) void gemm_f16(
    const __half* __restrict__ Ah,
    const __half* __restrict__ Bh, const __half* __restrict__ Bl,
    const float* __restrict__ bias,
    float* __restrict__ Cf, __half* __restrict__ Ch, __half* __restrict__ Cl,
    int Ntotal)
{
    const uint32_t sb = smem_u32(g_sm);
    const int tid = threadIdx.x, wid = tid >> 5, lane = tid & 31;
    const int g = lane >> 2, t = lane & 3;
    const int grp = lane >> 3, l7 = lane & 7;
    const int wm = wid >> 1, wn = wid & 1;
    const int m0 = blockIdx.x * 128, n0blk = blockIdx.y * 128;

    const int a_off = ((grp & 1) * 8 + l7) * TSTR + (grp >> 1) * 8;
    const int b_off = ((grp >> 1) * 8 + l7) * TSTR + (grp & 1) * 8;

    float Cacc[2][8][4] = {};

    auto load_chunk = [&](int kc, int s) {
        #pragma unroll
        for (int p = 0; p < 6; p++) {
            int o = tid + p * 256;
            int arr = o >> 9, r = (o >> 2) & 127, sg = o & 3;
            const __half* src =
                (arr == 0) ? Ah + (size_t)(m0 + r) * D_ + kc + sg * 8 :
                (arr == 1) ? Bh + (size_t)(n0blk + r) * D_ + kc + sg * 8 :
                             Bl + (size_t)(n0blk + r) * D_ + kc + sg * 8;
            cp16(sb + (uint32_t)(s * TSTAGE + arr * TTILE + r * TSTR + sg * 8) * 2, src);
        }
        CP_COMMIT();
    };

    load_chunk(0, 0);

    for (int ch = 0; ch < 32; ch++) {
        const int s = ch & 1;
        if (ch < 31) { load_chunk((ch + 1) * 32, s ^ 1); CP_WAIT(1); }
        else         { CP_WAIT(0); }
        __syncthreads();

        const uint32_t ah_b = sb + (uint32_t)(s * TSTAGE) * 2;
        const uint32_t bh_b = ah_b + TTILE * 2;
        const uint32_t bl_b = ah_b + 2 * TTILE * 2;

        #pragma unroll
        for (int ks = 0; ks < 2; ks++) {
            const int kb0 = 16 * ks;
            uint32_t af[2][4];
            #pragma unroll
            for (int i = 0; i < 2; i++) {
                const int rb = (wm * 32 + i * 16) * TSTR + kb0;
                ldsm_x4(af[i][0], af[i][1], af[i][2], af[i][3],
                        ah_b + (uint32_t)(rb + a_off) * 2);
            }
            #pragma unroll
            for (int np = 0; np < 4; np++) {
                const int n = np * 2;
                const int rb = (wn * 64 + n * 8) * TSTR + kb0;
                uint32_t bh0, bh1, bh2, bh3, bl0, bl1, bl2, bl3;
                ldsm_x4(bh0, bh1, bh2, bh3, bh_b + (uint32_t)(rb + b_off) * 2);
                ldsm_x4(bl0, bl1, bl2, bl3, bl_b + (uint32_t)(rb + b_off) * 2);
                #pragma unroll
                for (int i = 0; i < 2; i++) {
                    mma_f16_2(Cacc[i][n],     af[i], bh0, bh1);
                    mma_f16_2(Cacc[i][n],     af[i], bl0, bl1);
                    mma_f16_2(Cacc[i][n + 1], af[i], bh2, bh3);
                    mma_f16_2(Cacc[i][n + 1], af[i], bl2, bl3);
                }
            }
        }
        __syncthreads();
    }

    #pragma unroll
    for (int i = 0; i < 2; i++) {
        const int r0 = m0 + wm * 32 + i * 16 + g;
        #pragma unroll
        for (int n = 0; n < 8; n++) {
            const int c = n0blk + wn * 64 + n * 8 + 2 * t;
            float bx = __ldg(bias + c), by = __ldg(bias + c + 1);
            float v00 = Cacc[i][n][0] + bx, v01 = Cacc[i][n][1] + by;
            float v10 = Cacc[i][n][2] + bx, v11 = Cacc[i][n][3] + by;
            if (Cf) {
                *(float2*)(Cf + (size_t)r0 * Ntotal + c)       = make_float2(v00, v01);
                *(float2*)(Cf + (size_t)(r0 + 8) * Ntotal + c) = make_float2(v10, v11);
            } else {
                float ra, rb;
                *(uint32_t*)(Ch + (size_t)r0 * Ntotal + c) = packh_hi(v00, v01, ra, rb);
                *(uint32_t*)(Cl + (size_t)r0 * Ntotal + c) = packh(ra, rb);
                *(uint32_t*)(Ch + (size_t)(r0 + 8) * Ntotal + c) = packh_hi(v10, v11, ra, rb);
                *(uint32_t*)(Cl + (size_t)(r0 + 8) * Ntotal + c) = packh(ra, rb);
            }
        }
    }
}

// ---------------------------------------------------------------------------
// Flash attention: S = Q_hi(K_hi+K_lo)^T (2-product), O = P_hi V_hi (1-product).
// Double-buffered cp.async KV (KH|KL|VH), ldmatrix K + V(trans). 128 q, 8 warps.
// ---------------------------------------------------------------------------
static constexpr int ASTR  = 72;                  // halves per row
static constexpr int KVROW = 64 * ASTR;
static constexpr int STG   = 3 * KVROW;           // KH|KL|VH per stage
static constexpr int A_SMEM = 2 * STG * 2;        // 55296 bytes

// softmax in exp2 domain: logits scaled by 0.125 * log2(e)
static constexpr float SCL2 = 0.125f * 1.4426950408889634f;

__global__ __launch_bounds__(256) void attn_f16()
{
    const uint32_t sb = smem_u32(g_sm);
    const int qt = blockIdx.x, bh = blockIdx.y;
    const int bb = bh >> 4, h = bh & 15;
    const int tid = threadIdx.x, wid = tid >> 5, lane = tid & 31;
    const int g = lane >> 2, t = lane & 3;
    const int grp = lane >> 3, l7 = lane & 7;
    const int q0 = qt * 128;
    const int mrow = wid * 16 + g;

    const int kb_off = ((grp >> 1) * 8 + l7) * ASTR + (grp & 1) * 8;   // K (non-trans B)
    const int v_off  = ((grp & 1) * 8 + l7) * ASTR + (grp >> 1) * 8;   // V (trans B)

    const size_t rowbase = (size_t)(bb * S_);

    // ---- issue Q-hi load (into stage 1 region) + KV tile 0 (stage 0)
    {
        #pragma unroll
        for (int p = 0; p < 4; p++) {
            int o = tid + p * 256;
            int r = o >> 3, sg = o & 7;
            const __half* src = g_qkv_hi + (rowbase + q0 + r) * N3_ + h * DH_ + sg * 8;
            cp16(sb + (uint32_t)(STG + r * ASTR + sg * 8) * 2, src);
        }
        CP_COMMIT();
    }
    auto load_kv = [&](int j0, int s) {
        #pragma unroll
        for (int p = 0; p < 6; p++) {
            int o = tid + p * 256;
            int arr = o >> 9, r = (o >> 3) & 63, sg = o & 7;
            // arr: 0=KH 1=KL 2=VH
            const __half* src =
                (arr == 0) ? g_qkv_hi + (rowbase + j0 + r) * N3_ + D_ + h * DH_ + sg * 8 :
                (arr == 1) ? g_qkv_lo + (rowbase + j0 + r) * N3_ + D_ + h * DH_ + sg * 8 :
                             g_qkv_hi + (rowbase + j0 + r) * N3_ + 2 * D_ + h * DH_ + sg * 8;
            cp16(sb + (uint32_t)(s * STG + arr * KVROW + r * ASTR + sg * 8) * 2, src);
        }
        CP_COMMIT();
    };
    load_kv(0, 0);

    // ---- wait for Q (KV0 may still be in flight), extract Q-hi fragments
    CP_WAIT(1);
    __syncthreads();
    const __half* smh = g_sm;
    uint32_t qh[4][4];
    #pragma unroll
    for (int ks = 0; ks < 4; ks++) {
        const int kb = 2 * t + 16 * ks;
        const __half* QH = smh + STG;
        qh[ks][0] = lds32(QH + mrow * ASTR + kb);
        qh[ks][1] = lds32(QH + (mrow + 8) * ASTR + kb);
        qh[ks][2] = lds32(QH + mrow * ASTR + kb + 8);
        qh[ks][3] = lds32(QH + (mrow + 8) * ASTR + kb + 8);
    }
    __syncthreads();   // Q reads done before stage-1 is overwritten by tile 1

    float Oacc[8][4] = {};
    float m0r = -1e30f, m1r = -1e30f, l0r = 0.f, l1r = 0.f;

    for (int it = 0; it < 32; it++) {
        if (it + 1 < 32) { load_kv((it + 1) * 64, (it + 1) & 1); CP_WAIT(1); }
        else             { CP_WAIT(0); }
        __syncthreads();

        const uint32_t stg = sb + (uint32_t)((it & 1) * STG) * 2;
        const uint32_t KHb = stg;
        const uint32_t KLb = stg + (uint32_t)KVROW * 2;
        const uint32_t VHb = stg + (uint32_t)(2 * KVROW) * 2;

        // ---- S = Q_hi @ (K_hi + K_lo)^T
        float Sacc[8][4] = {};
        #pragma unroll
        for (int ks = 0; ks < 4; ks++) {
            const int kb0 = 16 * ks;
            #pragma unroll
            for (int np = 0; np < 4; np++) {
                const int n = np * 2;
                const uint32_t off = (uint32_t)(n * 8 * ASTR + kb0 + kb_off) * 2;
                uint32_t kh0, kh1, kh2, kh3, kl0, kl1, kl2, kl3;
                ldsm_x4(kh0, kh1, kh2, kh3, KHb + off);
                ldsm_x4(kl0, kl1, kl2, kl3, KLb + off);
                mma_f16_2(Sacc[n],     qh[ks], kh0, kh1);
                mma_f16_2(Sacc[n],     qh[ks], kl0, kl1);
                mma_f16_2(Sacc[n + 1], qh[ks], kh2, kh3);
                mma_f16_2(Sacc[n + 1], qh[ks], kl2, kl3);
            }
        }
        #pragma unroll
        for (int n = 0; n < 8; n++) {
            Sacc[n][0] *= SCL2; Sacc[n][1] *= SCL2;
            Sacc[n][2] *= SCL2; Sacc[n][3] *= SCL2;
        }

        // ---- online softmax (base-2 domain)
        float mx0 = -1e30f, mx1 = -1e30f;
        #pragma unroll
        for (int n = 0; n < 8; n++) {
            mx0 = fmaxf(mx0, fmaxf(Sacc[n][0], Sacc[n][1]));
            mx1 = fmaxf(mx1, fmaxf(Sacc[n][2], Sacc[n][3]));
        }
        mx0 = fmaxf(mx0, __shfl_xor_sync(0xffffffffu, mx0, 1));
        mx0 = fmaxf(mx0, __shfl_xor_sync(0xffffffffu, mx0, 2));
        mx1 = fmaxf(mx1, __shfl_xor_sync(0xffffffffu, mx1, 1));
        mx1 = fmaxf(mx1, __shfl_xor_sync(0xffffffffu, mx1, 2));

        const float mn0 = fmaxf(m0r, mx0), mn1 = fmaxf(m1r, mx1);
        const float c0 = exp2f(m0r - mn0), c1 = exp2f(m1r - mn1);
        float s0 = 0.f, s1 = 0.f;
        #pragma unroll
        for (int n = 0; n < 8; n++) {
            Sacc[n][0] = exp2f(Sacc[n][0] - mn0);
            Sacc[n][1] = exp2f(Sacc[n][1] - mn0);
            Sacc[n][2] = exp2f(Sacc[n][2] - mn1);
            Sacc[n][3] = exp2f(Sacc[n][3] - mn1);
            s0 += Sacc[n][0] + Sacc[n][1];
            s1 += Sacc[n][2] + Sacc[n][3];
        }
        s0 += __shfl_xor_sync(0xffffffffu, s0, 1);
        s0 += __shfl_xor_sync(0xffffffffu, s0, 2);
        s1 += __shfl_xor_sync(0xffffffffu, s1, 1);
        s1 += __shfl_xor_sync(0xffffffffu, s1, 2);
        l0r = l0r * c0 + s0;  l1r = l1r * c1 + s1;
        m0r = mn0;            m1r = mn1;

        #pragma unroll
        for (int n = 0; n < 8; n++) {
            Oacc[n][0] *= c0; Oacc[n][1] *= c0;
            Oacc[n][2] *= c1; Oacc[n][3] *= c1;
        }

        // ---- O += P_hi @ V_hi (1-product); P fragments from Sacc
        #pragma unroll
        for (int ks = 0; ks < 4; ks++) {
            uint32_t ph[4];
            ph[0] = packh(Sacc[2*ks][0],   Sacc[2*ks][1]);
            ph[1] = packh(Sacc[2*ks][2],   Sacc[2*ks][3]);
            ph[2] = packh(Sacc[2*ks+1][0], Sacc[2*ks+1][1]);
            ph[3] = packh(Sacc[2*ks+1][2], Sacc[2*ks+1][3]);
            #pragma unroll
            for (int np = 0; np < 4; np++) {
                const int n = np * 2;
                const uint32_t off = (uint32_t)(16 * ks * ASTR + n * 8 + v_off) * 2;
                uint32_t vh0, vh1, vh2, vh3;
                ldsm_x4t(vh0, vh1, vh2, vh3, VHb + off);
                mma_f16_2(Oacc[n],     ph, vh0, vh1);
                mma_f16_2(Oacc[n + 1], ph, vh2, vh3);
            }
        }
        __syncthreads();   // stage fully consumed before next load overwrites
    }

    // ---- epilogue: normalize, write hi-only concat for proj GEMM
    const float inv0 = 1.f / l0r, inv1 = 1.f / l1r;
    __half* oh = g_oc_hi + (rowbase + q0) * HD_ + h * DH_;
    #pragma unroll
    for (int n = 0; n < 8; n++) {
        const int c = n * 8 + 2 * t;
        *(uint32_t*)(oh + (size_t)mrow * HD_ + c) =
            packh(Oacc[n][0] * inv0, Oacc[n][1] * inv0);
        *(uint32_t*)(oh + (size_t)(mrow + 8) * HD_ + c) =
            packh(Oacc[n][2] * inv1, Oacc[n][3] * inv1);
    }
}

// ---------------------------------------------------------------------------
extern "C" void kernel_launch(void* const* d_in, const int* in_sizes, int n_in,
                              void* d_out, int out_size)
{
    const float* x  = (const float*)d_in[0];
    const float* Wq = (const float*)d_in[1];
    const float* bq = (const float*)d_in[2];
    const float* Wk = (const float*)d_in[3];
    const float* bk = (const float*)d_in[4];
    const float* Wv = (const float*)d_in[5];
    const float* bv = (const float*)d_in[6];
    const float* Wo = (const float*)d_in[7];
    const float* bo = (const float*)d_in[8];
    float* out = (float*)d_out;

    void *xh, *wth, *wtl, *woh, *wol, *qh, *qlp, *och, *bs;
    cudaGetSymbolAddress(&xh,  g_x_hi);
    cudaGetSymbolAddress(&wth, g_wt_hi);  cudaGetSymbolAddress(&wtl, g_wt_lo);
    cudaGetSymbolAddress(&woh, g_wot_hi); cudaGetSymbolAddress(&wol, g_wot_lo);
    cudaGetSymbolAddress(&qh,  g_qkv_hi); cudaGetSymbolAddress(&qlp, g_qkv_lo);
    cudaGetSymbolAddress(&och, g_oc_hi);
    cudaGetSymbolAddress(&bs,  g_bias);

    cudaFuncSetAttribute(gemm_f16, cudaFuncAttributeMaxDynamicSharedMemorySize, G_SMEM);
    cudaFuncSetAttribute(attn_f16, cudaFuncAttributeMaxDynamicSharedMemorySize, A_SMEM);

    prep_x   <<<BS_ * D_ / 1024, 256>>>(x);
    build_wt <<<dim3(D_ / 32, DH_ / 32, 3 * H_), dim3(32, 8)>>>(Wq, Wk, Wv);
    build_wot<<<dim3(D_ / 32, D_ / 32), dim3(32, 8)>>>(Wo);
    build_bias<<<3, D_>>>(bq, bk, bv);

    gemm_f16<<<dim3(BS_ / 128, N3_ / 128), 256, G_SMEM>>>(
        (const __half*)xh,
        (const __half*)wth, (const __half*)wtl,
        (const float*)bs, nullptr,
        (__half*)qh, (__half*)qlp, N3_);

    attn_f16<<<dim3(S_ / 128, B_ * H_), 256, A_SMEM>>>();

    gemm_f16<<<dim3(BS_ / 128, D_ / 128), 256, G_SMEM>>>(
        (const __half*)och,
        (const __half*)woh, (const __half*)wol,
        bo, out, nullptr, nullptr, D_);
}

// round 13
// speedup vs baseline: 4.5577x; 1.1087x over previous
#include <cuda_runtime.h>
#include <cuda_fp16.h>
#include <cstdint>

// Problem constants
static constexpr int B_  = 2;
static constexpr int S_  = 2048;
static constexpr int D_  = 1024;
static constexpr int H_  = 16;
static constexpr int DH_ = 64;
static constexpr int BS_ = B_ * S_;          // 4096
static constexpr int HD_ = H_ * DH_;         // 1024
static constexpr int N3_ = 3 * D_;           // 3072

// Operand storage. GEMMs: A_hi @ (B_hi + B_lo). Attn: S = Q_hi K_hi^T, O = P_hi V_hi.
__device__ __half g_x_hi [BS_ * D_];                         // A of qkv GEMM (hi only)
__device__ __half g_wt_hi[N3_ * D_],  g_wt_lo[N3_ * D_];     // B of qkv GEMM
__device__ __half g_wot_hi[D_ * D_],  g_wot_lo[D_ * D_];     // B of proj GEMM
__device__ __half g_qkv_hi[BS_ * N3_];                       // q|k|v (hi)
__device__ __half g_qkv_lo[BS_ * N3_];                       // lo (kept for epilogue symmetry; unused by attn)
__device__ __half g_oc_hi[BS_ * HD_];                        // A of proj GEMM (hi only)
__device__ float g_bias[N3_];

// ---------------------------------------------------------------------------
// Helpers
// ---------------------------------------------------------------------------
__device__ __forceinline__ void cp16(uint32_t dst, const void* src) {
    asm volatile("cp.async.cg.shared.global [%0], [%1], 16;" :: "r"(dst), "l"(src));
}
#define CP_COMMIT() asm volatile("cp.async.commit_group;")
#define CP_WAIT(n)  asm volatile("cp.async.wait_group %0;" :: "n"(n))

__device__ __forceinline__ uint32_t smem_u32(const void* p) {
    uint32_t a;
    asm("{ .reg .u64 t; cvta.to.shared.u64 t, %1; cvt.u32.u64 %0, t; }" : "=r"(a) : "l"(p));
    return a;
}
__device__ __forceinline__ uint32_t lds32(const __half* p) {
    return *(const uint32_t*)p;
}
__device__ __forceinline__ void ldsm_x4(uint32_t& r0, uint32_t& r1, uint32_t& r2, uint32_t& r3,
                                        uint32_t addr) {
    asm volatile("ldmatrix.sync.aligned.m8n8.x4.shared.b16 {%0,%1,%2,%3}, [%4];"
                 : "=r"(r0), "=r"(r1), "=r"(r2), "=r"(r3) : "r"(addr));
}
__device__ __forceinline__ void ldsm_x4t(uint32_t& r0, uint32_t& r1, uint32_t& r2, uint32_t& r3,
                                         uint32_t addr) {
    asm volatile("ldmatrix.sync.aligned.m8n8.x4.trans.shared.b16 {%0,%1,%2,%3}, [%4];"
                 : "=r"(r0), "=r"(r1), "=r"(r2), "=r"(r3) : "r"(addr));
}

// m16n8k16 fp16 MMA (A row-major, B col-major), fp32 accumulate
__device__ __forceinline__ void mma_f16_2(float* c, const uint32_t* a, uint32_t b0, uint32_t b1) {
    asm volatile(
        "mma.sync.aligned.m16n8k16.row.col.f32.f16.f16.f32 "
        "{%0,%1,%2,%3}, {%4,%5,%6,%7}, {%8,%9}, {%0,%1,%2,%3};"
        : "+f"(c[0]), "+f"(c[1]), "+f"(c[2]), "+f"(c[3])
        : "r"(a[0]), "r"(a[1]), "r"(a[2]), "r"(a[3]), "r"(b0), "r"(b1));
}

__device__ __forceinline__ uint32_t packh_hi(float a, float b, float& ra, float& rb) {
    __half ha = __float2half_rn(a), hb = __float2half_rn(b);
    ra = a - __half2float(ha);
    rb = b - __half2float(hb);
    return (uint32_t)__half_as_ushort(ha) | ((uint32_t)__half_as_ushort(hb) << 16);
}
__device__ __forceinline__ uint32_t packh(float a, float b) {
    return (uint32_t)__half_as_ushort(__float2half_rn(a)) |
           ((uint32_t)__half_as_ushort(__float2half_rn(b)) << 16);
}

// ---------------------------------------------------------------------------
// Prep kernels
// ---------------------------------------------------------------------------
__global__ void prep_x(const float* __restrict__ x) {
    int i = (blockIdx.x * 256 + threadIdx.x) * 4;
    float4 v = *(const float4*)(x + i);
    *(uint2*)(g_x_hi + i) = make_uint2(packh(v.x, v.y), packh(v.z, v.w));
}

__global__ void build_wt(const float* __restrict__ Wq, const float* __restrict__ Wk,
                         const float* __restrict__ Wv) {
    const int wsel = blockIdx.z >> 4, h = blockIdx.z & 15;
    const float* W = (wsel == 0) ? Wq : (wsel == 1) ? Wk : Wv;
    __shared__ float t[32][33];
    const int k0 = blockIdx.x * 32, d0 = blockIdx.y * 32;
    #pragma unroll
    for (int i = 0; i < 4; i++) {
        int k = k0 + threadIdx.y + i * 8;
        t[threadIdx.y + i * 8][threadIdx.x] = W[(size_t)h * D_ * DH_ + (size_t)k * DH_ + d0 + threadIdx.x];
    }
    __syncthreads();
    #pragma unroll
    for (int i = 0; i < 4; i++) {
        int d = d0 + threadIdx.y + i * 8;
        float v = t[threadIdx.x][threadIdx.y + i * 8];
        size_t idx = (size_t)(wsel * D_ + h * DH_ + d) * D_ + k0 + threadIdx.x;
        __half hv = __float2half_rn(v);
        g_wt_hi[idx] = hv;
        g_wt_lo[idx] = __float2half_rn(v - __half2float(hv));
    }
}

__global__ void build_wot(const float* __restrict__ Wo) {
    __shared__ float t[32][33];
    const int k0 = blockIdx.x * 32, n0 = blockIdx.y * 32;
    #pragma unroll
    for (int i = 0; i < 4; i++)
        t[threadIdx.y + i * 8][threadIdx.x] = Wo[(size_t)(k0 + threadIdx.y + i * 8) * D_ + n0 + threadIdx.x];
    __syncthreads();
    #pragma unroll
    for (int i = 0; i < 4; i++) {
        int n = n0 + threadIdx.y + i * 8;
        float v = t[threadIdx.x][threadIdx.y + i * 8];
        size_t idx = (size_t)n * D_ + k0 + threadIdx.x;
        __half hv = __float2half_rn(v);
        g_wot_hi[idx] = hv;
        g_wot_lo[idx] = __float2half_rn(v - __half2float(hv));
    }
}

__global__ void build_bias(const float* __restrict__ bq, const float* __restrict__ bk,
                           const float* __restrict__ bv) {
    const float* b = (blockIdx.x == 0) ? bq : (blockIdx.x == 1) ? bk : bv;
    g_bias[blockIdx.x * D_ + threadIdx.x] = b[threadIdx.x];
}

// ---------------------------------------------------------------------------
// 2-product GEMM: C = A_hi @ (B_hi + B_lo)^T + bias.
// Tile 128x128, K-chunk 32, double-buffered. Smem tiles: Ah|Bh|Bl.
// ---------------------------------------------------------------------------
static constexpr int TSTR   = 40;             // fp16 per smem row
static constexpr int TTILE  = 128 * TSTR;
static constexpr int TSTAGE = 3 * TTILE;      // Ah|Bh|Bl
static constexpr int G_SMEM = 2 * TSTAGE * 2; // 61440 bytes

extern __shared__ __half g_sm[];

__global__ __launch_bounds__(256) void gemm_f16(
    const __half* __restrict__ Ah,
    const __half* __restrict__ Bh, const __half* __restrict__ Bl,
    const float* __restrict__ bias,
    float* __restrict__ Cf, __half* __restrict__ Ch, __half* __restrict__ Cl,
    int Ntotal)
{
    const uint32_t sb = smem_u32(g_sm);
    const int tid = threadIdx.x, wid = tid >> 5, lane = tid & 31;
    const int g = lane >> 2, t = lane & 3;
    const int grp = lane >> 3, l7 = lane & 7;
    const int wm = wid >> 1, wn = wid & 1;
    const int m0 = blockIdx.x * 128, n0blk = blockIdx.y * 128;

    const int a_off = ((grp & 1) * 8 + l7) * TSTR + (grp >> 1) * 8;
    const int b_off = ((grp >> 1) * 8 + l7) * TSTR + (grp & 1) * 8;

    float Cacc[2][8][4] = {};

    auto load_chunk = [&](int kc, int s) {
        #pragma unroll
        for (int p = 0; p < 6; p++) {
            int o = tid + p * 256;
            int arr = o >> 9, r = (o >> 2) & 127, sg = o & 3;
            const __half* src =
                (arr == 0) ? Ah + (size_t)(m0 + r) * D_ + kc + sg * 8 :
                (arr == 1) ? Bh + (size_t)(n0blk + r) * D_ + kc + sg * 8 :
                             Bl + (size_t)(n0blk + r) * D_ + kc + sg * 8;
            cp16(sb + (uint32_t)(s * TSTAGE + arr * TTILE + r * TSTR + sg * 8) * 2, src);
        }
        CP_COMMIT();
    };

    load_chunk(0, 0);

    for (int ch = 0; ch < 32; ch++) {
        const int s = ch & 1;
        if (ch < 31) { load_chunk((ch + 1) * 32, s ^ 1); CP_WAIT(1); }
        else         { CP_WAIT(0); }
        __syncthreads();

        const uint32_t ah_b = sb + (uint32_t)(s * TSTAGE) * 2;
        const uint32_t bh_b = ah_b + TTILE * 2;
        const uint32_t bl_b = ah_b + 2 * TTILE * 2;

        #pragma unroll
        for (int ks = 0; ks < 2; ks++) {
            const int kb0 = 16 * ks;
            uint32_t af[2][4];
            #pragma unroll
            for (int i = 0; i < 2; i++) {
                const int rb = (wm * 32 + i * 16) * TSTR + kb0;
                ldsm_x4(af[i][0], af[i][1], af[i][2], af[i][3],
                        ah_b + (uint32_t)(rb + a_off) * 2);
            }
            #pragma unroll
            for (int np = 0; np < 4; np++) {
                const int n = np * 2;
                const int rb = (wn * 64 + n * 8) * TSTR + kb0;
                uint32_t bh0, bh1, bh2, bh3, bl0, bl1, bl2, bl3;
                ldsm_x4(bh0, bh1, bh2, bh3, bh_b + (uint32_t)(rb + b_off) * 2);
                ldsm_x4(bl0, bl1, bl2, bl3, bl_b + (uint32_t)(rb + b_off) * 2);
                #pragma unroll
                for (int i = 0; i < 2; i++) {
                    mma_f16_2(Cacc[i][n],     af[i], bh0, bh1);
                    mma_f16_2(Cacc[i][n],     af[i], bl0, bl1);
                    mma_f16_2(Cacc[i][n + 1], af[i], bh2, bh3);
                    mma_f16_2(Cacc[i][n + 1], af[i], bl2, bl3);
                }
            }
        }
        __syncthreads();
    }

    #pragma unroll
    for (int i = 0; i < 2; i++) {
        const int r0 = m0 + wm * 32 + i * 16 + g;
        #pragma unroll
        for (int n = 0; n < 8; n++) {
            const int c = n0blk + wn * 64 + n * 8 + 2 * t;
            float bx = __ldg(bias + c), by = __ldg(bias + c + 1);
            float v00 = Cacc[i][n][0] + bx, v01 = Cacc[i][n][1] + by;
            float v10 = Cacc[i][n][2] + bx, v11 = Cacc[i][n][3] + by;
            if (Cf) {
                *(float2*)(Cf + (size_t)r0 * Ntotal + c)       = make_float2(v00, v01);
                *(float2*)(Cf + (size_t)(r0 + 8) * Ntotal + c) = make_float2(v10, v11);
            } else {
                float ra, rb;
                *(uint32_t*)(Ch + (size_t)r0 * Ntotal + c) = packh_hi(v00, v01, ra, rb);
                *(uint32_t*)(Cl + (size_t)r0 * Ntotal + c) = packh(ra, rb);
                *(uint32_t*)(Ch + (size_t)(r0 + 8) * Ntotal + c) = packh_hi(v10, v11, ra, rb);
                *(uint32_t*)(Cl + (size_t)(r0 + 8) * Ntotal + c) = packh(ra, rb);
            }
        }
    }
}

// ---------------------------------------------------------------------------
// Flash attention: S = Q_hi K_hi^T (1-product), O = P_hi V_hi (1-product).
// Double-buffered cp.async KV (KH|VH), ldmatrix K + V(trans). 128 q, 8 warps.
// ---------------------------------------------------------------------------
static constexpr int ASTR  = 72;                  // halves per row
static constexpr int KVROW = 64 * ASTR;
static constexpr int STG   = 2 * KVROW;           // KH|VH per stage
static constexpr int A_SMEM = 2 * STG * 2 + 128 * ASTR * 2;  // stages + Q park = 55296 B

// softmax in exp2 domain: logits scaled by 0.125 * log2(e)
static constexpr float SCL2 = 0.125f * 1.4426950408889634f;

__global__ __launch_bounds__(256) void attn_f16()
{
    const uint32_t sb = smem_u32(g_sm);
    const int qt = blockIdx.x, bh = blockIdx.y;
    const int bb = bh >> 4, h = bh & 15;
    const int tid = threadIdx.x, wid = tid >> 5, lane = tid & 31;
    const int g = lane >> 2, t = lane & 3;
    const int grp = lane >> 3, l7 = lane & 7;
    const int q0 = qt * 128;
    const int mrow = wid * 16 + g;

    const int kb_off = ((grp >> 1) * 8 + l7) * ASTR + (grp & 1) * 8;   // K (non-trans B)
    const int v_off  = ((grp & 1) * 8 + l7) * ASTR + (grp >> 1) * 8;   // V (trans B)

    const size_t rowbase = (size_t)(bb * S_);

    // ---- issue Q-hi load (into dedicated park region after the 2 stages)
    {
        #pragma unroll
        for (int p = 0; p < 4; p++) {
            int o = tid + p * 256;
            int r = o >> 3, sg = o & 7;
            const __half* src = g_qkv_hi + (rowbase + q0 + r) * N3_ + h * DH_ + sg * 8;
            cp16(sb + (uint32_t)(2 * STG + r * ASTR + sg * 8) * 2, src);
        }
        CP_COMMIT();
    }
    auto load_kv = [&](int j0, int s) {
        #pragma unroll
        for (int p = 0; p < 4; p++) {
            int o = tid + p * 256;
            int arr = o >> 9, r = (o >> 3) & 63, sg = o & 7;
            // arr: 0=KH 1=VH
            const __half* src = g_qkv_hi
                + (rowbase + j0 + r) * N3_ + (arr + 1) * D_ + h * DH_ + sg * 8;
            cp16(sb + (uint32_t)(s * STG + arr * KVROW + r * ASTR + sg * 8) * 2, src);
        }
        CP_COMMIT();
    };
    load_kv(0, 0);

    // ---- wait for Q (KV0 may still be in flight), extract Q-hi fragments
    CP_WAIT(1);
    __syncthreads();
    const __half* smh = g_sm;
    uint32_t qh[4][4];
    #pragma unroll
    for (int ks = 0; ks < 4; ks++) {
        const int kb = 2 * t + 16 * ks;
        const __half* QH = smh + 2 * STG;
        qh[ks][0] = lds32(QH + mrow * ASTR + kb);
        qh[ks][1] = lds32(QH + (mrow + 8) * ASTR + kb);
        qh[ks][2] = lds32(QH + mrow * ASTR + kb + 8);
        qh[ks][3] = lds32(QH + (mrow + 8) * ASTR + kb + 8);
    }

    float Oacc[8][4] = {};
    float m0r = -1e30f, m1r = -1e30f, l0r = 0.f, l1r = 0.f;

    for (int it = 0; it < 32; it++) {
        if (it + 1 < 32) { load_kv((it + 1) * 64, (it + 1) & 1); CP_WAIT(1); }
        else             { CP_WAIT(0); }
        __syncthreads();

        const uint32_t stg = sb + (uint32_t)((it & 1) * STG) * 2;
        const uint32_t KHb = stg;
        const uint32_t VHb = stg + (uint32_t)KVROW * 2;

        // ---- S = Q_hi @ K_hi^T (1-product)
        float Sacc[8][4] = {};
        #pragma unroll
        for (int ks = 0; ks < 4; ks++) {
            const int kb0 = 16 * ks;
            #pragma unroll
            for (int np = 0; np < 4; np++) {
                const int n = np * 2;
                const uint32_t off = (uint32_t)(n * 8 * ASTR + kb0 + kb_off) * 2;
                uint32_t kh0, kh1, kh2, kh3;
                ldsm_x4(kh0, kh1, kh2, kh3, KHb + off);
                mma_f16_2(Sacc[n],     qh[ks], kh0, kh1);
                mma_f16_2(Sacc[n + 1], qh[ks], kh2, kh3);
            }
        }
        #pragma unroll
        for (int n = 0; n < 8; n++) {
            Sacc[n][0] *= SCL2; Sacc[n][1] *= SCL2;
            Sacc[n][2] *= SCL2; Sacc[n][3] *= SCL2;
        }

        // ---- online softmax (base-2 domain)
        float mx0 = -1e30f, mx1 = -1e30f;
        #pragma unroll
        for (int n = 0; n < 8; n++) {
            mx0 = fmaxf(mx0, fmaxf(Sacc[n][0], Sacc[n][1]));
            mx1 = fmaxf(mx1, fmaxf(Sacc[n][2], Sacc[n][3]));
        }
        mx0 = fmaxf(mx0, __shfl_xor_sync(0xffffffffu, mx0, 1));
        mx0 = fmaxf(mx0, __shfl_xor_sync(0xffffffffu, mx0, 2));
        mx1 = fmaxf(mx1, __shfl_xor_sync(0xffffffffu, mx1, 1));
        mx1 = fmaxf(mx1, __shfl_xor_sync(0xffffffffu, mx1, 2));

        const float mn0 = fmaxf(m0r, mx0), mn1 = fmaxf(m1r, mx1);
        const float c0 = exp2f(m0r - mn0), c1 = exp2f(m1r - mn1);
        float s0 = 0.f, s1 = 0.f;
        #pragma unroll
        for (int n = 0; n < 8; n++) {
            Sacc[n][0] = exp2f(Sacc[n][0] - mn0);
            Sacc[n][1] = exp2f(Sacc[n][1] - mn0);
            Sacc[n][2] = exp2f(Sacc[n][2] - mn1);
            Sacc[n][3] = exp2f(Sacc[n][3] - mn1);
            s0 += Sacc[n][0] + Sacc[n][1];
            s1 += Sacc[n][2] + Sacc[n][3];
        }
        s0 += __shfl_xor_sync(0xffffffffu, s0, 1);
        s0 += __shfl_xor_sync(0xffffffffu, s0, 2);
        s1 += __shfl_xor_sync(0xffffffffu, s1, 1);
        s1 += __shfl_xor_sync(0xffffffffu, s1, 2);
        l0r = l0r * c0 + s0;  l1r = l1r * c1 + s1;
        m0r = mn0;            m1r = mn1;

        #pragma unroll
        for (int n = 0; n < 8; n++) {
            Oacc[n][0] *= c0; Oacc[n][1] *= c0;
            Oacc[n][2] *= c1; Oacc[n][3] *= c1;
        }

        // ---- O += P_hi @ V_hi (1-product); P fragments from Sacc
        #pragma unroll
        for (int ks = 0; ks < 4; ks++) {
            uint32_t ph[4];
            ph[0] = packh(Sacc[2*ks][0],   Sacc[2*ks][1]);
            ph[1] = packh(Sacc[2*ks][2],   Sacc[2*ks][3]);
            ph[2] = packh(Sacc[2*ks+1][0], Sacc[2*ks+1][1]);
            ph[3] = packh(Sacc[2*ks+1][2], Sacc[2*ks+1][3]);
            #pragma unroll
            for (int np = 0; np < 4; np++) {
                const int n = np * 2;
                const uint32_t off = (uint32_t)(16 * ks * ASTR + n * 8 + v_off) * 2;
                uint32_t vh0, vh1, vh2, vh3;
                ldsm_x4t(vh0, vh1, vh2, vh3, VHb + off);
                mma_f16_2(Oacc[n],     ph, vh0, vh1);
                mma_f16_2(Oacc[n + 1], ph, vh2, vh3);
            }
        }
        __syncthreads();   // stage fully consumed before next load overwrites
    }

    // ---- epilogue: normalize, write hi-only concat for proj GEMM
    const float inv0 = 1.f / l0r, inv1 = 1.f / l1r;
    __half* oh = g_oc_hi + (rowbase + q0) * HD_ + h * DH_;
    #pragma unroll
    for (int n = 0; n < 8; n++) {
        const int c = n * 8 + 2 * t;
        *(uint32_t*)(oh + (size_t)mrow * HD_ + c) =
            packh(Oacc[n][0] * inv0, Oacc[n][1] * inv0);
        *(uint32_t*)(oh + (size_t)(mrow + 8) * HD_ + c) =
            packh(Oacc[n][2] * inv1, Oacc[n][3] * inv1);
    }
}

// ---------------------------------------------------------------------------
extern "C" void kernel_launch(void* const* d_in, const int* in_sizes, int n_in,
                              void* d_out, int out_size)
{
    const float* x  = (const float*)d_in[0];
    const float* Wq = (const float*)d_in[1];
    const float* bq = (const float*)d_in[2];
    const float* Wk = (const float*)d_in[3];
    const float* bk = (const float*)d_in[4];
    const float* Wv = (const float*)d_in[5];
    const float* bv = (const float*)d_in[6];
    const float* Wo = (const float*)d_in[7];
    const float* bo = (const float*)d_in[8];
    float* out = (float*)d_out;

    void *xh, *wth, *wtl, *woh, *wol, *qh, *qlp, *och, *bs;
    cudaGetSymbolAddress(&xh,  g_x_hi);
    cudaGetSymbolAddress(&wth, g_wt_hi);  cudaGetSymbolAddress(&wtl, g_wt_lo);
    cudaGetSymbolAddress(&woh, g_wot_hi); cudaGetSymbolAddress(&wol, g_wot_lo);
    cudaGetSymbolAddress(&qh,  g_qkv_hi); cudaGetSymbolAddress(&qlp, g_qkv_lo);
    cudaGetSymbolAddress(&och, g_oc_hi);
    cudaGetSymbolAddress(&bs,  g_bias);

    cudaFuncSetAttribute(gemm_f16, cudaFuncAttributeMaxDynamicSharedMemorySize, G_SMEM);
    cudaFuncSetAttribute(attn_f16, cudaFuncAttributeMaxDynamicSharedMemorySize, A_SMEM);

    prep_x   <<<BS_ * D_ / 1024, 256>>>(x);
    build_wt <<<dim3(D_ / 32, DH_ / 32, 3 * H_), dim3(32, 8)>>>(Wq, Wk, Wv);
    build_wot<<<dim3(D_ / 32, D_ / 32), dim3(32, 8)>>>(Wo);
    build_bias<<<3, D_>>>(bq, bk, bv);

    gemm_f16<<<dim3(BS_ / 128, N3_ / 128), 256, G_SMEM>>>(
        (const __half*)xh,
        (const __half*)wth, (const __half*)wtl,
        (const float*)bs, nullptr,
        (__half*)qh, (__half*)qlp, N3_);

    attn_f16<<<dim3(S_ / 128, B_ * H_), 256, A_SMEM>>>();

    gemm_f16<<<dim3(BS_ / 128, D_ / 128), 256, G_SMEM>>>(
        (const __half*)och,
        (const __half*)woh, (const __half*)wol,
        bo, out, nullptr, nullptr, D_);
}

// round 14
// speedup vs baseline: 5.9101x; 1.2967x over previous
#include <cuda_runtime.h>
#include <cuda_fp16.h>
#include <cstdint>

// Problem constants
static constexpr int B_  = 2;
static constexpr int S_  = 2048;
static constexpr int D_  = 1024;
static constexpr int H_  = 16;
static constexpr int DH_ = 64;
static constexpr int BS_ = B_ * S_;          // 4096
static constexpr int HD_ = H_ * DH_;         // 1024
static constexpr int N3_ = 3 * D_;           // 3072

// Plain fp16 pipeline (fp32 accumulate everywhere).
__device__ __half g_x_hi [BS_ * D_];         // A of qkv GEMM
__device__ __half g_wt_hi[N3_ * D_];         // B of qkv GEMM [n][k]
__device__ __half g_wot_hi[D_ * D_];         // B of proj GEMM [n][k]
__device__ __half g_qkv_hi[BS_ * N3_];       // q|k|v
__device__ __half g_oc_hi[BS_ * HD_];        // A of proj GEMM
__device__ float g_bias[N3_];

// ---------------------------------------------------------------------------
// Helpers
// ---------------------------------------------------------------------------
__device__ __forceinline__ void cp16(uint32_t dst, const void* src) {
    asm volatile("cp.async.cg.shared.global [%0], [%1], 16;" :: "r"(dst), "l"(src));
}
#define CP_COMMIT() asm volatile("cp.async.commit_group;")
#define CP_WAIT(n)  asm volatile("cp.async.wait_group %0;" :: "n"(n))

__device__ __forceinline__ uint32_t smem_u32(const void* p) {
    uint32_t a;
    asm("{ .reg .u64 t; cvta.to.shared.u64 t, %1; cvt.u32.u64 %0, t; }" : "=r"(a) : "l"(p));
    return a;
}
__device__ __forceinline__ uint32_t lds32(const __half* p) {
    return *(const uint32_t*)p;
}
__device__ __forceinline__ void ldsm_x4(uint32_t& r0, uint32_t& r1, uint32_t& r2, uint32_t& r3,
                                        uint32_t addr) {
    asm volatile("ldmatrix.sync.aligned.m8n8.x4.shared.b16 {%0,%1,%2,%3}, [%4];"
                 : "=r"(r0), "=r"(r1), "=r"(r2), "=r"(r3) : "r"(addr));
}
__device__ __forceinline__ void ldsm_x4t(uint32_t& r0, uint32_t& r1, uint32_t& r2, uint32_t& r3,
                                         uint32_t addr) {
    asm volatile("ldmatrix.sync.aligned.m8n8.x4.trans.shared.b16 {%0,%1,%2,%3}, [%4];"
                 : "=r"(r0), "=r"(r1), "=r"(r2), "=r"(r3) : "r"(addr));
}

// m16n8k16 fp16 MMA (A row-major, B col-major), fp32 accumulate
__device__ __forceinline__ void mma_f16_2(float* c, const uint32_t* a, uint32_t b0, uint32_t b1) {
    asm volatile(
        "mma.sync.aligned.m16n8k16.row.col.f32.f16.f16.f32 "
        "{%0,%1,%2,%3}, {%4,%5,%6,%7}, {%8,%9}, {%0,%1,%2,%3};"
        : "+f"(c[0]), "+f"(c[1]), "+f"(c[2]), "+f"(c[3])
        : "r"(a[0]), "r"(a[1]), "r"(a[2]), "r"(a[3]), "r"(b0), "r"(b1));
}

__device__ __forceinline__ uint32_t packh(float a, float b) {
    return (uint32_t)__half_as_ushort(__float2half_rn(a)) |
           ((uint32_t)__half_as_ushort(__float2half_rn(b)) << 16);
}

// ---------------------------------------------------------------------------
// Prep kernels
// ---------------------------------------------------------------------------
__global__ void prep_x(const float* __restrict__ x) {
    int i = (blockIdx.x * 256 + threadIdx.x) * 4;
    float4 v = *(const float4*)(x + i);
    *(uint2*)(g_x_hi + i) = make_uint2(packh(v.x, v.y), packh(v.z, v.w));
}

__global__ void build_wt(const float* __restrict__ Wq, const float* __restrict__ Wk,
                         const float* __restrict__ Wv) {
    const int wsel = blockIdx.z >> 4, h = blockIdx.z & 15;
    const float* W = (wsel == 0) ? Wq : (wsel == 1) ? Wk : Wv;
    __shared__ float t[32][33];
    const int k0 = blockIdx.x * 32, d0 = blockIdx.y * 32;
    #pragma unroll
    for (int i = 0; i < 4; i++) {
        int k = k0 + threadIdx.y + i * 8;
        t[threadIdx.y + i * 8][threadIdx.x] = W[(size_t)h * D_ * DH_ + (size_t)k * DH_ + d0 + threadIdx.x];
    }
    __syncthreads();
    #pragma unroll
    for (int i = 0; i < 4; i++) {
        int d = d0 + threadIdx.y + i * 8;
        size_t idx = (size_t)(wsel * D_ + h * DH_ + d) * D_ + k0 + threadIdx.x;
        g_wt_hi[idx] = __float2half_rn(t[threadIdx.x][threadIdx.y + i * 8]);
    }
}

__global__ void build_wot(const float* __restrict__ Wo) {
    __shared__ float t[32][33];
    const int k0 = blockIdx.x * 32, n0 = blockIdx.y * 32;
    #pragma unroll
    for (int i = 0; i < 4; i++)
        t[threadIdx.y + i * 8][threadIdx.x] = Wo[(size_t)(k0 + threadIdx.y + i * 8) * D_ + n0 + threadIdx.x];
    __syncthreads();
    #pragma unroll
    for (int i = 0; i < 4; i++) {
        int n = n0 + threadIdx.y + i * 8;
        size_t idx = (size_t)n * D_ + k0 + threadIdx.x;
        g_wot_hi[idx] = __float2half_rn(t[threadIdx.x][threadIdx.y + i * 8]);
    }
}

__global__ void build_bias(const float* __restrict__ bq, const float* __restrict__ bk,
                           const float* __restrict__ bv) {
    const float* b = (blockIdx.x == 0) ? bq : (blockIdx.x == 1) ? bk : bv;
    g_bias[blockIdx.x * D_ + threadIdx.x] = b[threadIdx.x];
}

// ---------------------------------------------------------------------------
// fp16 GEMM: C = A @ B^T + bias. Tile 128x128, K-chunk 32, double-buffered.
// Smem stage: Ah|Bh.
// ---------------------------------------------------------------------------
static constexpr int TSTR   = 40;             // fp16 per smem row
static constexpr int TTILE  = 128 * TSTR;
static constexpr int TSTAGE = 2 * TTILE;      // Ah|Bh
static constexpr int G_SMEM = 2 * TSTAGE * 2; // 40960 bytes

extern __shared__ __half g_sm[];

__global__ __launch_bounds__(256) void gemm_f16(
    const __half* __restrict__ Ah, const __half* __restrict__ Bh,
    const float* __restrict__ bias,
    float* __restrict__ Cf, __half* __restrict__ Ch,
    int Ntotal)
{
    const uint32_t sb = smem_u32(g_sm);
    const int tid = threadIdx.x, wid = tid >> 5, lane = tid & 31;
    const int g = lane >> 2, t = lane & 3;
    const int grp = lane >> 3, l7 = lane & 7;
    const int wm = wid >> 1, wn = wid & 1;
    const int m0 = blockIdx.x * 128, n0blk = blockIdx.y * 128;

    const int a_off = ((grp & 1) * 8 + l7) * TSTR + (grp >> 1) * 8;
    const int b_off = ((grp >> 1) * 8 + l7) * TSTR + (grp & 1) * 8;

    float Cacc[2][8][4] = {};

    auto load_chunk = [&](int kc, int s) {
        #pragma unroll
        for (int p = 0; p < 4; p++) {
            int o = tid + p * 256;
            int arr = o >> 9, r = (o >> 2) & 127, sg = o & 3;
            const __half* src =
                (arr == 0) ? Ah + (size_t)(m0 + r) * D_ + kc + sg * 8
                           : Bh + (size_t)(n0blk + r) * D_ + kc + sg * 8;
            cp16(sb + (uint32_t)(s * TSTAGE + arr * TTILE + r * TSTR + sg * 8) * 2, src);
        }
        CP_COMMIT();
    };

    load_chunk(0, 0);

    for (int ch = 0; ch < 32; ch++) {
        const int s = ch & 1;
        if (ch < 31) { load_chunk((ch + 1) * 32, s ^ 1); CP_WAIT(1); }
        else         { CP_WAIT(0); }
        __syncthreads();

        const uint32_t ah_b = sb + (uint32_t)(s * TSTAGE) * 2;
        const uint32_t bh_b = ah_b + TTILE * 2;

        #pragma unroll
        for (int ks = 0; ks < 2; ks++) {
            const int kb0 = 16 * ks;
            uint32_t af[2][4];
            #pragma unroll
            for (int i = 0; i < 2; i++) {
                const int rb = (wm * 32 + i * 16) * TSTR + kb0;
                ldsm_x4(af[i][0], af[i][1], af[i][2], af[i][3],
                        ah_b + (uint32_t)(rb + a_off) * 2);
            }
            #pragma unroll
            for (int np = 0; np < 4; np++) {
                const int n = np * 2;
                const int rb = (wn * 64 + n * 8) * TSTR + kb0;
                uint32_t bh0, bh1, bh2, bh3;
                ldsm_x4(bh0, bh1, bh2, bh3, bh_b + (uint32_t)(rb + b_off) * 2);
                #pragma unroll
                for (int i = 0; i < 2; i++) {
                    mma_f16_2(Cacc[i][n],     af[i], bh0, bh1);
                    mma_f16_2(Cacc[i][n + 1], af[i], bh2, bh3);
                }
            }
        }
        __syncthreads();
    }

    #pragma unroll
    for (int i = 0; i < 2; i++) {
        const int r0 = m0 + wm * 32 + i * 16 + g;
        #pragma unroll
        for (int n = 0; n < 8; n++) {
            const int c = n0blk + wn * 64 + n * 8 + 2 * t;
            float bx = __ldg(bias + c), by = __ldg(bias + c + 1);
            float v00 = Cacc[i][n][0] + bx, v01 = Cacc[i][n][1] + by;
            float v10 = Cacc[i][n][2] + bx, v11 = Cacc[i][n][3] + by;
            if (Cf) {
                *(float2*)(Cf + (size_t)r0 * Ntotal + c)       = make_float2(v00, v01);
                *(float2*)(Cf + (size_t)(r0 + 8) * Ntotal + c) = make_float2(v10, v11);
            } else {
                *(uint32_t*)(Ch + (size_t)r0 * Ntotal + c)       = packh(v00, v01);
                *(uint32_t*)(Ch + (size_t)(r0 + 8) * Ntotal + c) = packh(v10, v11);
            }
        }
    }
}

// ---------------------------------------------------------------------------
// Flash attention: S = Q K^T, O = P V (plain fp16, fp32 accum).
// Double-buffered cp.async KV (KH|VH), ldmatrix K + V(trans). 128 q, 8 warps.
// ---------------------------------------------------------------------------
static constexpr int ASTR  = 72;                  // halves per row
static constexpr int KVROW = 64 * ASTR;
static constexpr int STG   = 2 * KVROW;           // KH|VH per stage
static constexpr int A_SMEM = 2 * STG * 2 + 128 * ASTR * 2;  // stages + Q park = 55296 B

// softmax in exp2 domain: logits scaled by 0.125 * log2(e)
static constexpr float SCL2 = 0.125f * 1.4426950408889634f;

__global__ __launch_bounds__(256) void attn_f16()
{
    const uint32_t sb = smem_u32(g_sm);
    const int qt = blockIdx.x, bh = blockIdx.y;
    const int bb = bh >> 4, h = bh & 15;
    const int tid = threadIdx.x, wid = tid >> 5, lane = tid & 31;
    const int g = lane >> 2, t = lane & 3;
    const int grp = lane >> 3, l7 = lane & 7;
    const int q0 = qt * 128;
    const int mrow = wid * 16 + g;

    const int kb_off = ((grp >> 1) * 8 + l7) * ASTR + (grp & 1) * 8;   // K (non-trans B)
    const int v_off  = ((grp & 1) * 8 + l7) * ASTR + (grp >> 1) * 8;   // V (trans B)

    const size_t rowbase = (size_t)(bb * S_);

    // ---- issue Q load (into dedicated park region after the 2 stages)
    {
        #pragma unroll
        for (int p = 0; p < 4; p++) {
            int o = tid + p * 256;
            int r = o >> 3, sg = o & 7;
            const __half* src = g_qkv_hi + (rowbase + q0 + r) * N3_ + h * DH_ + sg * 8;
            cp16(sb + (uint32_t)(2 * STG + r * ASTR + sg * 8) * 2, src);
        }
        CP_COMMIT();
    }
    auto load_kv = [&](int j0, int s) {
        #pragma unroll
        for (int p = 0; p < 4; p++) {
            int o = tid + p * 256;
            int arr = o >> 9, r = (o >> 3) & 63, sg = o & 7;
            // arr: 0=KH 1=VH
            const __half* src = g_qkv_hi
                + (rowbase + j0 + r) * N3_ + (arr + 1) * D_ + h * DH_ + sg * 8;
            cp16(sb + (uint32_t)(s * STG + arr * KVROW + r * ASTR + sg * 8) * 2, src);
        }
        CP_COMMIT();
    };
    load_kv(0, 0);

    // ---- wait for Q (KV0 may still be in flight), extract Q fragments
    CP_WAIT(1);
    __syncthreads();
    const __half* smh = g_sm;
    uint32_t qh[4][4];
    #pragma unroll
    for (int ks = 0; ks < 4; ks++) {
        const int kb = 2 * t + 16 * ks;
        const __half* QH = smh + 2 * STG;
        qh[ks][0] = lds32(QH + mrow * ASTR + kb);
        qh[ks][1] = lds32(QH + (mrow + 8) * ASTR + kb);
        qh[ks][2] = lds32(QH + mrow * ASTR + kb + 8);
        qh[ks][3] = lds32(QH + (mrow + 8) * ASTR + kb + 8);
    }

    float Oacc[8][4] = {};
    float m0r = -1e30f, m1r = -1e30f, l0r = 0.f, l1r = 0.f;

    for (int it = 0; it < 32; it++) {
        if (it + 1 < 32) { load_kv((it + 1) * 64, (it + 1) & 1); CP_WAIT(1); }
        else             { CP_WAIT(0); }
        __syncthreads();

        const uint32_t stg = sb + (uint32_t)((it & 1) * STG) * 2;
        const uint32_t KHb = stg;
        const uint32_t VHb = stg + (uint32_t)KVROW * 2;

        // ---- S = Q @ K^T
        float Sacc[8][4] = {};
        #pragma unroll
        for (int ks = 0; ks < 4; ks++) {
            const int kb0 = 16 * ks;
            #pragma unroll
            for (int np = 0; np < 4; np++) {
                const int n = np * 2;
                const uint32_t off = (uint32_t)(n * 8 * ASTR + kb0 + kb_off) * 2;
                uint32_t kh0, kh1, kh2, kh3;
                ldsm_x4(kh0, kh1, kh2, kh3, KHb + off);
                mma_f16_2(Sacc[n],     qh[ks], kh0, kh1);
                mma_f16_2(Sacc[n + 1], qh[ks], kh2, kh3);
            }
        }
        #pragma unroll
        for (int n = 0; n < 8; n++) {
            Sacc[n][0] *= SCL2; Sacc[n][1] *= SCL2;
            Sacc[n][2] *= SCL2; Sacc[n][3] *= SCL2;
        }

        // ---- online softmax (base-2 domain)
        float mx0 = -1e30f, mx1 = -1e30f;
        #pragma unroll
        for (int n = 0; n < 8; n++) {
            mx0 = fmaxf(mx0, fmaxf(Sacc[n][0], Sacc[n][1]));
            mx1 = fmaxf(mx1, fmaxf(Sacc[n][2], Sacc[n][3]));
        }
        mx0 = fmaxf(mx0, __shfl_xor_sync(0xffffffffu, mx0, 1));
        mx0 = fmaxf(mx0, __shfl_xor_sync(0xffffffffu, mx0, 2));
        mx1 = fmaxf(mx1, __shfl_xor_sync(0xffffffffu, mx1, 1));
        mx1 = fmaxf(mx1, __shfl_xor_sync(0xffffffffu, mx1, 2));

        const float mn0 = fmaxf(m0r, mx0), mn1 = fmaxf(m1r, mx1);
        const float c0 = exp2f(m0r - mn0), c1 = exp2f(m1r - mn1);
        float s0 = 0.f, s1 = 0.f;
        #pragma unroll
        for (int n = 0; n < 8; n++) {
            Sacc[n][0] = exp2f(Sacc[n][0] - mn0);
            Sacc[n][1] = exp2f(Sacc[n][1] - mn0);
            Sacc[n][2] = exp2f(Sacc[n][2] - mn1);
            Sacc[n][3] = exp2f(Sacc[n][3] - mn1);
            s0 += Sacc[n][0] + Sacc[n][1];
            s1 += Sacc[n][2] + Sacc[n][3];
        }
        s0 += __shfl_xor_sync(0xffffffffu, s0, 1);
        s0 += __shfl_xor_sync(0xffffffffu, s0, 2);
        s1 += __shfl_xor_sync(0xffffffffu, s1, 1);
        s1 += __shfl_xor_sync(0xffffffffu, s1, 2);
        l0r = l0r * c0 + s0;  l1r = l1r * c1 + s1;
        m0r = mn0;            m1r = mn1;

        #pragma unroll
        for (int n = 0; n < 8; n++) {
            Oacc[n][0] *= c0; Oacc[n][1] *= c0;
            Oacc[n][2] *= c1; Oacc[n][3] *= c1;
        }

        // ---- O += P @ V; P fragments from Sacc
        #pragma unroll
        for (int ks = 0; ks < 4; ks++) {
            uint32_t ph[4];
            ph[0] = packh(Sacc[2*ks][0],   Sacc[2*ks][1]);
            ph[1] = packh(Sacc[2*ks][2],   Sacc[2*ks][3]);
            ph[2] = packh(Sacc[2*ks+1][0], Sacc[2*ks+1][1]);
            ph[3] = packh(Sacc[2*ks+1][2], Sacc[2*ks+1][3]);
            #pragma unroll
            for (int np = 0; np < 4; np++) {
                const int n = np * 2;
                const uint32_t off = (uint32_t)(16 * ks * ASTR + n * 8 + v_off) * 2;
                uint32_t vh0, vh1, vh2, vh3;
                ldsm_x4t(vh0, vh1, vh2, vh3, VHb + off);
                mma_f16_2(Oacc[n],     ph, vh0, vh1);
                mma_f16_2(Oacc[n + 1], ph, vh2, vh3);
            }
        }
        __syncthreads();   // stage fully consumed before next load overwrites
    }

    // ---- epilogue: normalize, write fp16 concat for proj GEMM
    const float inv0 = 1.f / l0r, inv1 = 1.f / l1r;
    __half* oh = g_oc_hi + (rowbase + q0) * HD_ + h * DH_;
    #pragma unroll
    for (int n = 0; n < 8; n++) {
        const int c = n * 8 + 2 * t;
        *(uint32_t*)(oh + (size_t)mrow * HD_ + c) =
            packh(Oacc[n][0] * inv0, Oacc[n][1] * inv0);
        *(uint32_t*)(oh + (size_t)(mrow + 8) * HD_ + c) =
            packh(Oacc[n][2] * inv1, Oacc[n][3] * inv1);
    }
}

// ---------------------------------------------------------------------------
extern "C" void kernel_launch(void* const* d_in, const int* in_sizes, int n_in,
                              void* d_out, int out_size)
{
    const float* x  = (const float*)d_in[0];
    const float* Wq = (const float*)d_in[1];
    const float* bq = (const float*)d_in[2];
    const float* Wk = (const float*)d_in[3];
    const float* bk = (const float*)d_in[4];
    const float* Wv = (const float*)d_in[5];
    const float* bv = (const float*)d_in[6];
    const float* Wo = (const float*)d_in[7];
    const float* bo = (const float*)d_in[8];
    float* out = (float*)d_out;

    void *xh, *wth, *woh, *qh, *och, *bs;
    cudaGetSymbolAddress(&xh,  g_x_hi);
    cudaGetSymbolAddress(&wth, g_wt_hi);
    cudaGetSymbolAddress(&woh, g_wot_hi);
    cudaGetSymbolAddress(&qh,  g_qkv_hi);
    cudaGetSymbolAddress(&och, g_oc_hi);
    cudaGetSymbolAddress(&bs,  g_bias);

    cudaFuncSetAttribute(gemm_f16, cudaFuncAttributeMaxDynamicSharedMemorySize, G_SMEM);
    cudaFuncSetAttribute(attn_f16, cudaFuncAttributeMaxDynamicSharedMemorySize, A_SMEM);

    prep_x   <<<BS_ * D_ / 1024, 256>>>(x);
    build_wt <<<dim3(D_ / 32, DH_ / 32, 3 * H_), dim3(32, 8)>>>(Wq, Wk, Wv);
    build_wot<<<dim3(D_ / 32, D_ / 32), dim3(32, 8)>>>(Wo);
    build_bias<<<3, D_>>>(bq, bk, bv);

    gemm_f16<<<dim3(BS_ / 128, N3_ / 128), 256, G_SMEM>>>(
        (const __half*)xh, (const __half*)wth,
        (const float*)bs, nullptr, (__half*)qh, N3_);

    attn_f16<<<dim3(S_ / 128, B_ * H_), 256, A_SMEM>>>();

    gemm_f16<<<dim3(BS_ / 128, D_ / 128), 256, G_SMEM>>>(
        (const __half*)och, (const __half*)woh,
        bo, out, nullptr, D_);
}

// round 15
// speedup vs baseline: 6.1697x; 1.0439x over previous
#include <cuda_runtime.h>
#include <cuda_fp16.h>
#include <cstdint>

// Problem constants
static constexpr int B_  = 2;
static constexpr int S_  = 2048;
static constexpr int D_  = 1024;
static constexpr int H_  = 16;
static constexpr int DH_ = 64;
static constexpr int BS_ = B_ * S_;          // 4096
static constexpr int HD_ = H_ * DH_;         // 1024
static constexpr int N3_ = 3 * D_;           // 3072

// Plain fp16 pipeline (fp32 accumulate everywhere).
__device__ __half g_x_hi [BS_ * D_];         // A of qkv GEMM
__device__ __half g_wt_hi[N3_ * D_];         // B of qkv GEMM [n][k]
__device__ __half g_wot_hi[D_ * D_];         // B of proj GEMM [n][k]
__device__ __half g_qkv_hi[BS_ * N3_];       // q|k|v
__device__ __half g_oc_hi[BS_ * HD_];        // A of proj GEMM
__device__ float g_bias[N3_];

// ---------------------------------------------------------------------------
// Helpers
// ---------------------------------------------------------------------------
__device__ __forceinline__ void cp16(uint32_t dst, const void* src) {
    asm volatile("cp.async.cg.shared.global [%0], [%1], 16;" :: "r"(dst), "l"(src));
}
#define CP_COMMIT() asm volatile("cp.async.commit_group;")
#define CP_WAIT(n)  asm volatile("cp.async.wait_group %0;" :: "n"(n))

__device__ __forceinline__ uint32_t smem_u32(const void* p) {
    uint32_t a;
    asm("{ .reg .u64 t; cvta.to.shared.u64 t, %1; cvt.u32.u64 %0, t; }" : "=r"(a) : "l"(p));
    return a;
}
__device__ __forceinline__ uint32_t lds32(const __half* p) {
    return *(const uint32_t*)p;
}
__device__ __forceinline__ void ldsm_x4(uint32_t& r0, uint32_t& r1, uint32_t& r2, uint32_t& r3,
                                        uint32_t addr) {
    asm volatile("ldmatrix.sync.aligned.m8n8.x4.shared.b16 {%0,%1,%2,%3}, [%4];"
                 : "=r"(r0), "=r"(r1), "=r"(r2), "=r"(r3) : "r"(addr));
}
__device__ __forceinline__ void ldsm_x4t(uint32_t& r0, uint32_t& r1, uint32_t& r2, uint32_t& r3,
                                         uint32_t addr) {
    asm volatile("ldmatrix.sync.aligned.m8n8.x4.trans.shared.b16 {%0,%1,%2,%3}, [%4];"
                 : "=r"(r0), "=r"(r1), "=r"(r2), "=r"(r3) : "r"(addr));
}

// m16n8k16 fp16 MMA (A row-major, B col-major), fp32 accumulate
__device__ __forceinline__ void mma_f16_2(float* c, const uint32_t* a, uint32_t b0, uint32_t b1) {
    asm volatile(
        "mma.sync.aligned.m16n8k16.row.col.f32.f16.f16.f32 "
        "{%0,%1,%2,%3}, {%4,%5,%6,%7}, {%8,%9}, {%0,%1,%2,%3};"
        : "+f"(c[0]), "+f"(c[1]), "+f"(c[2]), "+f"(c[3])
        : "r"(a[0]), "r"(a[1]), "r"(a[2]), "r"(a[3]), "r"(b0), "r"(b1));
}

__device__ __forceinline__ uint32_t packh(float a, float b) {
    return (uint32_t)__half_as_ushort(__float2half_rn(a)) |
           ((uint32_t)__half_as_ushort(__float2half_rn(b)) << 16);
}

// ---------------------------------------------------------------------------
// Fused prep kernel: block-range dispatch.
//   [0,4096):      x -> fp16
//   [4096,7168):   qkv weight transpose + convert   (3072 blocks)
//   [7168,8192):   Wo transpose + convert           (1024 blocks)
//   [8192,8195):   bias concat
// ---------------------------------------------------------------------------
__global__ __launch_bounds__(256) void prep_all(
    const float* __restrict__ x,
    const float* __restrict__ Wq, const float* __restrict__ Wk, const float* __restrict__ Wv,
    const float* __restrict__ Wo,
    const float* __restrict__ bq, const float* __restrict__ bk, const float* __restrict__ bv)
{
    const int bid = blockIdx.x, tid = threadIdx.x;
    if (bid < 4096) {
        int i = bid * 1024 + tid * 4;
        float4 v = *(const float4*)(x + i);
        *(uint2*)(g_x_hi + i) = make_uint2(packh(v.x, v.y), packh(v.z, v.w));
    } else if (bid < 7168) {
        __shared__ float t[32][33];
        const int b = bid - 4096;
        const int z = b >> 6, rem = b & 63;
        const int bx = rem & 31, by = rem >> 5;
        const int wsel = z >> 4, h = z & 15;
        const float* W = (wsel == 0) ? Wq : (wsel == 1) ? Wk : Wv;
        const int k0 = bx * 32, d0 = by * 32;
        const int tx = tid & 31, ty = tid >> 5;
        #pragma unroll
        for (int i = 0; i < 4; i++)
            t[ty + i * 8][tx] = W[(size_t)h * D_ * DH_ + (size_t)(k0 + ty + i * 8) * DH_ + d0 + tx];
        __syncthreads();
        #pragma unroll
        for (int i = 0; i < 4; i++) {
            int d = d0 + ty + i * 8;
            g_wt_hi[(size_t)(wsel * D_ + h * DH_ + d) * D_ + k0 + tx] =
                __float2half_rn(t[tx][ty + i * 8]);
        }
    } else if (bid < 8192) {
        __shared__ float t[32][33];
        const int b = bid - 7168;
        const int bx = b & 31, by = b >> 5;
        const int k0 = bx * 32, n0 = by * 32;
        const int tx = tid & 31, ty = tid >> 5;
        #pragma unroll
        for (int i = 0; i < 4; i++)
            t[ty + i * 8][tx] = Wo[(size_t)(k0 + ty + i * 8) * D_ + n0 + tx];
        __syncthreads();
        #pragma unroll
        for (int i = 0; i < 4; i++) {
            int n = n0 + ty + i * 8;
            g_wot_hi[(size_t)n * D_ + k0 + tx] = __float2half_rn(t[tx][ty + i * 8]);
        }
    } else {
        const int set = bid - 8192;
        const float* b = (set == 0) ? bq : (set == 1) ? bk : bv;
        float4 v = *(const float4*)(b + tid * 4);
        *(float4*)(g_bias + set * 1024 + tid * 4) = v;
    }
}

// ---------------------------------------------------------------------------
// fp16 GEMM: C = A @ B^T + bias. Tile 128x128, K-chunk 32.
// 3-stage cp.async pipeline, ONE __syncthreads per iteration.
// ---------------------------------------------------------------------------
static constexpr int TSTR   = 40;             // fp16 per smem row
static constexpr int TTILE  = 128 * TSTR;
static constexpr int TSTAGE = 2 * TTILE;      // Ah|Bh
static constexpr int G_SMEM = 3 * TSTAGE * 2; // 61440 bytes

extern __shared__ __half g_sm[];

__global__ __launch_bounds__(256) void gemm_f16(
    const __half* __restrict__ Ah, const __half* __restrict__ Bh,
    const float* __restrict__ bias,
    float* __restrict__ Cf, __half* __restrict__ Ch,
    int Ntotal)
{
    const uint32_t sb = smem_u32(g_sm);
    const int tid = threadIdx.x, wid = tid >> 5, lane = tid & 31;
    const int g = lane >> 2, t = lane & 3;
    const int grp = lane >> 3, l7 = lane & 7;
    const int wm = wid >> 1, wn = wid & 1;
    const int m0 = blockIdx.x * 128, n0blk = blockIdx.y * 128;

    const int a_off = ((grp & 1) * 8 + l7) * TSTR + (grp >> 1) * 8;
    const int b_off = ((grp >> 1) * 8 + l7) * TSTR + (grp & 1) * 8;

    float Cacc[2][8][4] = {};

    auto load_chunk = [&](int kc, int s) {
        #pragma unroll
        for (int p = 0; p < 4; p++) {
            int o = tid + p * 256;
            int arr = o >> 9, r = (o >> 2) & 127, sg = o & 3;
            const __half* src =
                (arr == 0) ? Ah + (size_t)(m0 + r) * D_ + kc + sg * 8
                           : Bh + (size_t)(n0blk + r) * D_ + kc + sg * 8;
            cp16(sb + (uint32_t)(s * TSTAGE + arr * TTILE + r * TSTR + sg * 8) * 2, src);
        }
        CP_COMMIT();
    };

    load_chunk(0, 0);
    load_chunk(32, 1);

    for (int ch = 0; ch < 32; ch++) {
        const int s = ch % 3;
        if (ch < 31) { CP_WAIT(1); } else { CP_WAIT(0); }
        __syncthreads();
        if (ch < 30) load_chunk((ch + 2) * 32, (ch + 2) % 3);

        const uint32_t ah_b = sb + (uint32_t)(s * TSTAGE) * 2;
        const uint32_t bh_b = ah_b + TTILE * 2;

        #pragma unroll
        for (int ks = 0; ks < 2; ks++) {
            const int kb0 = 16 * ks;
            uint32_t af[2][4];
            #pragma unroll
            for (int i = 0; i < 2; i++) {
                const int rb = (wm * 32 + i * 16) * TSTR + kb0;
                ldsm_x4(af[i][0], af[i][1], af[i][2], af[i][3],
                        ah_b + (uint32_t)(rb + a_off) * 2);
            }
            #pragma unroll
            for (int np = 0; np < 4; np++) {
                const int n = np * 2;
                const int rb = (wn * 64 + n * 8) * TSTR + kb0;
                uint32_t bh0, bh1, bh2, bh3;
                ldsm_x4(bh0, bh1, bh2, bh3, bh_b + (uint32_t)(rb + b_off) * 2);
                #pragma unroll
                for (int i = 0; i < 2; i++) {
                    mma_f16_2(Cacc[i][n],     af[i], bh0, bh1);
                    mma_f16_2(Cacc[i][n + 1], af[i], bh2, bh3);
                }
            }
        }
    }

    #pragma unroll
    for (int i = 0; i < 2; i++) {
        const int r0 = m0 + wm * 32 + i * 16 + g;
        #pragma unroll
        for (int n = 0; n < 8; n++) {
            const int c = n0blk + wn * 64 + n * 8 + 2 * t;
            float bx = __ldg(bias + c), by = __ldg(bias + c + 1);
            float v00 = Cacc[i][n][0] + bx, v01 = Cacc[i][n][1] + by;
            float v10 = Cacc[i][n][2] + bx, v11 = Cacc[i][n][3] + by;
            if (Cf) {
                *(float2*)(Cf + (size_t)r0 * Ntotal + c)       = make_float2(v00, v01);
                *(float2*)(Cf + (size_t)(r0 + 8) * Ntotal + c) = make_float2(v10, v11);
            } else {
                *(uint32_t*)(Ch + (size_t)r0 * Ntotal + c)       = packh(v00, v01);
                *(uint32_t*)(Ch + (size_t)(r0 + 8) * Ntotal + c) = packh(v10, v11);
            }
        }
    }
}

// ---------------------------------------------------------------------------
// Flash attention: S = Q K^T, O = P V (plain fp16, fp32 accum).
// 3-stage cp.async KV pipeline (KH|VH), one sync per iteration.
// ldmatrix K + V(trans). 128 queries, 8 warps.
// ---------------------------------------------------------------------------
static constexpr int ASTR  = 72;                  // halves per row
static constexpr int KVROW = 64 * ASTR;
static constexpr int STG   = 2 * KVROW;           // KH|VH per stage
static constexpr int A_SMEM = 3 * STG * 2 + 128 * ASTR * 2;  // 3 stages + Q park = 73728 B

// softmax in exp2 domain: logits scaled by 0.125 * log2(e)
static constexpr float SCL2 = 0.125f * 1.4426950408889634f;

__global__ __launch_bounds__(256) void attn_f16()
{
    const uint32_t sb = smem_u32(g_sm);
    const int qt = blockIdx.x, bh = blockIdx.y;
    const int bb = bh >> 4, h = bh & 15;
    const int tid = threadIdx.x, wid = tid >> 5, lane = tid & 31;
    const int g = lane >> 2, t = lane & 3;
    const int grp = lane >> 3, l7 = lane & 7;
    const int q0 = qt * 128;
    const int mrow = wid * 16 + g;

    const int kb_off = ((grp >> 1) * 8 + l7) * ASTR + (grp & 1) * 8;   // K (non-trans B)
    const int v_off  = ((grp & 1) * 8 + l7) * ASTR + (grp >> 1) * 8;   // V (trans B)

    const size_t rowbase = (size_t)(bb * S_);

    // ---- issue Q load (into dedicated park region after the 3 stages)
    {
        #pragma unroll
        for (int p = 0; p < 4; p++) {
            int o = tid + p * 256;
            int r = o >> 3, sg = o & 7;
            const __half* src = g_qkv_hi + (rowbase + q0 + r) * N3_ + h * DH_ + sg * 8;
            cp16(sb + (uint32_t)(3 * STG + r * ASTR + sg * 8) * 2, src);
        }
        CP_COMMIT();
    }
    auto load_kv = [&](int j0, int s) {
        #pragma unroll
        for (int p = 0; p < 4; p++) {
            int o = tid + p * 256;
            int arr = o >> 9, r = (o >> 3) & 63, sg = o & 7;
            // arr: 0=KH 1=VH
            const __half* src = g_qkv_hi
                + (rowbase + j0 + r) * N3_ + (arr + 1) * D_ + h * DH_ + sg * 8;
            cp16(sb + (uint32_t)(s * STG + arr * KVROW + r * ASTR + sg * 8) * 2, src);
        }
        CP_COMMIT();
    };
    load_kv(0, 0);
    load_kv(64, 1);

    // ---- wait for Q (KV0/KV1 may still be in flight), extract Q fragments
    CP_WAIT(2);
    __syncthreads();
    const __half* smh = g_sm;
    uint32_t qh[4][4];
    #pragma unroll
    for (int ks = 0; ks < 4; ks++) {
        const int kb = 2 * t + 16 * ks;
        const __half* QH = smh + 3 * STG;
        qh[ks][0] = lds32(QH + mrow * ASTR + kb);
        qh[ks][1] = lds32(QH + (mrow + 8) * ASTR + kb);
        qh[ks][2] = lds32(QH + mrow * ASTR + kb + 8);
        qh[ks][3] = lds32(QH + (mrow + 8) * ASTR + kb + 8);
    }

    float Oacc[8][4] = {};
    float m0r = -1e30f, m1r = -1e30f, l0r = 0.f, l1r = 0.f;

    for (int it = 0; it < 32; it++) {
        const int s = it % 3;
        if (it < 31) { CP_WAIT(1); } else { CP_WAIT(0); }
        __syncthreads();
        if (it < 30) load_kv((it + 2) * 64, (it + 2) % 3);

        const uint32_t stg = sb + (uint32_t)(s * STG) * 2;
        const uint32_t KHb = stg;
        const uint32_t VHb = stg + (uint32_t)KVROW * 2;

        // ---- S = Q @ K^T
        float Sacc[8][4] = {};
        #pragma unroll
        for (int ks = 0; ks < 4; ks++) {
            const int kb0 = 16 * ks;
            #pragma unroll
            for (int np = 0; np < 4; np++) {
                const int n = np * 2;
                const uint32_t off = (uint32_t)(n * 8 * ASTR + kb0 + kb_off) * 2;
                uint32_t kh0, kh1, kh2, kh3;
                ldsm_x4(kh0, kh1, kh2, kh3, KHb + off);
                mma_f16_2(Sacc[n],     qh[ks], kh0, kh1);
                mma_f16_2(Sacc[n + 1], qh[ks], kh2, kh3);
            }
        }
        #pragma unroll
        for (int n = 0; n < 8; n++) {
            Sacc[n][0] *= SCL2; Sacc[n][1] *= SCL2;
            Sacc[n][2] *= SCL2; Sacc[n][3] *= SCL2;
        }

        // ---- online softmax (base-2 domain)
        float mx0 = -1e30f, mx1 = -1e30f;
        #pragma unroll
        for (int n = 0; n < 8; n++) {
            mx0 = fmaxf(mx0, fmaxf(Sacc[n][0], Sacc[n][1]));
            mx1 = fmaxf(mx1, fmaxf(Sacc[n][2], Sacc[n][3]));
        }
        mx0 = fmaxf(mx0, __shfl_xor_sync(0xffffffffu, mx0, 1));
        mx0 = fmaxf(mx0, __shfl_xor_sync(0xffffffffu, mx0, 2));
        mx1 = fmaxf(mx1, __shfl_xor_sync(0xffffffffu, mx1, 1));
        mx1 = fmaxf(mx1, __shfl_xor_sync(0xffffffffu, mx1, 2));

        const float mn0 = fmaxf(m0r, mx0), mn1 = fmaxf(m1r, mx1);
        const float c0 = exp2f(m0r - mn0), c1 = exp2f(m1r - mn1);
        float s0 = 0.f, s1 = 0.f;
        #pragma unroll
        for (int n = 0; n < 8; n++) {
            Sacc[n][0] = exp2f(Sacc[n][0] - mn0);
            Sacc[n][1] = exp2f(Sacc[n][1] - mn0);
            Sacc[n][2] = exp2f(Sacc[n][2] - mn1);
            Sacc[n][3] = exp2f(Sacc[n][3] - mn1);
            s0 += Sacc[n][0] + Sacc[n][1];
            s1 += Sacc[n][2] + Sacc[n][3];
        }
        s0 += __shfl_xor_sync(0xffffffffu, s0, 1);
        s0 += __shfl_xor_sync(0xffffffffu, s0, 2);
        s1 += __shfl_xor_sync(0xffffffffu, s1, 1);
        s1 += __shfl_xor_sync(0xffffffffu, s1, 2);
        l0r = l0r * c0 + s0;  l1r = l1r * c1 + s1;
        m0r = mn0;            m1r = mn1;

        #pragma unroll
        for (int n = 0; n < 8; n++) {
            Oacc[n][0] *= c0; Oacc[n][1] *= c0;
            Oacc[n][2] *= c1; Oacc[n][3] *= c1;
        }

        // ---- O += P @ V; P fragments from Sacc
        #pragma unroll
        for (int ks = 0; ks < 4; ks++) {
            uint32_t ph[4];
            ph[0] = packh(Sacc[2*ks][0],   Sacc[2*ks][1]);
            ph[1] = packh(Sacc[2*ks][2],   Sacc[2*ks][3]);
            ph[2] = packh(Sacc[2*ks+1][0], Sacc[2*ks+1][1]);
            ph[3] = packh(Sacc[2*ks+1][2], Sacc[2*ks+1][3]);
            #pragma unroll
            for (int np = 0; np < 4; np++) {
                const int n = np * 2;
                const uint32_t off = (uint32_t)(16 * ks * ASTR + n * 8 + v_off) * 2;
                uint32_t vh0, vh1, vh2, vh3;
                ldsm_x4t(vh0, vh1, vh2, vh3, VHb + off);
                mma_f16_2(Oacc[n],     ph, vh0, vh1);
                mma_f16_2(Oacc[n + 1], ph, vh2, vh3);
            }
        }
    }

    // ---- epilogue: normalize, write fp16 concat for proj GEMM
    const float inv0 = 1.f / l0r, inv1 = 1.f / l1r;
    __half* oh = g_oc_hi + (rowbase + q0) * HD_ + h * DH_;
    #pragma unroll
    for (int n = 0; n < 8; n++) {
        const int c = n * 8 + 2 * t;
        *(uint32_t*)(oh + (size_t)mrow * HD_ + c) =
            packh(Oacc[n][0] * inv0, Oacc[n][1] * inv0);
        *(uint32_t*)(oh + (size_t)(mrow + 8) * HD_ + c) =
            packh(Oacc[n][2] * inv1, Oacc[n][3] * inv1);
    }
}

// ---------------------------------------------------------------------------
extern "C" void kernel_launch(void* const* d_in, const int* in_sizes, int n_in,
                              void* d_out, int out_size)
{
    const float* x  = (const float*)d_in[0];
    const float* Wq = (const float*)d_in[1];
    const float* bq = (const float*)d_in[2];
    const float* Wk = (const float*)d_in[3];
    const float* bk = (const float*)d_in[4];
    const float* Wv = (const float*)d_in[5];
    const float* bv = (const float*)d_in[6];
    const float* Wo = (const float*)d_in[7];
    const float* bo = (const float*)d_in[8];
    float* out = (float*)d_out;

    void *xh, *wth, *woh, *qh, *och, *bs;
    cudaGetSymbolAddress(&xh,  g_x_hi);
    cudaGetSymbolAddress(&wth, g_wt_hi);
    cudaGetSymbolAddress(&woh, g_wot_hi);
    cudaGetSymbolAddress(&qh,  g_qkv_hi);
    cudaGetSymbolAddress(&och, g_oc_hi);
    cudaGetSymbolAddress(&bs,  g_bias);

    cudaFuncSetAttribute(gemm_f16, cudaFuncAttributeMaxDynamicSharedMemorySize, G_SMEM);
    cudaFuncSetAttribute(attn_f16, cudaFuncAttributeMaxDynamicSharedMemorySize, A_SMEM);

    prep_all<<<8195, 256>>>(x, Wq, Wk, Wv, Wo, bq, bk, bv);

    gemm_f16<<<dim3(BS_ / 128, N3_ / 128), 256, G_SMEM>>>(
        (const __half*)xh, (const __half*)wth,
        (const float*)bs, nullptr, (__half*)qh, N3_);

    attn_f16<<<dim3(S_ / 128, B_ * H_), 256, A_SMEM>>>();

    gemm_f16<<<dim3(BS_ / 128, D_ / 128), 256, G_SMEM>>>(
        (const __half*)och, (const __half*)woh,
        bo, out, nullptr, D_);
}

// round 16
// speedup vs baseline: 6.6826x; 1.0831x over previous
#include <cuda_runtime.h>
#include <cuda_fp16.h>
#include <cstdint>

// Problem constants
static constexpr int B_  = 2;
static constexpr int S_  = 2048;
static constexpr int D_  = 1024;
static constexpr int H_  = 16;
static constexpr int DH_ = 64;
static constexpr int BS_ = B_ * S_;          // 4096
static constexpr int HD_ = H_ * DH_;         // 1024
static constexpr int N3_ = 3 * D_;           // 3072

// Plain fp16 pipeline (fp32 accumulate everywhere).
__device__ __half g_x_hi [BS_ * D_];         // A of qkv GEMM
__device__ __half g_wt_hi[N3_ * D_];         // B of qkv GEMM [n][k]
__device__ __half g_wot_hi[D_ * D_];         // B of proj GEMM [n][k]
__device__ __half g_qkv_hi[BS_ * N3_];       // q|k|v
__device__ __half g_oc_hi[BS_ * HD_];        // A of proj GEMM
__device__ float g_bias[N3_];

// ---------------------------------------------------------------------------
// Helpers
// ---------------------------------------------------------------------------
__device__ __forceinline__ void cp16(uint32_t dst, const void* src) {
    asm volatile("cp.async.cg.shared.global [%0], [%1], 16;" :: "r"(dst), "l"(src));
}
#define CP_COMMIT() asm volatile("cp.async.commit_group;")
#define CP_WAIT(n)  asm volatile("cp.async.wait_group %0;" :: "n"(n))

__device__ __forceinline__ uint32_t smem_u32(const void* p) {
    uint32_t a;
    asm("{ .reg .u64 t; cvta.to.shared.u64 t, %1; cvt.u32.u64 %0, t; }" : "=r"(a) : "l"(p));
    return a;
}
__device__ __forceinline__ uint32_t lds32(const __half* p) {
    return *(const uint32_t*)p;
}
__device__ __forceinline__ void ldsm_x4(uint32_t& r0, uint32_t& r1, uint32_t& r2, uint32_t& r3,
                                        uint32_t addr) {
    asm volatile("ldmatrix.sync.aligned.m8n8.x4.shared.b16 {%0,%1,%2,%3}, [%4];"
                 : "=r"(r0), "=r"(r1), "=r"(r2), "=r"(r3) : "r"(addr));
}
__device__ __forceinline__ void ldsm_x4t(uint32_t& r0, uint32_t& r1, uint32_t& r2, uint32_t& r3,
                                         uint32_t addr) {
    asm volatile("ldmatrix.sync.aligned.m8n8.x4.trans.shared.b16 {%0,%1,%2,%3}, [%4];"
                 : "=r"(r0), "=r"(r1), "=r"(r2), "=r"(r3) : "r"(addr));
}

// m16n8k16 fp16 MMA (A row-major, B col-major), fp32 accumulate
__device__ __forceinline__ void mma_f16_2(float* c, const uint32_t* a, uint32_t b0, uint32_t b1) {
    asm volatile(
        "mma.sync.aligned.m16n8k16.row.col.f32.f16.f16.f32 "
        "{%0,%1,%2,%3}, {%4,%5,%6,%7}, {%8,%9}, {%0,%1,%2,%3};"
        : "+f"(c[0]), "+f"(c[1]), "+f"(c[2]), "+f"(c[3])
        : "r"(a[0]), "r"(a[1]), "r"(a[2]), "r"(a[3]), "r"(b0), "r"(b1));
}

__device__ __forceinline__ uint32_t packh(float a, float b) {
    return (uint32_t)__half_as_ushort(__float2half_rn(a)) |
           ((uint32_t)__half_as_ushort(__float2half_rn(b)) << 16);
}

// ---------------------------------------------------------------------------
// Fused prep kernel: block-range dispatch.
// ---------------------------------------------------------------------------
__global__ __launch_bounds__(256) void prep_all(
    const float* __restrict__ x,
    const float* __restrict__ Wq, const float* __restrict__ Wk, const float* __restrict__ Wv,
    const float* __restrict__ Wo,
    const float* __restrict__ bq, const float* __restrict__ bk, const float* __restrict__ bv)
{
    const int bid = blockIdx.x, tid = threadIdx.x;
    if (bid < 4096) {
        int i = bid * 1024 + tid * 4;
        float4 v = *(const float4*)(x + i);
        *(uint2*)(g_x_hi + i) = make_uint2(packh(v.x, v.y), packh(v.z, v.w));
    } else if (bid < 7168) {
        __shared__ float t[32][33];
        const int b = bid - 4096;
        const int z = b >> 6, rem = b & 63;
        const int bx = rem & 31, by = rem >> 5;
        const int wsel = z >> 4, h = z & 15;
        const float* W = (wsel == 0) ? Wq : (wsel == 1) ? Wk : Wv;
        const int k0 = bx * 32, d0 = by * 32;
        const int tx = tid & 31, ty = tid >> 5;
        #pragma unroll
        for (int i = 0; i < 4; i++)
            t[ty + i * 8][tx] = W[(size_t)h * D_ * DH_ + (size_t)(k0 + ty + i * 8) * DH_ + d0 + tx];
        __syncthreads();
        #pragma unroll
        for (int i = 0; i < 4; i++) {
            int d = d0 + ty + i * 8;
            g_wt_hi[(size_t)(wsel * D_ + h * DH_ + d) * D_ + k0 + tx] =
                __float2half_rn(t[tx][ty + i * 8]);
        }
    } else if (bid < 8192) {
        __shared__ float t[32][33];
        const int b = bid - 7168;
        const int bx = b & 31, by = b >> 5;
        const int k0 = bx * 32, n0 = by * 32;
        const int tx = tid & 31, ty = tid >> 5;
        #pragma unroll
        for (int i = 0; i < 4; i++)
            t[ty + i * 8][tx] = Wo[(size_t)(k0 + ty + i * 8) * D_ + n0 + tx];
        __syncthreads();
        #pragma unroll
        for (int i = 0; i < 4; i++) {
            int n = n0 + ty + i * 8;
            g_wot_hi[(size_t)n * D_ + k0 + tx] = __float2half_rn(t[tx][ty + i * 8]);
        }
    } else {
        const int set = bid - 8192;
        const float* b = (set == 0) ? bq : (set == 1) ? bk : bv;
        float4 v = *(const float4*)(b + tid * 4);
        *(float4*)(g_bias + set * 1024 + tid * 4) = v;
    }
}

// ---------------------------------------------------------------------------
// fp16 GEMM: C = A @ B^T + bias. Tile 128x128, K-chunk 64.
// 2-stage cp.async pipeline, ONE __syncthreads per iteration (16 total).
// ---------------------------------------------------------------------------
static constexpr int TSTR   = 72;             // fp16 per smem row (64 data + 8 pad)
static constexpr int TTILE  = 128 * TSTR;     // 9216 halves
static constexpr int TSTAGE = 2 * TTILE;      // Ah|Bh
static constexpr int G_SMEM = 2 * TSTAGE * 2; // 73728 bytes

extern __shared__ __half g_sm[];

__global__ __launch_bounds__(256) void gemm_f16(
    const __half* __restrict__ Ah, const __half* __restrict__ Bh,
    const float* __restrict__ bias,
    float* __restrict__ Cf, __half* __restrict__ Ch,
    int Ntotal)
{
    const uint32_t sb = smem_u32(g_sm);
    const int tid = threadIdx.x, wid = tid >> 5, lane = tid & 31;
    const int g = lane >> 2, t = lane & 3;
    const int grp = lane >> 3, l7 = lane & 7;
    const int wm = wid >> 1, wn = wid & 1;
    const int m0 = blockIdx.x * 128, n0blk = blockIdx.y * 128;

    const int a_off = ((grp & 1) * 8 + l7) * TSTR + (grp >> 1) * 8;
    const int b_off = ((grp >> 1) * 8 + l7) * TSTR + (grp & 1) * 8;

    float Cacc[2][8][4] = {};

    auto load_chunk = [&](int kc, int s) {
        #pragma unroll
        for (int p = 0; p < 8; p++) {
            int o = tid + p * 256;
            int arr = o >> 10, r = (o >> 3) & 127, sg = o & 7;
            const __half* src =
                (arr == 0) ? Ah + (size_t)(m0 + r) * D_ + kc + sg * 8
                           : Bh + (size_t)(n0blk + r) * D_ + kc + sg * 8;
            cp16(sb + (uint32_t)(s * TSTAGE + arr * TTILE + r * TSTR + sg * 8) * 2, src);
        }
        CP_COMMIT();
    };

    load_chunk(0, 0);

    for (int ch = 0; ch < 16; ch++) {
        const int s = ch & 1;
        CP_WAIT(0);
        __syncthreads();
        if (ch < 15) load_chunk((ch + 1) * 64, s ^ 1);

        const uint32_t ah_b = sb + (uint32_t)(s * TSTAGE) * 2;
        const uint32_t bh_b = ah_b + TTILE * 2;

        #pragma unroll
        for (int ks = 0; ks < 4; ks++) {
            const int kb0 = 16 * ks;
            uint32_t af[2][4];
            #pragma unroll
            for (int i = 0; i < 2; i++) {
                const int rb = (wm * 32 + i * 16) * TSTR + kb0;
                ldsm_x4(af[i][0], af[i][1], af[i][2], af[i][3],
                        ah_b + (uint32_t)(rb + a_off) * 2);
            }
            #pragma unroll
            for (int np = 0; np < 4; np++) {
                const int n = np * 2;
                const int rb = (wn * 64 + n * 8) * TSTR + kb0;
                uint32_t bh0, bh1, bh2, bh3;
                ldsm_x4(bh0, bh1, bh2, bh3, bh_b + (uint32_t)(rb + b_off) * 2);
                #pragma unroll
                for (int i = 0; i < 2; i++) {
                    mma_f16_2(Cacc[i][n],     af[i], bh0, bh1);
                    mma_f16_2(Cacc[i][n + 1], af[i], bh2, bh3);
                }
            }
        }
    }

    #pragma unroll
    for (int i = 0; i < 2; i++) {
        const int r0 = m0 + wm * 32 + i * 16 + g;
        #pragma unroll
        for (int n = 0; n < 8; n++) {
            const int c = n0blk + wn * 64 + n * 8 + 2 * t;
            float bx = __ldg(bias + c), by = __ldg(bias + c + 1);
            float v00 = Cacc[i][n][0] + bx, v01 = Cacc[i][n][1] + by;
            float v10 = Cacc[i][n][2] + bx, v11 = Cacc[i][n][3] + by;
            if (Cf) {
                *(float2*)(Cf + (size_t)r0 * Ntotal + c)       = make_float2(v00, v01);
                *(float2*)(Cf + (size_t)(r0 + 8) * Ntotal + c) = make_float2(v10, v11);
            } else {
                *(uint32_t*)(Ch + (size_t)r0 * Ntotal + c)       = packh(v00, v01);
                *(uint32_t*)(Ch + (size_t)(r0 + 8) * Ntotal + c) = packh(v10, v11);
            }
        }
    }
}

// ---------------------------------------------------------------------------
// Flash attention: S = Q K^T, O = P V (plain fp16, fp32 accum).
// 3-stage cp.async KV pipeline (KH|VH), one sync per iteration.
// ldmatrix K + V(trans). 128 queries, 8 warps.
// ---------------------------------------------------------------------------
static constexpr int ASTR  = 72;                  // halves per row
static constexpr int KVROW = 64 * ASTR;
static constexpr int STG   = 2 * KVROW;           // KH|VH per stage
static constexpr int A_SMEM = 3 * STG * 2 + 128 * ASTR * 2;  // 3 stages + Q park = 73728 B

// softmax in exp2 domain: logits scaled by 0.125 * log2(e)
static constexpr float SCL2 = 0.125f * 1.4426950408889634f;

__global__ __launch_bounds__(256) void attn_f16()
{
    const uint32_t sb = smem_u32(g_sm);
    const int qt = blockIdx.x, bh = blockIdx.y;
    const int bb = bh >> 4, h = bh & 15;
    const int tid = threadIdx.x, wid = tid >> 5, lane = tid & 31;
    const int g = lane >> 2, t = lane & 3;
    const int grp = lane >> 3, l7 = lane & 7;
    const int q0 = qt * 128;
    const int mrow = wid * 16 + g;

    const int kb_off = ((grp >> 1) * 8 + l7) * ASTR + (grp & 1) * 8;   // K (non-trans B)
    const int v_off  = ((grp & 1) * 8 + l7) * ASTR + (grp >> 1) * 8;   // V (trans B)

    const size_t rowbase = (size_t)(bb * S_);

    // ---- issue Q load (into dedicated park region after the 3 stages)
    {
        #pragma unroll
        for (int p = 0; p < 4; p++) {
            int o = tid + p * 256;
            int r = o >> 3, sg = o & 7;
            const __half* src = g_qkv_hi + (rowbase + q0 + r) * N3_ + h * DH_ + sg * 8;
            cp16(sb + (uint32_t)(3 * STG + r * ASTR + sg * 8) * 2, src);
        }
        CP_COMMIT();
    }
    auto load_kv = [&](int j0, int s) {
        #pragma unroll
        for (int p = 0; p < 4; p++) {
            int o = tid + p * 256;
            int arr = o >> 9, r = (o >> 3) & 63, sg = o & 7;
            // arr: 0=KH 1=VH
            const __half* src = g_qkv_hi
                + (rowbase + j0 + r) * N3_ + (arr + 1) * D_ + h * DH_ + sg * 8;
            cp16(sb + (uint32_t)(s * STG + arr * KVROW + r * ASTR + sg * 8) * 2, src);
        }
        CP_COMMIT();
    };
    load_kv(0, 0);
    load_kv(64, 1);

    // ---- wait for Q (KV0/KV1 may still be in flight), extract Q fragments
    CP_WAIT(2);
    __syncthreads();
    const __half* smh = g_sm;
    uint32_t qh[4][4];
    #pragma unroll
    for (int ks = 0; ks < 4; ks++) {
        const int kb = 2 * t + 16 * ks;
        const __half* QH = smh + 3 * STG;
        qh[ks][0] = lds32(QH + mrow * ASTR + kb);
        qh[ks][1] = lds32(QH + (mrow + 8) * ASTR + kb);
        qh[ks][2] = lds32(QH + mrow * ASTR + kb + 8);
        qh[ks][3] = lds32(QH + (mrow + 8) * ASTR + kb + 8);
    }

    float Oacc[8][4] = {};
    float m0r = -1e30f, m1r = -1e30f, l0r = 0.f, l1r = 0.f;

    for (int it = 0; it < 32; it++) {
        const int s = it % 3;
        if (it < 31) { CP_WAIT(1); } else { CP_WAIT(0); }
        __syncthreads();
        if (it < 30) load_kv((it + 2) * 64, (it + 2) % 3);

        const uint32_t stg = sb + (uint32_t)(s * STG) * 2;
        const uint32_t KHb = stg;
        const uint32_t VHb = stg + (uint32_t)KVROW * 2;

        // ---- S = Q @ K^T
        float Sacc[8][4] = {};
        #pragma unroll
        for (int ks = 0; ks < 4; ks++) {
            const int kb0 = 16 * ks;
            #pragma unroll
            for (int np = 0; np < 4; np++) {
                const int n = np * 2;
                const uint32_t off = (uint32_t)(n * 8 * ASTR + kb0 + kb_off) * 2;
                uint32_t kh0, kh1, kh2, kh3;
                ldsm_x4(kh0, kh1, kh2, kh3, KHb + off);
                mma_f16_2(Sacc[n],     qh[ks], kh0, kh1);
                mma_f16_2(Sacc[n + 1], qh[ks], kh2, kh3);
            }
        }
        #pragma unroll
        for (int n = 0; n < 8; n++) {
            Sacc[n][0] *= SCL2; Sacc[n][1] *= SCL2;
            Sacc[n][2] *= SCL2; Sacc[n][3] *= SCL2;
        }

        // ---- online softmax (base-2 domain)
        float mx0 = -1e30f, mx1 = -1e30f;
        #pragma unroll
        for (int n = 0; n < 8; n++) {
            mx0 = fmaxf(mx0, fmaxf(Sacc[n][0], Sacc[n][1]));
            mx1 = fmaxf(mx1, fmaxf(Sacc[n][2], Sacc[n][3]));
        }
        mx0 = fmaxf(mx0, __shfl_xor_sync(0xffffffffu, mx0, 1));
        mx0 = fmaxf(mx0, __shfl_xor_sync(0xffffffffu, mx0, 2));
        mx1 = fmaxf(mx1, __shfl_xor_sync(0xffffffffu, mx1, 1));
        mx1 = fmaxf(mx1, __shfl_xor_sync(0xffffffffu, mx1, 2));

        const float mn0 = fmaxf(m0r, mx0), mn1 = fmaxf(m1r, mx1);
        const float c0 = exp2f(m0r - mn0), c1 = exp2f(m1r - mn1);
        float s0 = 0.f, s1 = 0.f;
        #pragma unroll
        for (int n = 0; n < 8; n++) {
            Sacc[n][0] = exp2f(Sacc[n][0] - mn0);
            Sacc[n][1] = exp2f(Sacc[n][1] - mn0);
            Sacc[n][2] = exp2f(Sacc[n][2] - mn1);
            Sacc[n][3] = exp2f(Sacc[n][3] - mn1);
            s0 += Sacc[n][0] + Sacc[n][1];
            s1 += Sacc[n][2] + Sacc[n][3];
        }
        s0 += __shfl_xor_sync(0xffffffffu, s0, 1);
        s0 += __shfl_xor_sync(0xffffffffu, s0, 2);
        s1 += __shfl_xor_sync(0xffffffffu, s1, 1);
        s1 += __shfl_xor_sync(0xffffffffu, s1, 2);
        l0r = l0r * c0 + s0;  l1r = l1r * c1 + s1;
        m0r = mn0;            m1r = mn1;

        #pragma unroll
        for (int n = 0; n < 8; n++) {
            Oacc[n][0] *= c0; Oacc[n][1] *= c0;
            Oacc[n][2] *= c1; Oacc[n][3] *= c1;
        }

        // ---- O += P @ V; P fragments from Sacc
        #pragma unroll
        for (int ks = 0; ks < 4; ks++) {
            uint32_t ph[4];
            ph[0] = packh(Sacc[2*ks][0],   Sacc[2*ks][1]);
            ph[1] = packh(Sacc[2*ks][2],   Sacc[2*ks][3]);
            ph[2] = packh(Sacc[2*ks+1][0], Sacc[2*ks+1][1]);
            ph[3] = packh(Sacc[2*ks+1][2], Sacc[2*ks+1][3]);
            #pragma unroll
            for (int np = 0; np < 4; np++) {
                const int n = np * 2;
                const uint32_t off = (uint32_t)(16 * ks * ASTR + n * 8 + v_off) * 2;
                uint32_t vh0, vh1, vh2, vh3;
                ldsm_x4t(vh0, vh1, vh2, vh3, VHb + off);
                mma_f16_2(Oacc[n],     ph, vh0, vh1);
                mma_f16_2(Oacc[n + 1], ph, vh2, vh3);
            }
        }
    }

    // ---- epilogue: normalize, write fp16 concat for proj GEMM
    const float inv0 = 1.f / l0r, inv1 = 1.f / l1r;
    __half* oh = g_oc_hi + (rowbase + q0) * HD_ + h * DH_;
    #pragma unroll
    for (int n = 0; n < 8; n++) {
        const int c = n * 8 + 2 * t;
        *(uint32_t*)(oh + (size_t)mrow * HD_ + c) =
            packh(Oacc[n][0] * inv0, Oacc[n][1] * inv0);
        *(uint32_t*)(oh + (size_t)(mrow + 8) * HD_ + c) =
            packh(Oacc[n][2] * inv1, Oacc[n][3] * inv1);
    }
}

// ---------------------------------------------------------------------------
extern "C" void kernel_launch(void* const* d_in, const int* in_sizes, int n_in,
                              void* d_out, int out_size)
{
    const float* x  = (const float*)d_in[0];
    const float* Wq = (const float*)d_in[1];
    const float* bq = (const float*)d_in[2];
    const float* Wk = (const float*)d_in[3];
    const float* bk = (const float*)d_in[4];
    const float* Wv = (const float*)d_in[5];
    const float* bv = (const float*)d_in[6];
    const float* Wo = (const float*)d_in[7];
    const float* bo = (const float*)d_in[8];
    float* out = (float*)d_out;

    void *xh, *wth, *woh, *qh, *och, *bs;
    cudaGetSymbolAddress(&xh,  g_x_hi);
    cudaGetSymbolAddress(&wth, g_wt_hi);
    cudaGetSymbolAddress(&woh, g_wot_hi);
    cudaGetSymbolAddress(&qh,  g_qkv_hi);
    cudaGetSymbolAddress(&och, g_oc_hi);
    cudaGetSymbolAddress(&bs,  g_bias);

    cudaFuncSetAttribute(gemm_f16, cudaFuncAttributeMaxDynamicSharedMemorySize, G_SMEM);
    cudaFuncSetAttribute(attn_f16, cudaFuncAttributeMaxDynamicSharedMemorySize, A_SMEM);

    prep_all<<<8195, 256>>>(x, Wq, Wk, Wv, Wo, bq, bk, bv);

    gemm_f16<<<dim3(BS_ / 128, N3_ / 128), 256, G_SMEM>>>(
        (const __half*)xh, (const __half*)wth,
        (const float*)bs, nullptr, (__half*)qh, N3_);

    attn_f16<<<dim3(S_ / 128, B_ * H_), 256, A_SMEM>>>();

    gemm_f16<<<dim3(BS_ / 128, D_ / 128), 256, G_SMEM>>>(
        (const __half*)och, (const __half*)woh,
        bo, out, nullptr, D_);
}

// round 17
// speedup vs baseline: 7.2139x; 1.0795x over previous
#include <cuda_runtime.h>
#include <cuda_fp16.h>
#include <cstdint>

// Problem constants
static constexpr int B_  = 2;
static constexpr int S_  = 2048;
static constexpr int D_  = 1024;
static constexpr int H_  = 16;
static constexpr int DH_ = 64;
static constexpr int BS_ = B_ * S_;          // 4096
static constexpr int HD_ = H_ * DH_;         // 1024
static constexpr int N3_ = 3 * D_;           // 3072

// Plain fp16 pipeline (fp32 accumulate everywhere).
__device__ __half g_x_hi [BS_ * D_];         // A of qkv GEMM
__device__ __half g_wt_hi[N3_ * D_];         // B of qkv GEMM [n][k]
__device__ __half g_wot_hi[D_ * D_];         // B of proj GEMM [n][k]
__device__ __half g_qkv_hi[BS_ * N3_];       // q|k|v
__device__ __half g_oc_hi[BS_ * HD_];        // A of proj GEMM
__device__ float g_bias[N3_];

// ---------------------------------------------------------------------------
// Helpers
// ---------------------------------------------------------------------------
__device__ __forceinline__ void cp16(uint32_t dst, const void* src) {
    asm volatile("cp.async.cg.shared.global [%0], [%1], 16;" :: "r"(dst), "l"(src));
}
#define CP_COMMIT() asm volatile("cp.async.commit_group;")
#define CP_WAIT(n)  asm volatile("cp.async.wait_group %0;" :: "n"(n))

__device__ __forceinline__ uint32_t smem_u32(const void* p) {
    uint32_t a;
    asm("{ .reg .u64 t; cvta.to.shared.u64 t, %1; cvt.u32.u64 %0, t; }" : "=r"(a) : "l"(p));
    return a;
}
__device__ __forceinline__ uint32_t lds32(const __half* p) {
    return *(const uint32_t*)p;
}
__device__ __forceinline__ void ldsm_x4(uint32_t& r0, uint32_t& r1, uint32_t& r2, uint32_t& r3,
                                        uint32_t addr) {
    asm volatile("ldmatrix.sync.aligned.m8n8.x4.shared.b16 {%0,%1,%2,%3}, [%4];"
                 : "=r"(r0), "=r"(r1), "=r"(r2), "=r"(r3) : "r"(addr));
}
__device__ __forceinline__ void ldsm_x4t(uint32_t& r0, uint32_t& r1, uint32_t& r2, uint32_t& r3,
                                         uint32_t addr) {
    asm volatile("ldmatrix.sync.aligned.m8n8.x4.trans.shared.b16 {%0,%1,%2,%3}, [%4];"
                 : "=r"(r0), "=r"(r1), "=r"(r2), "=r"(r3) : "r"(addr));
}

// m16n8k16 fp16 MMA (A row-major, B col-major), fp32 accumulate
__device__ __forceinline__ void mma_f16_2(float* c, const uint32_t* a, uint32_t b0, uint32_t b1) {
    asm volatile(
        "mma.sync.aligned.m16n8k16.row.col.f32.f16.f16.f32 "
        "{%0,%1,%2,%3}, {%4,%5,%6,%7}, {%8,%9}, {%0,%1,%2,%3};"
        : "+f"(c[0]), "+f"(c[1]), "+f"(c[2]), "+f"(c[3])
        : "r"(a[0]), "r"(a[1]), "r"(a[2]), "r"(a[3]), "r"(b0), "r"(b1));
}

__device__ __forceinline__ uint32_t packh(float a, float b) {
    return (uint32_t)__half_as_ushort(__float2half_rn(a)) |
           ((uint32_t)__half_as_ushort(__float2half_rn(b)) << 16);
}

// pack two fp32 into f16x2 and take 2^x of both halves in one MUFU op
__device__ __forceinline__ uint32_t exp2_pair(float lo, float hi) {
    uint32_t d, p;
    asm("cvt.rn.f16x2.f32 %0, %1, %2;" : "=r"(d) : "f"(hi), "f"(lo));
    asm("ex2.approx.f16x2 %0, %1;" : "=r"(p) : "r"(d));
    return p;
}

// ---------------------------------------------------------------------------
// Fused prep kernel: block-range dispatch.
// ---------------------------------------------------------------------------
__global__ __launch_bounds__(256) void prep_all(
    const float* __restrict__ x,
    const float* __restrict__ Wq, const float* __restrict__ Wk, const float* __restrict__ Wv,
    const float* __restrict__ Wo,
    const float* __restrict__ bq, const float* __restrict__ bk, const float* __restrict__ bv)
{
    const int bid = blockIdx.x, tid = threadIdx.x;
    if (bid < 4096) {
        int i = bid * 1024 + tid * 4;
        float4 v = *(const float4*)(x + i);
        *(uint2*)(g_x_hi + i) = make_uint2(packh(v.x, v.y), packh(v.z, v.w));
    } else if (bid < 7168) {
        __shared__ float t[32][33];
        const int b = bid - 4096;
        const int z = b >> 6, rem = b & 63;
        const int bx = rem & 31, by = rem >> 5;
        const int wsel = z >> 4, h = z & 15;
        const float* W = (wsel == 0) ? Wq : (wsel == 1) ? Wk : Wv;
        const int k0 = bx * 32, d0 = by * 32;
        const int tx = tid & 31, ty = tid >> 5;
        #pragma unroll
        for (int i = 0; i < 4; i++)
            t[ty + i * 8][tx] = W[(size_t)h * D_ * DH_ + (size_t)(k0 + ty + i * 8) * DH_ + d0 + tx];
        __syncthreads();
        #pragma unroll
        for (int i = 0; i < 4; i++) {
            int d = d0 + ty + i * 8;
            g_wt_hi[(size_t)(wsel * D_ + h * DH_ + d) * D_ + k0 + tx] =
                __float2half_rn(t[tx][ty + i * 8]);
        }
    } else if (bid < 8192) {
        __shared__ float t[32][33];
        const int b = bid - 7168;
        const int bx = b & 31, by = b >> 5;
        const int k0 = bx * 32, n0 = by * 32;
        const int tx = tid & 31, ty = tid >> 5;
        #pragma unroll
        for (int i = 0; i < 4; i++)
            t[ty + i * 8][tx] = Wo[(size_t)(k0 + ty + i * 8) * D_ + n0 + tx];
        __syncthreads();
        #pragma unroll
        for (int i = 0; i < 4; i++) {
            int n = n0 + ty + i * 8;
            g_wot_hi[(size_t)n * D_ + k0 + tx] = __float2half_rn(t[tx][ty + i * 8]);
        }
    } else {
        const int set = bid - 8192;
        const float* b = (set == 0) ? bq : (set == 1) ? bk : bv;
        float4 v = *(const float4*)(b + tid * 4);
        *(float4*)(g_bias + set * 1024 + tid * 4) = v;
    }
}

// ---------------------------------------------------------------------------
// fp16 GEMM: C = A @ B^T + bias. Tile 128x128, K-chunk 64.
// 3-stage cp.async pipeline, one __syncthreads per iteration (16 total).
// ---------------------------------------------------------------------------
static constexpr int TSTR   = 72;             // fp16 per smem row (64 data + 8 pad)
static constexpr int TTILE  = 128 * TSTR;     // 9216 halves
static constexpr int TSTAGE = 2 * TTILE;      // Ah|Bh
static constexpr int G_SMEM = 3 * TSTAGE * 2; // 110592 bytes

extern __shared__ __half g_sm[];

__global__ __launch_bounds__(256) void gemm_f16(
    const __half* __restrict__ Ah, const __half* __restrict__ Bh,
    const float* __restrict__ bias,
    float* __restrict__ Cf, __half* __restrict__ Ch,
    int Ntotal)
{
    const uint32_t sb = smem_u32(g_sm);
    const int tid = threadIdx.x, wid = tid >> 5, lane = tid & 31;
    const int g = lane >> 2, t = lane & 3;
    const int grp = lane >> 3, l7 = lane & 7;
    const int wm = wid >> 1, wn = wid & 1;
    const int m0 = blockIdx.x * 128, n0blk = blockIdx.y * 128;

    const int a_off = ((grp & 1) * 8 + l7) * TSTR + (grp >> 1) * 8;
    const int b_off = ((grp >> 1) * 8 + l7) * TSTR + (grp & 1) * 8;

    float Cacc[2][8][4] = {};

    auto load_chunk = [&](int kc, int s) {
        #pragma unroll
        for (int p = 0; p < 8; p++) {
            int o = tid + p * 256;
            int arr = o >> 10, r = (o >> 3) & 127, sg = o & 7;
            const __half* src =
                (arr == 0) ? Ah + (size_t)(m0 + r) * D_ + kc + sg * 8
                           : Bh + (size_t)(n0blk + r) * D_ + kc + sg * 8;
            cp16(sb + (uint32_t)(s * TSTAGE + arr * TTILE + r * TSTR + sg * 8) * 2, src);
        }
        CP_COMMIT();
    };

    load_chunk(0, 0);
    load_chunk(64, 1);

    for (int ch = 0; ch < 16; ch++) {
        const int s = ch % 3;
        if (ch < 15) { CP_WAIT(1); } else { CP_WAIT(0); }
        __syncthreads();
        if (ch < 14) load_chunk((ch + 2) * 64, (ch + 2) % 3);

        const uint32_t ah_b = sb + (uint32_t)(s * TSTAGE) * 2;
        const uint32_t bh_b = ah_b + TTILE * 2;

        #pragma unroll
        for (int ks = 0; ks < 4; ks++) {
            const int kb0 = 16 * ks;
            uint32_t af[2][4];
            #pragma unroll
            for (int i = 0; i < 2; i++) {
                const int rb = (wm * 32 + i * 16) * TSTR + kb0;
                ldsm_x4(af[i][0], af[i][1], af[i][2], af[i][3],
                        ah_b + (uint32_t)(rb + a_off) * 2);
            }
            #pragma unroll
            for (int np = 0; np < 4; np++) {
                const int n = np * 2;
                const int rb = (wn * 64 + n * 8) * TSTR + kb0;
                uint32_t bh0, bh1, bh2, bh3;
                ldsm_x4(bh0, bh1, bh2, bh3, bh_b + (uint32_t)(rb + b_off) * 2);
                #pragma unroll
                for (int i = 0; i < 2; i++) {
                    mma_f16_2(Cacc[i][n],     af[i], bh0, bh1);
                    mma_f16_2(Cacc[i][n + 1], af[i], bh2, bh3);
                }
            }
        }
    }

    #pragma unroll
    for (int i = 0; i < 2; i++) {
        const int r0 = m0 + wm * 32 + i * 16 + g;
        #pragma unroll
        for (int n = 0; n < 8; n++) {
            const int c = n0blk + wn * 64 + n * 8 + 2 * t;
            float bx = __ldg(bias + c), by = __ldg(bias + c + 1);
            float v00 = Cacc[i][n][0] + bx, v01 = Cacc[i][n][1] + by;
            float v10 = Cacc[i][n][2] + bx, v11 = Cacc[i][n][3] + by;
            if (Cf) {
                *(float2*)(Cf + (size_t)r0 * Ntotal + c)       = make_float2(v00, v01);
                *(float2*)(Cf + (size_t)(r0 + 8) * Ntotal + c) = make_float2(v10, v11);
            } else {
                *(uint32_t*)(Ch + (size_t)r0 * Ntotal + c)       = packh(v00, v01);
                *(uint32_t*)(Ch + (size_t)(r0 + 8) * Ntotal + c) = packh(v10, v11);
            }
        }
    }
}

// ---------------------------------------------------------------------------
// Flash attention: S = Q K^T, O = P V (fp16 mma, fp32 accum).
// f16x2 exp; row sums via mma with constant ones-fragment.
// 3-stage cp.async KV pipeline, one sync per iteration. 128 q, 8 warps.
// ---------------------------------------------------------------------------
static constexpr int ASTR  = 72;                  // halves per row
static constexpr int KVROW = 64 * ASTR;
static constexpr int STG   = 2 * KVROW;           // KH|VH per stage
static constexpr int A_SMEM = 3 * STG * 2 + 128 * ASTR * 2;  // 3 stages + Q park = 73728 B

// softmax in exp2 domain: logits scaled by 0.125 * log2(e)
static constexpr float SCL2 = 0.125f * 1.4426950408889634f;
static constexpr uint32_t ONESx2 = 0x3C003C00u;   // fp16 {1.0, 1.0}

__global__ __launch_bounds__(256) void attn_f16()
{
    const uint32_t sb = smem_u32(g_sm);
    const int qt = blockIdx.x, bh = blockIdx.y;
    const int bb = bh >> 4, h = bh & 15;
    const int tid = threadIdx.x, wid = tid >> 5, lane = tid & 31;
    const int g = lane >> 2, t = lane & 3;
    const int grp = lane >> 3, l7 = lane & 7;
    const int q0 = qt * 128;
    const int mrow = wid * 16 + g;

    const int kb_off = ((grp >> 1) * 8 + l7) * ASTR + (grp & 1) * 8;   // K (non-trans B)
    const int v_off  = ((grp & 1) * 8 + l7) * ASTR + (grp >> 1) * 8;   // V (trans B)

    const size_t rowbase = (size_t)(bb * S_);

    // ---- issue Q load (into dedicated park region after the 3 stages)
    {
        #pragma unroll
        for (int p = 0; p < 4; p++) {
            int o = tid + p * 256;
            int r = o >> 3, sg = o & 7;
            const __half* src = g_qkv_hi + (rowbase + q0 + r) * N3_ + h * DH_ + sg * 8;
            cp16(sb + (uint32_t)(3 * STG + r * ASTR + sg * 8) * 2, src);
        }
        CP_COMMIT();
    }
    auto load_kv = [&](int j0, int s) {
        #pragma unroll
        for (int p = 0; p < 4; p++) {
            int o = tid + p * 256;
            int arr = o >> 9, r = (o >> 3) & 63, sg = o & 7;
            // arr: 0=KH 1=VH
            const __half* src = g_qkv_hi
                + (rowbase + j0 + r) * N3_ + (arr + 1) * D_ + h * DH_ + sg * 8;
            cp16(sb + (uint32_t)(s * STG + arr * KVROW + r * ASTR + sg * 8) * 2, src);
        }
        CP_COMMIT();
    };
    load_kv(0, 0);
    load_kv(64, 1);

    // ---- wait for Q (KV0/KV1 may still be in flight), extract Q fragments
    CP_WAIT(2);
    __syncthreads();
    const __half* smh = g_sm;
    uint32_t qh[4][4];
    #pragma unroll
    for (int ks = 0; ks < 4; ks++) {
        const int kb = 2 * t + 16 * ks;
        const __half* QH = smh + 3 * STG;
        qh[ks][0] = lds32(QH + mrow * ASTR + kb);
        qh[ks][1] = lds32(QH + (mrow + 8) * ASTR + kb);
        qh[ks][2] = lds32(QH + mrow * ASTR + kb + 8);
        qh[ks][3] = lds32(QH + (mrow + 8) * ASTR + kb + 8);
    }

    float Oacc[8][4] = {};
    float m0r = -1e30f, m1r = -1e30f, l0r = 0.f, l1r = 0.f;

    for (int it = 0; it < 32; it++) {
        const int s = it % 3;
        if (it < 31) { CP_WAIT(1); } else { CP_WAIT(0); }
        __syncthreads();
        if (it < 30) load_kv((it + 2) * 64, (it + 2) % 3);

        const uint32_t stg = sb + (uint32_t)(s * STG) * 2;
        const uint32_t KHb = stg;
        const uint32_t VHb = stg + (uint32_t)KVROW * 2;

        // ---- S = Q @ K^T (raw logits, fp32)
        float Sacc[8][4] = {};
        #pragma unroll
        for (int ks = 0; ks < 4; ks++) {
            const int kb0 = 16 * ks;
            #pragma unroll
            for (int np = 0; np < 4; np++) {
                const int n = np * 2;
                const uint32_t off = (uint32_t)(n * 8 * ASTR + kb0 + kb_off) * 2;
                uint32_t kh0, kh1, kh2, kh3;
                ldsm_x4(kh0, kh1, kh2, kh3, KHb + off);
                mma_f16_2(Sacc[n],     qh[ks], kh0, kh1);
                mma_f16_2(Sacc[n + 1], qh[ks], kh2, kh3);
            }
        }

        // ---- online softmax (scaled base-2 domain; m stored scaled)
        float mx0 = -1e30f, mx1 = -1e30f;
        #pragma unroll
        for (int n = 0; n < 8; n++) {
            mx0 = fmaxf(mx0, fmaxf(Sacc[n][0], Sacc[n][1]));
            mx1 = fmaxf(mx1, fmaxf(Sacc[n][2], Sacc[n][3]));
        }
        mx0 = fmaxf(mx0, __shfl_xor_sync(0xffffffffu, mx0, 1));
        mx0 = fmaxf(mx0, __shfl_xor_sync(0xffffffffu, mx0, 2));
        mx1 = fmaxf(mx1, __shfl_xor_sync(0xffffffffu, mx1, 1));
        mx1 = fmaxf(mx1, __shfl_xor_sync(0xffffffffu, mx1, 2));

        const float mn0 = fmaxf(m0r, mx0 * SCL2), mn1 = fmaxf(m1r, mx1 * SCL2);
        const float c0 = exp2f(m0r - mn0), c1 = exp2f(m1r - mn1);
        m0r = mn0;  m1r = mn1;

        // ---- P = 2^(s*SCL2 - mn), computed pairwise in f16x2 (packed for mma)
        uint32_t Pp[8][2];
        #pragma unroll
        for (int n = 0; n < 8; n++) {
            Pp[n][0] = exp2_pair(fmaf(Sacc[n][0], SCL2, -mn0),
                                 fmaf(Sacc[n][1], SCL2, -mn0));
            Pp[n][1] = exp2_pair(fmaf(Sacc[n][2], SCL2, -mn1),
                                 fmaf(Sacc[n][3], SCL2, -mn1));
        }

        #pragma unroll
        for (int n = 0; n < 8; n++) {
            Oacc[n][0] *= c0; Oacc[n][1] *= c0;
            Oacc[n][2] *= c1; Oacc[n][3] *= c1;
        }

        // ---- O += P @ V, and l-sums via mma with ones-fragment
        float Lacc[4] = {};
        #pragma unroll
        for (int ks = 0; ks < 4; ks++) {
            uint32_t ph[4] = { Pp[2*ks][0], Pp[2*ks][1], Pp[2*ks+1][0], Pp[2*ks+1][1] };
            mma_f16_2(Lacc, ph, ONESx2, ONESx2);
            #pragma unroll
            for (int np = 0; np < 4; np++) {
                const int n = np * 2;
                const uint32_t off = (uint32_t)(16 * ks * ASTR + n * 8 + v_off) * 2;
                uint32_t vh0, vh1, vh2, vh3;
                ldsm_x4t(vh0, vh1, vh2, vh3, VHb + off);
                mma_f16_2(Oacc[n],     ph, vh0, vh1);
                mma_f16_2(Oacc[n + 1], ph, vh2, vh3);
            }
        }
        l0r = l0r * c0 + Lacc[0];
        l1r = l1r * c1 + Lacc[2];
    }

    // ---- epilogue: normalize, write fp16 concat for proj GEMM
    const float inv0 = 1.f / l0r, inv1 = 1.f / l1r;
    __half* oh = g_oc_hi + (rowbase + q0) * HD_ + h * DH_;
    #pragma unroll
    for (int n = 0; n < 8; n++) {
        const int c = n * 8 + 2 * t;
        *(uint32_t*)(oh + (size_t)mrow * HD_ + c) =
            packh(Oacc[n][0] * inv0, Oacc[n][1] * inv0);
        *(uint32_t*)(oh + (size_t)(mrow + 8) * HD_ + c) =
            packh(Oacc[n][2] * inv1, Oacc[n][3] * inv1);
    }
}

// ---------------------------------------------------------------------------
extern "C" void kernel_launch(void* const* d_in, const int* in_sizes, int n_in,
                              void* d_out, int out_size)
{
    const float* x  = (const float*)d_in[0];
    const float* Wq = (const float*)d_in[1];
    const float* bq = (const float*)d_in[2];
    const float* Wk = (const float*)d_in[3];
    const float* bk = (const float*)d_in[4];
    const float* Wv = (const float*)d_in[5];
    const float* bv = (const float*)d_in[6];
    const float* Wo = (const float*)d_in[7];
    const float* bo = (const float*)d_in[8];
    float* out = (float*)d_out;

    void *xh, *wth, *woh, *qh, *och, *bs;
    cudaGetSymbolAddress(&xh,  g_x_hi);
    cudaGetSymbolAddress(&wth, g_wt_hi);
    cudaGetSymbolAddress(&woh, g_wot_hi);
    cudaGetSymbolAddress(&qh,  g_qkv_hi);
    cudaGetSymbolAddress(&och, g_oc_hi);
    cudaGetSymbolAddress(&bs,  g_bias);

    cudaFuncSetAttribute(gemm_f16, cudaFuncAttributeMaxDynamicSharedMemorySize, G_SMEM);
    cudaFuncSetAttribute(attn_f16, cudaFuncAttributeMaxDynamicSharedMemorySize, A_SMEM);

    prep_all<<<8195, 256>>>(x, Wq, Wk, Wv, Wo, bq, bk, bv);

    gemm_f16<<<dim3(BS_ / 128, N3_ / 128), 256, G_SMEM>>>(
        (const __half*)xh, (const __half*)wth,
        (const float*)bs, nullptr, (__half*)qh, N3_);

    attn_f16<<<dim3(S_ / 128, B_ * H_), 256, A_SMEM>>>();

    gemm_f16<<<dim3(BS_ / 128, D_ / 128), 256, G_SMEM>>>(
        (const __half*)och, (const __half*)woh,
        bo, out, nullptr, D_);
}